// round 4
// baseline (speedup 1.0000x reference)
#include <cuda_runtime.h>
#include <cuda_bf16.h>
#include <mma.h>
#include <math.h>
#include <stdint.h>

using namespace nvcuda;

#define CB 2
#define CS 2048
#define CH 1024
#define CNH 16
#define CHD 64
#define CE 8
#define CD 1024
#define CT (CB*CS)

#define MB (1024ull*1024ull)

// ---------------- scratch layout ----------------
static constexpr size_t OFF_WQ_ATTN = 0;               // 4 MB  int8: q,k,v,o
static constexpr size_t OFF_WQ_GATE = 4*MB;            // 8 MB
static constexpr size_t OFF_WQ_UP   = 12*MB;           // 8 MB
static constexpr size_t OFF_WQ_DOWN = 20*MB;           // 8 MB
static constexpr size_t OFF_WSCALE  = 28*MB;           // 28 floats
static constexpr size_t OFF_PART    = 28*MB + 4096;    // 28*256 floats
static constexpr size_t OFF_XQ1     = 29*MB;           // 4 MB int8
static constexpr size_t OFF_A1S     = 33*MB;           // T floats
static constexpr size_t OFF_QKV     = 34*MB;           // 48 MB fp32: q,k,v [B,NH,S,HD]
static constexpr size_t OFF_HB      = 82*MB;           // 16 MB fp32 attention out [T,H]
static constexpr size_t OFF_HQA     = 98*MB;           // 4 MB int8
static constexpr size_t OFF_HSA     = 102*MB;          // T floats
static constexpr size_t OFF_X2      = 103*MB;          // 16 MB fp32
static constexpr size_t OFF_XQ2     = 119*MB;          // 4 MB int8
static constexpr size_t OFF_A2S     = 123*MB;          // T floats
static constexpr size_t OFF_IDX     = 123*MB + 64*1024;
static constexpr size_t OFF_CNT     = 123*MB + 128*1024;
static constexpr size_t OFF_SEG     = 123*MB + 129*1024;
static constexpr size_t OFF_CUR     = 123*MB + 130*1024;
static constexpr size_t OFF_PERM    = 124*MB;          // T ints
static constexpr size_t OFF_GB      = 125*MB;          // 16 MB fp32
static constexpr size_t OFF_UB      = 141*MB;          // 16 MB fp32
static constexpr size_t OFF_HQM     = 157*MB;          // 4 MB int8
static constexpr size_t OFF_HSM     = 161*MB;          // T floats
static constexpr size_t SCRATCH_BYTES = 162*MB;

__device__ __align__(256) unsigned char g_scratch[SCRATCH_BYTES];

// ---------------- helpers ----------------
__device__ __forceinline__ float blk_reduce_sum(float v, float* red) {
    int tid = threadIdx.x;
    red[tid] = v; __syncthreads();
    #pragma unroll
    for (int s = 128; s > 0; s >>= 1) {
        if (tid < s) red[tid] += red[tid + s];
        __syncthreads();
    }
    float r = red[0]; __syncthreads();
    return r;
}

__device__ __forceinline__ float blk_reduce_max(float v, float* red) {
    int tid = threadIdx.x;
    red[tid] = v; __syncthreads();
    #pragma unroll
    for (int s = 128; s > 0; s >>= 1) {
        if (tid < s) red[tid] = fmaxf(red[tid], red[tid + s]);
        __syncthreads();
    }
    float r = red[0]; __syncthreads();
    return r;
}

// ---------------- weight quantization ----------------
__global__ void absmean_partial(const float* __restrict__ w, float* __restrict__ part, int len) {
    __shared__ float red[256];
    const float* p = w + (size_t)blockIdx.y * len;
    float s = 0.f;
    for (int i = blockIdx.x * 256 + threadIdx.x; i < len; i += gridDim.x * 256)
        s += fabsf(p[i]);
    s = blk_reduce_sum(s, red);
    if (threadIdx.x == 0) part[(size_t)blockIdx.y * gridDim.x + blockIdx.x] = s;
}

__global__ void absmean4(const float* __restrict__ w0, const float* __restrict__ w1,
                         const float* __restrict__ w2, const float* __restrict__ w3,
                         float* __restrict__ part, int len) {
    __shared__ float red[256];
    int sl = blockIdx.y;
    const float* p = sl == 0 ? w0 : sl == 1 ? w1 : sl == 2 ? w2 : w3;
    float s = 0.f;
    for (int i = blockIdx.x * 256 + threadIdx.x; i < len; i += gridDim.x * 256)
        s += fabsf(p[i]);
    s = blk_reduce_sum(s, red);
    if (threadIdx.x == 0) part[(size_t)sl * gridDim.x + blockIdx.x] = s;
}

__global__ void finalize_wscale(const float* __restrict__ part, float* __restrict__ wsc,
                                int i0, int n) {
    int i = i0 + threadIdx.x;
    if (threadIdx.x >= n) return;
    float s = 0.f;
    for (int j = 0; j < 256; j++) s += part[i * 256 + j];
    wsc[i] = fmaxf(s * (1.0f / (1024.f * 1024.f)), 1e-5f);
}

__global__ void quantize_w(const float* __restrict__ w, int8_t* __restrict__ wq,
                           const float* __restrict__ wsc, int widx0, int len) {
    int slice = blockIdx.y;
    float s = 1.0f / wsc[widx0 + slice];
    const float* p = w + (size_t)slice * len;
    int8_t* q = wq + (size_t)slice * len;
    for (int i = blockIdx.x * 256 + threadIdx.x; i < len; i += gridDim.x * 256) {
        float v = rintf(p[i] * s);
        v = fminf(fmaxf(v, -1.f), 1.f);
        q[i] = (int8_t)(int)v;
    }
}

__global__ void quantize4(const float* __restrict__ w0, const float* __restrict__ w1,
                          const float* __restrict__ w2, const float* __restrict__ w3,
                          int8_t* __restrict__ wq, const float* __restrict__ wsc, int len) {
    int sl = blockIdx.y;
    const float* p = sl == 0 ? w0 : sl == 1 ? w1 : sl == 2 ? w2 : w3;
    float s = 1.0f / wsc[sl];
    int8_t* q = wq + (size_t)sl * len;
    for (int i = blockIdx.x * 256 + threadIdx.x; i < len; i += gridDim.x * 256) {
        float v = rintf(p[i] * s);
        v = fminf(fmaxf(v, -1.f), 1.f);
        q[i] = (int8_t)(int)v;
    }
}

// ---------------- activation rmsnorm + quant ----------------
__global__ void rmsnorm_quant(const float* __restrict__ x, const float* __restrict__ lnw,
                              int8_t* __restrict__ xq, float* __restrict__ ainv) {
    __shared__ float red[256];
    __shared__ float xs[CH];
    int t = blockIdx.x, tid = threadIdx.x;
    const float* xr = x + (size_t)t * CH;
    float v[4]; float ss = 0.f;
    #pragma unroll
    for (int i = 0; i < 4; i++) { v[i] = xr[tid + i * 256]; ss += v[i] * v[i]; }
    ss = blk_reduce_sum(ss, red);
    float r = rsqrtf(ss * (1.0f / CH) + 1e-5f);
    float amax = 0.f;
    #pragma unroll
    for (int i = 0; i < 4; i++) {
        float xn = v[i] * r * lnw[tid + i * 256];
        xs[tid + i * 256] = xn;
        amax = fmaxf(amax, fabsf(xn));
    }
    amax = blk_reduce_max(amax, red);
    float m = fmaxf(amax, 1e-5f);
    float s = 127.f / m;
    #pragma unroll
    for (int i = 0; i < 4; i++) {
        float qv = fminf(fmaxf(rintf(xs[tid + i * 256] * s), -128.f), 127.f);
        xq[(size_t)t * CH + tid + i * 256] = (int8_t)(int)qv;
    }
    if (tid == 0) ainv[t] = m * (1.0f / 127.f);
}

__global__ void act_quant_rows(const float* __restrict__ x, int8_t* __restrict__ xq,
                               float* __restrict__ ainv) {
    __shared__ float red[256];
    int t = blockIdx.x, tid = threadIdx.x;
    const float* xr = x + (size_t)t * CH;
    float v[4]; float amax = 0.f;
    #pragma unroll
    for (int i = 0; i < 4; i++) { v[i] = xr[tid + i * 256]; amax = fmaxf(amax, fabsf(v[i])); }
    amax = blk_reduce_max(amax, red);
    float m = fmaxf(amax, 1e-5f);
    float s = 127.f / m;
    #pragma unroll
    for (int i = 0; i < 4; i++) {
        float qv = fminf(fmaxf(rintf(v[i] * s), -128.f), 127.f);
        xq[(size_t)t * CH + tid + i * 256] = (int8_t)(int)qv;
    }
    if (tid == 0) ainv[t] = m * (1.0f / 127.f);
}

__global__ void rmsnorm2_router(const float* __restrict__ x, const float* __restrict__ lnw,
                                const float* __restrict__ rw, int8_t* __restrict__ xq,
                                float* __restrict__ ainv, int* __restrict__ idx,
                                int* __restrict__ counts) {
    __shared__ float red[256];
    __shared__ float xs[CH];
    __shared__ float logits[CE];
    int t = blockIdx.x, tid = threadIdx.x;
    const float* xr = x + (size_t)t * CH;
    float v[4]; float ss = 0.f;
    #pragma unroll
    for (int i = 0; i < 4; i++) { v[i] = xr[tid + i * 256]; ss += v[i] * v[i]; }
    ss = blk_reduce_sum(ss, red);
    float r = rsqrtf(ss * (1.0f / CH) + 1e-5f);
    float amax = 0.f;
    #pragma unroll
    for (int i = 0; i < 4; i++) {
        float xn = v[i] * r * lnw[tid + i * 256];
        xs[tid + i * 256] = xn;
        amax = fmaxf(amax, fabsf(xn));
    }
    amax = blk_reduce_max(amax, red);
    float m = fmaxf(amax, 1e-5f);
    float s = 127.f / m;
    #pragma unroll
    for (int i = 0; i < 4; i++) {
        float qv = fminf(fmaxf(rintf(xs[tid + i * 256] * s), -128.f), 127.f);
        xq[(size_t)t * CH + tid + i * 256] = (int8_t)(int)qv;
    }
    if (tid == 0) ainv[t] = m * (1.0f / 127.f);
    __syncthreads();

    int w = tid >> 5, lane = tid & 31;
    float acc = 0.f;
    for (int h = lane; h < CH; h += 32) acc += xs[h] * rw[w * CH + h];
    #pragma unroll
    for (int o = 16; o > 0; o >>= 1) acc += __shfl_down_sync(0xffffffffu, acc, o);
    if (lane == 0) logits[w] = acc;
    __syncthreads();
    if (tid == 0) {
        float best = logits[0]; int bi = 0;
        #pragma unroll
        for (int e = 1; e < CE; e++) if (logits[e] > best) { best = logits[e]; bi = e; }
        idx[t] = bi;
        atomicAdd(&counts[bi], 1);
    }
}

__global__ void zero_ints(int* __restrict__ counts, int* __restrict__ cursor) {
    if (threadIdx.x < CE) { counts[threadIdx.x] = 0; cursor[threadIdx.x] = 0; }
}

__global__ void build_offsets(const int* __restrict__ counts, int* __restrict__ seg) {
    if (threadIdx.x == 0) {
        int a = 0;
        for (int e = 0; e < CE; e++) { seg[e] = a; a += counts[e]; }
        seg[CE] = a;
    }
}

__global__ void scatter_tokens(const int* __restrict__ idx, const int* __restrict__ seg,
                               int* __restrict__ cursor, int* __restrict__ perm) {
    int t = blockIdx.x * 256 + threadIdx.x;
    if (t >= CT) return;
    int e = idx[t];
    int p = atomicAdd(&cursor[e], 1);
    perm[seg[e] + p] = t;
}

// ---------------- int8 x ternary GEMM via IMMA tensor cores ----------------
// 64x64 output tile, 4 warps (128 threads), K staged 64 at a time in smem.
// Accumulation in int32 (exact); scaled fp32 epilogue per MODE.
// MODE 0: QKV -> fp32 dest [3][B,NH,S,HD]
// MODE 1: O-proj: out = resid + val, [T,H] fp32
// MODE 2: MoE gate/up: rows gathered via perm; out[slot, D] fp32
// MODE 3: MoE down: out[tok] = resid[tok] + val
template<int MODE>
__global__ void __launch_bounds__(128) gemm_imma(
        const int8_t* __restrict__ A, const int8_t* __restrict__ Bw,
        float* __restrict__ Out,
        const float* __restrict__ ascale,
        const float* __restrict__ wscale,
        const float* __restrict__ resid,
        const int* __restrict__ perm,
        const int* __restrict__ seg) {
    int n0 = blockIdx.x * 64;
    int m0 = blockIdx.y * 64;
    int z = blockIdx.z;

    int off = 0, cnt = CT;
    if (MODE >= 2) {
        off = seg[z];
        cnt = seg[z + 1] - off;
        if (m0 >= cnt) return;
    }

    const int8_t* Bz = Bw;
    if (MODE == 0) Bz = Bw + (size_t)z * (CH * CH);
    if (MODE >= 2) Bz = Bw + (size_t)z * ((size_t)CD * CH);
    const int8_t* brow0 = Bz + (size_t)n0 * 1024;

    __shared__ int8_t As[64][80];
    __shared__ int8_t Bs[64][80];
    __shared__ int    Cs[64][68];
    __shared__ const int8_t* aptr[64];

    int tid = threadIdx.x;
    int w = tid >> 5;

    if (tid < 64) {
        int r = m0 + tid;
        const int8_t* p;
        if (MODE <= 1) {
            p = A + (size_t)r * 1024;
        } else if (MODE == 2) {
            int rr = r < cnt - 1 ? r : cnt - 1;
            p = A + (size_t)perm[off + rr] * 1024;
        } else {
            int rr = r < cnt - 1 ? r : cnt - 1;
            p = A + (size_t)(off + rr) * 1024;
        }
        aptr[tid] = p;
    }

    wmma::fragment<wmma::accumulator, 16, 16, 16, int> c[4];
    #pragma unroll
    for (int j = 0; j < 4; j++) wmma::fill_fragment(c[j], 0);

    for (int kt = 0; kt < 1024; kt += 64) {
        __syncthreads();
        #pragma unroll
        for (int i = tid; i < 256; i += 128) {
            int row = i >> 2, c16 = (i & 3) << 4;
            *(int4*)&As[row][c16] = *(const int4*)(aptr[row] + kt + c16);
            *(int4*)&Bs[row][c16] = *(const int4*)(brow0 + (size_t)row * 1024 + kt + c16);
        }
        __syncthreads();
        #pragma unroll
        for (int kk = 0; kk < 4; kk++) {
            wmma::fragment<wmma::matrix_a, 16, 16, 16, signed char, wmma::row_major> a;
            wmma::load_matrix_sync(a, &As[w * 16][kk * 16], 80);
            #pragma unroll
            for (int j = 0; j < 4; j++) {
                wmma::fragment<wmma::matrix_b, 16, 16, 16, signed char, wmma::col_major> b;
                wmma::load_matrix_sync(b, &Bs[j * 16][kk * 16], 80);
                wmma::mma_sync(c[j], a, b, c[j]);
            }
        }
    }

    #pragma unroll
    for (int j = 0; j < 4; j++)
        wmma::store_matrix_sync(&Cs[w * 16][j * 16], c[j], 68, wmma::mem_row_major);
    __syncthreads();

    float wS = wscale[(MODE == 0 || MODE >= 2) ? z : 0];

    for (int i = tid; i < 1024; i += 128) {
        int r = i >> 4, c4 = (i & 15) << 2;
        int4 cv = *(const int4*)&Cs[r][c4];
        int gr = m0 + r;
        if (MODE == 0) {
            float av = ascale[gr] * wS;
            int b = gr / CS, sr = gr % CS;
            int nh = n0 >> 6;
            float* dst = Out + (size_t)z * ((size_t)CT * CH)
                       + (((size_t)b * CNH + nh) * CS + sr) * CHD + c4;
            float4 o = {cv.x * av, cv.y * av, cv.z * av, cv.w * av};
            *(float4*)dst = o;
        } else if (MODE == 1) {
            float av = ascale[gr] * wS;
            size_t rb = (size_t)gr * CH + n0 + c4;
            float4 rv = *(const float4*)(resid + rb);
            float4 o = {rv.x + cv.x * av, rv.y + cv.y * av, rv.z + cv.z * av, rv.w + cv.w * av};
            *(float4*)(Out + rb) = o;
        } else if (MODE == 2) {
            if (gr < cnt) {
                int tok = perm[off + gr];
                float av = ascale[tok] * wS;
                size_t rb = (size_t)(off + gr) * CD + n0 + c4;
                float4 o = {cv.x * av, cv.y * av, cv.z * av, cv.w * av};
                *(float4*)(Out + rb) = o;
            }
        } else {
            if (gr < cnt) {
                int tok = perm[off + gr];
                float av = ascale[off + gr] * wS;
                size_t rb = (size_t)tok * CH + n0 + c4;
                float4 rv = *(const float4*)(resid + rb);
                float4 o = {rv.x + cv.x * av, rv.y + cv.y * av, rv.z + cv.z * av, rv.w + cv.w * av};
                *(float4*)(Out + rb) = o;
            }
        }
    }
}

// ---------------- attention: tf32 WMMA flash, 64q x 64k tiles ----------------
static constexpr int ALD = 68;
static constexpr int ATTN_SMEM = 6 * 64 * ALD * 4 + 3 * 64 * 4;  // 105216 B

__global__ void __launch_bounds__(128) attn_tf32(
        const float* __restrict__ Qg, const float* __restrict__ Kg,
        const float* __restrict__ Vg, float* __restrict__ Hout) {
    extern __shared__ float sm[];
    float* Qs = sm;                  // 64*68
    float* Ks = Qs + 64 * ALD;
    float* Vs = Ks + 64 * ALD;
    float* Ps = Vs + 64 * ALD;
    float* Ss = Ps + 64 * ALD;
    float* Os = Ss + 64 * ALD;
    float* m_s  = Os + 64 * ALD;
    float* l_s  = m_s + 64;
    float* rs_s = l_s + 64;

    int bh = blockIdx.y;
    int q0 = blockIdx.x * 64;
    const float* Qb = Qg + (size_t)bh * CS * CHD;
    const float* Kb = Kg + (size_t)bh * CS * CHD;
    const float* Vb = Vg + (size_t)bh * CS * CHD;

    int tid = threadIdx.x;
    int w = tid >> 5, lane = tid & 31;

    for (int i = tid; i < 1024; i += 128) {
        int row = i >> 4, c4 = (i & 15) << 2;
        *(float4*)&Qs[row * ALD + c4] = *(const float4*)(Qb + (size_t)(q0 + row) * CHD + c4);
        *(float4*)&Os[row * ALD + c4] = make_float4(0.f, 0.f, 0.f, 0.f);
    }
    if (tid < 64) { m_s[tid] = -INFINITY; l_s[tid] = 0.f; }

    int nkt = blockIdx.x + 1;
    for (int kt = 0; kt < nkt; kt++) {
        int k0 = kt * 64;
        __syncthreads();
        for (int i = tid; i < 1024; i += 128) {
            int row = i >> 4, c4 = (i & 15) << 2;
            *(float4*)&Ks[row * ALD + c4] = *(const float4*)(Kb + (size_t)(k0 + row) * CHD + c4);
            *(float4*)&Vs[row * ALD + c4] = *(const float4*)(Vb + (size_t)(k0 + row) * CHD + c4);
        }
        __syncthreads();

        // S = Q.K^T  (tf32 m16n16k8)
        {
            wmma::fragment<wmma::accumulator, 16, 16, 8, float> c[4];
            #pragma unroll
            for (int j = 0; j < 4; j++) wmma::fill_fragment(c[j], 0.f);
            #pragma unroll
            for (int kk = 0; kk < 8; kk++) {
                wmma::fragment<wmma::matrix_a, 16, 16, 8, wmma::precision::tf32, wmma::row_major> a;
                wmma::load_matrix_sync(a, Qs + (w * 16) * ALD + kk * 8, ALD);
                #pragma unroll
                for (int t2 = 0; t2 < a.num_elements; t2++) a.x[t2] = wmma::__float_to_tf32(a.x[t2]);
                #pragma unroll
                for (int j = 0; j < 4; j++) {
                    wmma::fragment<wmma::matrix_b, 16, 16, 8, wmma::precision::tf32, wmma::col_major> b;
                    wmma::load_matrix_sync(b, Ks + (j * 16) * ALD + kk * 8, ALD);
                    #pragma unroll
                    for (int t2 = 0; t2 < b.num_elements; t2++) b.x[t2] = wmma::__float_to_tf32(b.x[t2]);
                    wmma::mma_sync(c[j], a, b, c[j]);
                }
            }
            #pragma unroll
            for (int j = 0; j < 4; j++)
                wmma::store_matrix_sync(Ss + (w * 16) * ALD + j * 16, c[j], ALD, wmma::mem_row_major);
        }
        __syncthreads();

        // online softmax: 2 lanes per row, 32 cols each
        {
            int r = w * 16 + (lane >> 1);
            int c0 = (lane & 1) * 32;
            int climit = q0 + r - k0 - c0;
            const float* Srow = Ss + r * ALD + c0;
            float mx = -INFINITY;
            #pragma unroll 8
            for (int c = 0; c < 32; c++) {
                float v = Srow[c] * 0.125f;
                if (c <= climit) mx = fmaxf(mx, v);
            }
            mx = fmaxf(mx, __shfl_xor_sync(0xffffffffu, mx, 1));
            float mo = m_s[r];
            float mnew = fmaxf(mo, mx);
            float sum = 0.f;
            #pragma unroll 8
            for (int c = 0; c < 32; c++) {
                float p = 0.f;
                if (c <= climit) p = __expf(Srow[c] * 0.125f - mnew);
                Ps[r * ALD + c0 + c] = p;
                sum += p;
            }
            sum += __shfl_xor_sync(0xffffffffu, sum, 1);
            if ((lane & 1) == 0) {
                float rs = __expf(mo - mnew);
                m_s[r] = mnew;
                l_s[r] = l_s[r] * rs + sum;
                rs_s[r] = rs;
            }
        }
        __syncthreads();

        // rescale O
        for (int i = tid; i < 1024; i += 128) {
            int r = i >> 4, c4 = (i & 15) << 2;
            float rs = rs_s[r];
            float4 o = *(float4*)&Os[r * ALD + c4];
            o.x *= rs; o.y *= rs; o.z *= rs; o.w *= rs;
            *(float4*)&Os[r * ALD + c4] = o;
        }
        __syncthreads();

        // O += P.V (tf32)
        {
            #pragma unroll
            for (int j = 0; j < 4; j++) {
                wmma::fragment<wmma::accumulator, 16, 16, 8, float> c;
                wmma::load_matrix_sync(c, Os + (w * 16) * ALD + j * 16, ALD, wmma::mem_row_major);
                #pragma unroll
                for (int kk = 0; kk < 8; kk++) {
                    wmma::fragment<wmma::matrix_a, 16, 16, 8, wmma::precision::tf32, wmma::row_major> a;
                    wmma::fragment<wmma::matrix_b, 16, 16, 8, wmma::precision::tf32, wmma::row_major> b;
                    wmma::load_matrix_sync(a, Ps + (w * 16) * ALD + kk * 8, ALD);
                    wmma::load_matrix_sync(b, Vs + (kk * 8) * ALD + j * 16, ALD);
                    #pragma unroll
                    for (int t2 = 0; t2 < a.num_elements; t2++) a.x[t2] = wmma::__float_to_tf32(a.x[t2]);
                    #pragma unroll
                    for (int t2 = 0; t2 < b.num_elements; t2++) b.x[t2] = wmma::__float_to_tf32(b.x[t2]);
                    wmma::mma_sync(c, a, b, c);
                }
                wmma::store_matrix_sync(Os + (w * 16) * ALD + j * 16, c, ALD, wmma::mem_row_major);
            }
        }
    }
    __syncthreads();

    // write out [B,S,NH,HD]
    int b = bh / CNH, nh = bh % CNH;
    for (int i = tid; i < 1024; i += 128) {
        int r = i >> 4, c4 = (i & 15) << 2;
        float inv = 1.0f / l_s[r];
        float4 o = *(float4*)&Os[r * ALD + c4];
        o.x *= inv; o.y *= inv; o.z *= inv; o.w *= inv;
        *(float4*)(Hout + (((size_t)b * CS + q0 + r) * CNH + nh) * CHD + c4) = o;
    }
}

// ---------------- MoE elementwise: hh = relu(g)^2 * u, then act_quant ----------------
__global__ void hh_quant(const float* __restrict__ g, const float* __restrict__ u,
                         int8_t* __restrict__ hq, float* __restrict__ hs) {
    __shared__ float red[256];
    __shared__ float hb[CD];
    int slot = blockIdx.x, tid = threadIdx.x;
    float amax = 0.f;
    #pragma unroll
    for (int i = 0; i < 4; i++) {
        int k = tid + i * 256;
        float gv = g[(size_t)slot * CD + k];
        float uv = u[(size_t)slot * CD + k];
        float rl = fmaxf(gv, 0.f);
        float h = rl * rl * uv;
        hb[k] = h;
        amax = fmaxf(amax, fabsf(h));
    }
    amax = blk_reduce_max(amax, red);
    float m = fmaxf(amax, 1e-5f);
    float s = 127.f / m;
    #pragma unroll
    for (int i = 0; i < 4; i++) {
        int k = tid + i * 256;
        float qv = fminf(fmaxf(rintf(hb[k] * s), -128.f), 127.f);
        hq[(size_t)slot * CD + k] = (int8_t)(int)qv;
    }
    if (tid == 0) hs[slot] = m * (1.0f / 127.f);
}

// ---------------- launch ----------------
extern "C" void kernel_launch(void* const* d_in, const int* in_sizes, int n_in,
                              void* d_out, int out_size) {
    const float* x        = (const float*)d_in[0];
    const float* q_w      = (const float*)d_in[1];
    const float* k_w      = (const float*)d_in[2];
    const float* v_w      = (const float*)d_in[3];
    const float* o_w      = (const float*)d_in[4];
    const float* ln1_w    = (const float*)d_in[5];
    const float* ln2_w    = (const float*)d_in[6];
    const float* router_w = (const float*)d_in[7];
    const float* gate_w   = (const float*)d_in[8];
    const float* up_w     = (const float*)d_in[9];
    const float* down_w   = (const float*)d_in[10];

    unsigned char* base = nullptr;
    cudaGetSymbolAddress((void**)&base, g_scratch);

    int8_t* wq_attn = (int8_t*)(base + OFF_WQ_ATTN);
    int8_t* wq_gate = (int8_t*)(base + OFF_WQ_GATE);
    int8_t* wq_up   = (int8_t*)(base + OFF_WQ_UP);
    int8_t* wq_down = (int8_t*)(base + OFF_WQ_DOWN);
    float*  wsc     = (float*)(base + OFF_WSCALE);
    float*  part    = (float*)(base + OFF_PART);
    int8_t* xq1     = (int8_t*)(base + OFF_XQ1);
    float*  a1s     = (float*)(base + OFF_A1S);
    float*  qkv     = (float*)(base + OFF_QKV);
    float*  hb      = (float*)(base + OFF_HB);
    int8_t* hqa     = (int8_t*)(base + OFF_HQA);
    float*  hsa     = (float*)(base + OFF_HSA);
    float*  x2      = (float*)(base + OFF_X2);
    int8_t* xq2     = (int8_t*)(base + OFF_XQ2);
    float*  a2s     = (float*)(base + OFF_A2S);
    int*    idx     = (int*)(base + OFF_IDX);
    int*    cnt     = (int*)(base + OFF_CNT);
    int*    seg     = (int*)(base + OFF_SEG);
    int*    cur     = (int*)(base + OFF_CUR);
    int*    perm    = (int*)(base + OFF_PERM);
    float*  gb      = (float*)(base + OFF_GB);
    float*  ub      = (float*)(base + OFF_UB);
    int8_t* hqm     = (int8_t*)(base + OFF_HQM);
    float*  hsm     = (float*)(base + OFF_HSM);
    float*  out     = (float*)d_out;

    // ---- attention path first ----
    absmean4<<<dim3(256, 4), 256>>>(q_w, k_w, v_w, o_w, part, CH * CH);
    finalize_wscale<<<1, 32>>>(part, wsc, 0, 4);
    quantize4<<<dim3(512, 4), 256>>>(q_w, k_w, v_w, o_w, wq_attn, wsc, CH * CH);
    rmsnorm_quant<<<CT, 256>>>(x, ln1_w, xq1, a1s);
    gemm_imma<0><<<dim3(16, 64, 3), 128>>>(xq1, wq_attn, qkv, a1s, wsc, nullptr, nullptr, nullptr);

    cudaFuncSetAttribute(attn_tf32, cudaFuncAttributeMaxDynamicSharedMemorySize, ATTN_SMEM);
    attn_tf32<<<dim3(32, CB * CNH), 128, ATTN_SMEM>>>(
        qkv, qkv + (size_t)CT * CH, qkv + 2 * (size_t)CT * CH, hb);

    // ---- MoE weight quant ----
    absmean_partial<<<dim3(256, 8), 256>>>(gate_w, part + 4 * 256, CD * CH);
    absmean_partial<<<dim3(256, 8), 256>>>(up_w,   part + 12 * 256, CD * CH);
    absmean_partial<<<dim3(256, 8), 256>>>(down_w, part + 20 * 256, CH * CD);
    finalize_wscale<<<1, 32>>>(part, wsc, 4, 24);
    quantize_w<<<dim3(512, 8), 256>>>(gate_w, wq_gate, wsc, 4, CD * CH);
    quantize_w<<<dim3(512, 8), 256>>>(up_w,   wq_up,   wsc, 12, CD * CH);
    quantize_w<<<dim3(512, 8), 256>>>(down_w, wq_down, wsc, 20, CH * CD);
    zero_ints<<<1, 32>>>(cnt, cur);

    // ---- o-proj + residual ----
    act_quant_rows<<<CT, 256>>>(hb, hqa, hsa);
    gemm_imma<1><<<dim3(16, 64, 1), 128>>>(hqa, wq_attn + 3 * (CH * CH), x2, hsa, wsc + 3, x, nullptr, nullptr);

    // ---- MoE ----
    rmsnorm2_router<<<CT, 256>>>(x2, ln2_w, router_w, xq2, a2s, idx, cnt);
    build_offsets<<<1, 1>>>(cnt, seg);
    scatter_tokens<<<16, 256>>>(idx, seg, cur, perm);

    gemm_imma<2><<<dim3(16, 64, 8), 128>>>(xq2, wq_gate, gb, a2s, wsc + 4, nullptr, perm, seg);
    gemm_imma<2><<<dim3(16, 64, 8), 128>>>(xq2, wq_up,   ub, a2s, wsc + 12, nullptr, perm, seg);
    hh_quant<<<CT, 256>>>(gb, ub, hqm, hsm);
    gemm_imma<3><<<dim3(16, 64, 8), 128>>>(hqm, wq_down, out, hsm, wsc + 20, x2, perm, seg);
}

// round 5
// speedup vs baseline: 1.1865x; 1.1865x over previous
#include <cuda_runtime.h>
#include <cuda_bf16.h>
#include <mma.h>
#include <math.h>
#include <stdint.h>

using namespace nvcuda;

#define CB 2
#define CS 2048
#define CH 1024
#define CNH 16
#define CHD 64
#define CE 8
#define CD 1024
#define CT (CB*CS)

#define MB (1024ull*1024ull)

// ---------------- scratch layout ----------------
static constexpr size_t OFF_WQ_ATTN = 0;               // 4 MB  int8: q,k,v,o
static constexpr size_t OFF_WQ_GATE = 4*MB;            // 8 MB
static constexpr size_t OFF_WQ_UP   = 12*MB;           // 8 MB
static constexpr size_t OFF_WQ_DOWN = 20*MB;           // 8 MB
static constexpr size_t OFF_WSCALE  = 28*MB;           // 28 floats
static constexpr size_t OFF_PART    = 28*MB + 4096;    // 28*256 floats
static constexpr size_t OFF_XQ1     = 29*MB;           // 4 MB int8
static constexpr size_t OFF_A1S     = 33*MB;           // T floats
static constexpr size_t OFF_QKV     = 34*MB;           // 24 MB bf16: q,k,v [B,NH,S,HD]
static constexpr size_t OFF_HB      = 82*MB;           // 16 MB fp32 attention out [T,H]
static constexpr size_t OFF_HQA     = 98*MB;           // 4 MB int8
static constexpr size_t OFF_HSA     = 102*MB;          // T floats
static constexpr size_t OFF_X2      = 103*MB;          // 16 MB fp32
static constexpr size_t OFF_XQ2     = 119*MB;          // 4 MB int8
static constexpr size_t OFF_A2S     = 123*MB;          // T floats
static constexpr size_t OFF_IDX     = 123*MB + 64*1024;
static constexpr size_t OFF_CNT     = 123*MB + 128*1024;
static constexpr size_t OFF_SEG     = 123*MB + 129*1024;
static constexpr size_t OFF_CUR     = 123*MB + 130*1024;
static constexpr size_t OFF_PERM    = 124*MB;          // T ints
static constexpr size_t OFF_GB      = 125*MB;          // 16 MB fp32
static constexpr size_t OFF_UB      = 141*MB;          // 16 MB fp32
static constexpr size_t OFF_HQM     = 157*MB;          // 4 MB int8
static constexpr size_t OFF_HSM     = 161*MB;          // T floats
static constexpr size_t SCRATCH_BYTES = 162*MB;

__device__ __align__(256) unsigned char g_scratch[SCRATCH_BYTES];

// ---------------- helpers ----------------
__device__ __forceinline__ float blk_reduce_sum(float v, float* red) {
    int tid = threadIdx.x;
    red[tid] = v; __syncthreads();
    #pragma unroll
    for (int s = 128; s > 0; s >>= 1) {
        if (tid < s) red[tid] += red[tid + s];
        __syncthreads();
    }
    float r = red[0]; __syncthreads();
    return r;
}

__device__ __forceinline__ float blk_reduce_max(float v, float* red) {
    int tid = threadIdx.x;
    red[tid] = v; __syncthreads();
    #pragma unroll
    for (int s = 128; s > 0; s >>= 1) {
        if (tid < s) red[tid] = fmaxf(red[tid], red[tid + s]);
        __syncthreads();
    }
    float r = red[0]; __syncthreads();
    return r;
}

// ---------------- weight quantization (float4 vectorized) ----------------
__global__ void absmean_partial(const float* __restrict__ w, float* __restrict__ part, int len4) {
    __shared__ float red[256];
    const float4* p = (const float4*)w + (size_t)blockIdx.y * len4;
    float s = 0.f;
    for (int i = blockIdx.x * 256 + threadIdx.x; i < len4; i += gridDim.x * 256) {
        float4 v = p[i];
        s += fabsf(v.x) + fabsf(v.y) + fabsf(v.z) + fabsf(v.w);
    }
    s = blk_reduce_sum(s, red);
    if (threadIdx.x == 0) part[(size_t)blockIdx.y * gridDim.x + blockIdx.x] = s;
}

__global__ void absmean4(const float* __restrict__ w0, const float* __restrict__ w1,
                         const float* __restrict__ w2, const float* __restrict__ w3,
                         float* __restrict__ part, int len4) {
    __shared__ float red[256];
    int sl = blockIdx.y;
    const float* p = sl == 0 ? w0 : sl == 1 ? w1 : sl == 2 ? w2 : w3;
    const float4* p4 = (const float4*)p;
    float s = 0.f;
    for (int i = blockIdx.x * 256 + threadIdx.x; i < len4; i += gridDim.x * 256) {
        float4 v = p4[i];
        s += fabsf(v.x) + fabsf(v.y) + fabsf(v.z) + fabsf(v.w);
    }
    s = blk_reduce_sum(s, red);
    if (threadIdx.x == 0) part[(size_t)sl * gridDim.x + blockIdx.x] = s;
}

__global__ void finalize_wscale(const float* __restrict__ part, float* __restrict__ wsc,
                                int i0, int n) {
    int i = i0 + threadIdx.x;
    if (threadIdx.x >= n) return;
    float s = 0.f;
    for (int j = 0; j < 256; j++) s += part[i * 256 + j];
    wsc[i] = fmaxf(s * (1.0f / (1024.f * 1024.f)), 1e-5f);
}

__device__ __forceinline__ char quant_tern(float v, float s) {
    float q = rintf(v * s);
    q = fminf(fmaxf(q, -1.f), 1.f);
    return (char)(int)q;
}

__global__ void quantize_w(const float* __restrict__ w, int8_t* __restrict__ wq,
                           const float* __restrict__ wsc, int widx0, int len4) {
    int slice = blockIdx.y;
    float s = 1.0f / wsc[widx0 + slice];
    const float4* p = (const float4*)w + (size_t)slice * len4;
    char4* q = (char4*)wq + (size_t)slice * len4;
    for (int i = blockIdx.x * 256 + threadIdx.x; i < len4; i += gridDim.x * 256) {
        float4 v = p[i];
        char4 o;
        o.x = quant_tern(v.x, s); o.y = quant_tern(v.y, s);
        o.z = quant_tern(v.z, s); o.w = quant_tern(v.w, s);
        q[i] = o;
    }
}

__global__ void quantize4(const float* __restrict__ w0, const float* __restrict__ w1,
                          const float* __restrict__ w2, const float* __restrict__ w3,
                          int8_t* __restrict__ wq, const float* __restrict__ wsc, int len4) {
    int sl = blockIdx.y;
    const float* p = sl == 0 ? w0 : sl == 1 ? w1 : sl == 2 ? w2 : w3;
    const float4* p4 = (const float4*)p;
    float s = 1.0f / wsc[sl];
    char4* q = (char4*)wq + (size_t)sl * len4;
    for (int i = blockIdx.x * 256 + threadIdx.x; i < len4; i += gridDim.x * 256) {
        float4 v = p4[i];
        char4 o;
        o.x = quant_tern(v.x, s); o.y = quant_tern(v.y, s);
        o.z = quant_tern(v.z, s); o.w = quant_tern(v.w, s);
        q[i] = o;
    }
}

// ---------------- activation rmsnorm + quant ----------------
__global__ void rmsnorm_quant(const float* __restrict__ x, const float* __restrict__ lnw,
                              int8_t* __restrict__ xq, float* __restrict__ ainv) {
    __shared__ float red[256];
    __shared__ float xs[CH];
    int t = blockIdx.x, tid = threadIdx.x;
    const float* xr = x + (size_t)t * CH;
    float v[4]; float ss = 0.f;
    #pragma unroll
    for (int i = 0; i < 4; i++) { v[i] = xr[tid + i * 256]; ss += v[i] * v[i]; }
    ss = blk_reduce_sum(ss, red);
    float r = rsqrtf(ss * (1.0f / CH) + 1e-5f);
    float amax = 0.f;
    #pragma unroll
    for (int i = 0; i < 4; i++) {
        float xn = v[i] * r * lnw[tid + i * 256];
        xs[tid + i * 256] = xn;
        amax = fmaxf(amax, fabsf(xn));
    }
    amax = blk_reduce_max(amax, red);
    float m = fmaxf(amax, 1e-5f);
    float s = 127.f / m;
    #pragma unroll
    for (int i = 0; i < 4; i++) {
        float qv = fminf(fmaxf(rintf(xs[tid + i * 256] * s), -128.f), 127.f);
        xq[(size_t)t * CH + tid + i * 256] = (int8_t)(int)qv;
    }
    if (tid == 0) ainv[t] = m * (1.0f / 127.f);
}

__global__ void act_quant_rows(const float* __restrict__ x, int8_t* __restrict__ xq,
                               float* __restrict__ ainv) {
    __shared__ float red[256];
    int t = blockIdx.x, tid = threadIdx.x;
    const float* xr = x + (size_t)t * CH;
    float v[4]; float amax = 0.f;
    #pragma unroll
    for (int i = 0; i < 4; i++) { v[i] = xr[tid + i * 256]; amax = fmaxf(amax, fabsf(v[i])); }
    amax = blk_reduce_max(amax, red);
    float m = fmaxf(amax, 1e-5f);
    float s = 127.f / m;
    #pragma unroll
    for (int i = 0; i < 4; i++) {
        float qv = fminf(fmaxf(rintf(v[i] * s), -128.f), 127.f);
        xq[(size_t)t * CH + tid + i * 256] = (int8_t)(int)qv;
    }
    if (tid == 0) ainv[t] = m * (1.0f / 127.f);
}

__global__ void rmsnorm2_router(const float* __restrict__ x, const float* __restrict__ lnw,
                                const float* __restrict__ rw, int8_t* __restrict__ xq,
                                float* __restrict__ ainv, int* __restrict__ idx,
                                int* __restrict__ counts) {
    __shared__ float red[256];
    __shared__ float xs[CH];
    __shared__ float logits[CE];
    int t = blockIdx.x, tid = threadIdx.x;
    const float* xr = x + (size_t)t * CH;
    float v[4]; float ss = 0.f;
    #pragma unroll
    for (int i = 0; i < 4; i++) { v[i] = xr[tid + i * 256]; ss += v[i] * v[i]; }
    ss = blk_reduce_sum(ss, red);
    float r = rsqrtf(ss * (1.0f / CH) + 1e-5f);
    float amax = 0.f;
    #pragma unroll
    for (int i = 0; i < 4; i++) {
        float xn = v[i] * r * lnw[tid + i * 256];
        xs[tid + i * 256] = xn;
        amax = fmaxf(amax, fabsf(xn));
    }
    amax = blk_reduce_max(amax, red);
    float m = fmaxf(amax, 1e-5f);
    float s = 127.f / m;
    #pragma unroll
    for (int i = 0; i < 4; i++) {
        float qv = fminf(fmaxf(rintf(xs[tid + i * 256] * s), -128.f), 127.f);
        xq[(size_t)t * CH + tid + i * 256] = (int8_t)(int)qv;
    }
    if (tid == 0) ainv[t] = m * (1.0f / 127.f);
    __syncthreads();

    int w = tid >> 5, lane = tid & 31;
    float acc = 0.f;
    for (int h = lane; h < CH; h += 32) acc += xs[h] * rw[w * CH + h];
    #pragma unroll
    for (int o = 16; o > 0; o >>= 1) acc += __shfl_down_sync(0xffffffffu, acc, o);
    if (lane == 0) logits[w] = acc;
    __syncthreads();
    if (tid == 0) {
        float best = logits[0]; int bi = 0;
        #pragma unroll
        for (int e = 1; e < CE; e++) if (logits[e] > best) { best = logits[e]; bi = e; }
        idx[t] = bi;
        atomicAdd(&counts[bi], 1);
    }
}

__global__ void zero_ints(int* __restrict__ counts, int* __restrict__ cursor) {
    if (threadIdx.x < CE) { counts[threadIdx.x] = 0; cursor[threadIdx.x] = 0; }
}

__global__ void build_offsets(const int* __restrict__ counts, int* __restrict__ seg) {
    if (threadIdx.x == 0) {
        int a = 0;
        for (int e = 0; e < CE; e++) { seg[e] = a; a += counts[e]; }
        seg[CE] = a;
    }
}

__global__ void scatter_tokens(const int* __restrict__ idx, const int* __restrict__ seg,
                               int* __restrict__ cursor, int* __restrict__ perm) {
    int t = blockIdx.x * 256 + threadIdx.x;
    if (t >= CT) return;
    int e = idx[t];
    int p = atomicAdd(&cursor[e], 1);
    perm[seg[e] + p] = t;
}

// ---------------- int8 x ternary GEMM via IMMA, 128x64 tile, 8 warps ----------------
// Register-prefetched K staging (64 per stage); int32 accumulation (exact).
// MODE 0: QKV -> bf16 dest [3][B,NH,S,HD]
// MODE 1: O-proj: out = resid + val, [T,H] fp32
// MODE 2: MoE gate/up: rows gathered via perm; out[slot, D] fp32
// MODE 3: MoE down: out[tok] = resid[tok] + val
template<int MODE>
__global__ void __launch_bounds__(256) gemm_imma(
        const int8_t* __restrict__ A, const int8_t* __restrict__ Bw,
        float* __restrict__ Out, __nv_bfloat16* __restrict__ OutB,
        const float* __restrict__ ascale,
        const float* __restrict__ wscale,
        const float* __restrict__ resid,
        const int* __restrict__ perm,
        const int* __restrict__ seg) {
    int n0 = blockIdx.x * 64;
    int m0 = blockIdx.y * 128;
    int z = blockIdx.z;

    int off = 0, cnt = CT;
    if (MODE >= 2) {
        off = seg[z];
        cnt = seg[z + 1] - off;
        if (m0 >= cnt) return;
    }

    const int8_t* Bz = Bw;
    if (MODE == 0) Bz = Bw + (size_t)z * (CH * CH);
    if (MODE >= 2) Bz = Bw + (size_t)z * ((size_t)CD * CH);
    const int8_t* brow0 = Bz + (size_t)n0 * 1024;

    // smem union: stage buffers (A:128x80, B:64x80 int8) alias epilogue Cs (128x68 int)
    __shared__ __align__(16) unsigned char smbuf[128 * 68 * 4];
    int8_t (*As)[80] = (int8_t(*)[80])smbuf;
    int8_t (*Bs)[80] = (int8_t(*)[80])(smbuf + 128 * 80);
    int (*Cs)[68] = (int(*)[68])smbuf;
    __shared__ const int8_t* aptr[128];

    int tid = threadIdx.x;
    int w = tid >> 5;
    int wm = w * 16;

    if (tid < 128) {
        int r = m0 + tid;
        const int8_t* p;
        if (MODE <= 1) {
            p = A + (size_t)r * 1024;
        } else if (MODE == 2) {
            int rr = r < cnt - 1 ? r : cnt - 1;
            p = A + (size_t)perm[off + rr] * 1024;
        } else {
            int rr = r < cnt - 1 ? r : cnt - 1;
            p = A + (size_t)(off + rr) * 1024;
        }
        aptr[tid] = p;
    }
    __syncthreads();

    // per-thread load assignments
    int ar0 = tid >> 1, as0 = (tid & 1) << 5;          // A: 128 rows, 2 thr/row, 32B each
    int ar1 = ar0, as1 = as0 + 16;                      // second int4
    int br = tid >> 2, bs = (tid & 3) << 4;             // B: 64 rows, 4 thr/row, 16B each
    const int8_t* pA = aptr[ar0];
    const int8_t* pB = brow0 + (size_t)br * 1024;

    int4 pa0 = *(const int4*)(pA + as0);
    int4 pa1 = *(const int4*)(pA + as1);
    int4 pb  = *(const int4*)(pB + bs);

    wmma::fragment<wmma::accumulator, 16, 16, 16, int> c[4];
    #pragma unroll
    for (int j = 0; j < 4; j++) wmma::fill_fragment(c[j], 0);

    for (int kt = 0; kt < 1024; kt += 64) {
        __syncthreads();
        *(int4*)&As[ar0][as0] = pa0;
        *(int4*)&As[ar1][as1] = pa1;
        *(int4*)&Bs[br][bs]   = pb;
        __syncthreads();
        if (kt + 64 < 1024) {
            pa0 = *(const int4*)(pA + kt + 64 + as0);
            pa1 = *(const int4*)(pA + kt + 64 + as1);
            pb  = *(const int4*)(pB + kt + 64 + bs);
        }
        #pragma unroll
        for (int kk = 0; kk < 4; kk++) {
            wmma::fragment<wmma::matrix_a, 16, 16, 16, signed char, wmma::row_major> a;
            wmma::load_matrix_sync(a, &As[wm][kk * 16], 80);
            #pragma unroll
            for (int j = 0; j < 4; j++) {
                wmma::fragment<wmma::matrix_b, 16, 16, 16, signed char, wmma::col_major> b;
                wmma::load_matrix_sync(b, &Bs[j * 16][kk * 16], 80);
                wmma::mma_sync(c[j], a, b, c[j]);
            }
        }
    }

    __syncthreads();   // all compute done before Cs aliases As/Bs
    #pragma unroll
    for (int j = 0; j < 4; j++)
        wmma::store_matrix_sync(&Cs[wm][j * 16], c[j], 68, wmma::mem_row_major);
    __syncthreads();

    float wS = wscale[(MODE == 0 || MODE >= 2) ? z : 0];

    for (int i = tid; i < 2048; i += 256) {
        int r = i >> 4, c4 = (i & 15) << 2;
        int4 cv = *(const int4*)&Cs[r][c4];
        int gr = m0 + r;
        if (MODE == 0) {
            float av = ascale[gr] * wS;
            int b = gr / CS, sr = gr % CS;
            int nh = n0 >> 6;
            __nv_bfloat16* dst = OutB + (size_t)z * ((size_t)CT * CH)
                               + (((size_t)b * CNH + nh) * CS + sr) * CHD + c4;
            __nv_bfloat162 o0 = {__float2bfloat16(cv.x * av), __float2bfloat16(cv.y * av)};
            __nv_bfloat162 o1 = {__float2bfloat16(cv.z * av), __float2bfloat16(cv.w * av)};
            *(__nv_bfloat162*)dst = o0;
            *(__nv_bfloat162*)(dst + 2) = o1;
        } else if (MODE == 1) {
            float av = ascale[gr] * wS;
            size_t rb = (size_t)gr * CH + n0 + c4;
            float4 rv = *(const float4*)(resid + rb);
            float4 o = {rv.x + cv.x * av, rv.y + cv.y * av, rv.z + cv.z * av, rv.w + cv.w * av};
            *(float4*)(Out + rb) = o;
        } else if (MODE == 2) {
            if (gr < cnt) {
                int tok = perm[off + gr];
                float av = ascale[tok] * wS;
                size_t rb = (size_t)(off + gr) * CD + n0 + c4;
                float4 o = {cv.x * av, cv.y * av, cv.z * av, cv.w * av};
                *(float4*)(Out + rb) = o;
            }
        } else {
            if (gr < cnt) {
                int tok = perm[off + gr];
                float av = ascale[off + gr] * wS;
                size_t rb = (size_t)tok * CH + n0 + c4;
                float4 rv = *(const float4*)(resid + rb);
                float4 o = {rv.x + cv.x * av, rv.y + cv.y * av, rv.z + cv.z * av, rv.w + cv.w * av};
                *(float4*)(Out + rb) = o;
            }
        }
    }
}

// ---------------- attention: bf16 WMMA flash, 64q x 64k tiles (round-3 version) ----------------
static constexpr int ALD = 72;
static constexpr int ATTN_SMEM = (64*ALD*4)*2 + (64*ALD*2)*4 + 3*64*4;  // 74496

__global__ void __launch_bounds__(128) attn_wmma(
        const __nv_bfloat16* __restrict__ Qg, const __nv_bfloat16* __restrict__ Kg,
        const __nv_bfloat16* __restrict__ Vg, float* __restrict__ Hout) {
    extern __shared__ char smraw[];
    float* Ss = (float*)smraw;                    // 64*72
    float* Os = Ss + 64*ALD;                      // 64*72
    __nv_bfloat16* Qs = (__nv_bfloat16*)(Os + 64*ALD);
    __nv_bfloat16* Ks = Qs + 64*ALD;
    __nv_bfloat16* Vs = Ks + 64*ALD;
    __nv_bfloat16* Ps = Vs + 64*ALD;
    float* m_s  = (float*)(Ps + 64*ALD);
    float* l_s  = m_s + 64;
    float* rs_s = l_s + 64;

    int bh = blockIdx.y;
    int q0 = blockIdx.x * 64;
    const __nv_bfloat16* Qb = Qg + (size_t)bh * CS * CHD;
    const __nv_bfloat16* Kb = Kg + (size_t)bh * CS * CHD;
    const __nv_bfloat16* Vb = Vg + (size_t)bh * CS * CHD;

    int tid = threadIdx.x;
    int w = tid >> 5, lane = tid & 31;

    for (int i = tid; i < 512; i += 128) {
        int row = i >> 3, c8 = (i & 7) * 8;
        *(uint4*)&Qs[row * ALD + c8] = *(const uint4*)(Qb + (size_t)(q0 + row) * CHD + c8);
    }
    for (int i = tid; i < 4096; i += 128) Os[(i >> 6) * ALD + (i & 63)] = 0.f;
    if (tid < 64) { m_s[tid] = -INFINITY; l_s[tid] = 0.f; }

    int nkt = blockIdx.x + 1;
    for (int kt = 0; kt < nkt; kt++) {
        int k0 = kt * 64;
        __syncthreads();
        for (int i = tid; i < 512; i += 128) {
            int row = i >> 3, c8 = (i & 7) * 8;
            *(uint4*)&Ks[row * ALD + c8] = *(const uint4*)(Kb + (size_t)(k0 + row) * CHD + c8);
            *(uint4*)&Vs[row * ALD + c8] = *(const uint4*)(Vb + (size_t)(k0 + row) * CHD + c8);
        }
        __syncthreads();

        // S = Q.K^T
        {
            wmma::fragment<wmma::accumulator, 16, 16, 16, float> c[4];
            #pragma unroll
            for (int j = 0; j < 4; j++) wmma::fill_fragment(c[j], 0.f);
            #pragma unroll
            for (int kk = 0; kk < 4; kk++) {
                wmma::fragment<wmma::matrix_a, 16, 16, 16, __nv_bfloat16, wmma::row_major> a;
                wmma::load_matrix_sync(a, Qs + (w * 16) * ALD + kk * 16, ALD);
                #pragma unroll
                for (int j = 0; j < 4; j++) {
                    wmma::fragment<wmma::matrix_b, 16, 16, 16, __nv_bfloat16, wmma::col_major> b;
                    wmma::load_matrix_sync(b, Ks + (j * 16) * ALD + kk * 16, ALD);
                    wmma::mma_sync(c[j], a, b, c[j]);
                }
            }
            #pragma unroll
            for (int j = 0; j < 4; j++)
                wmma::store_matrix_sync(Ss + (w * 16) * ALD + j * 16, c[j], ALD, wmma::mem_row_major);
        }
        __syncthreads();

        // online softmax: 2 lanes per row, 32 cols each
        {
            int r = w * 16 + (lane >> 1);
            int c0 = (lane & 1) * 32;
            int qglob = q0 + r;
            int climit = qglob - k0 - c0;
            const float* Srow = Ss + r * ALD + c0;
            float mx = -INFINITY;
            #pragma unroll 8
            for (int c = 0; c < 32; c++) {
                float v = Srow[c] * 0.125f;
                if (c <= climit) mx = fmaxf(mx, v);
            }
            mx = fmaxf(mx, __shfl_xor_sync(0xffffffffu, mx, 1));
            float mo = m_s[r];
            float mnew = fmaxf(mo, mx);
            float sum = 0.f;
            #pragma unroll 8
            for (int c = 0; c < 32; c++) {
                float p = 0.f;
                if (c <= climit) p = __expf(Srow[c] * 0.125f - mnew);
                Ps[r * ALD + c0 + c] = __float2bfloat16(p);
                sum += p;
            }
            sum += __shfl_xor_sync(0xffffffffu, sum, 1);
            if ((lane & 1) == 0) {
                float rs = __expf(mo - mnew);
                m_s[r] = mnew;
                l_s[r] = l_s[r] * rs + sum;
                rs_s[r] = rs;
            }
        }
        __syncthreads();

        // rescale O
        for (int i = tid; i < 4096; i += 128) {
            int r = i >> 6, c = i & 63;
            Os[r * ALD + c] *= rs_s[r];
        }
        __syncthreads();

        // O += P.V
        {
            #pragma unroll
            for (int j = 0; j < 4; j++) {
                wmma::fragment<wmma::accumulator, 16, 16, 16, float> c;
                wmma::load_matrix_sync(c, Os + (w * 16) * ALD + j * 16, ALD, wmma::mem_row_major);
                #pragma unroll
                for (int kk = 0; kk < 4; kk++) {
                    wmma::fragment<wmma::matrix_a, 16, 16, 16, __nv_bfloat16, wmma::row_major> a;
                    wmma::fragment<wmma::matrix_b, 16, 16, 16, __nv_bfloat16, wmma::row_major> b;
                    wmma::load_matrix_sync(a, Ps + (w * 16) * ALD + kk * 16, ALD);
                    wmma::load_matrix_sync(b, Vs + (kk * 16) * ALD + j * 16, ALD);
                    wmma::mma_sync(c, a, b, c);
                }
                wmma::store_matrix_sync(Os + (w * 16) * ALD + j * 16, c, ALD, wmma::mem_row_major);
            }
        }
    }
    __syncthreads();

    int b = bh / CNH, nh = bh % CNH;
    for (int i = tid; i < 4096; i += 128) {
        int r = i >> 6, c = i & 63;
        Hout[(((size_t)b * CS + q0 + r) * CNH + nh) * CHD + c] = Os[r * ALD + c] / l_s[r];
    }
}

// ---------------- MoE elementwise: hh = relu(g)^2 * u, then act_quant ----------------
__global__ void hh_quant(const float* __restrict__ g, const float* __restrict__ u,
                         int8_t* __restrict__ hq, float* __restrict__ hs) {
    __shared__ float red[256];
    __shared__ float hb[CD];
    int slot = blockIdx.x, tid = threadIdx.x;
    float amax = 0.f;
    #pragma unroll
    for (int i = 0; i < 4; i++) {
        int k = tid + i * 256;
        float gv = g[(size_t)slot * CD + k];
        float uv = u[(size_t)slot * CD + k];
        float rl = fmaxf(gv, 0.f);
        float h = rl * rl * uv;
        hb[k] = h;
        amax = fmaxf(amax, fabsf(h));
    }
    amax = blk_reduce_max(amax, red);
    float m = fmaxf(amax, 1e-5f);
    float s = 127.f / m;
    #pragma unroll
    for (int i = 0; i < 4; i++) {
        int k = tid + i * 256;
        float qv = fminf(fmaxf(rintf(hb[k] * s), -128.f), 127.f);
        hq[(size_t)slot * CD + k] = (int8_t)(int)qv;
    }
    if (tid == 0) hs[slot] = m * (1.0f / 127.f);
}

// ---------------- launch ----------------
extern "C" void kernel_launch(void* const* d_in, const int* in_sizes, int n_in,
                              void* d_out, int out_size) {
    const float* x        = (const float*)d_in[0];
    const float* q_w      = (const float*)d_in[1];
    const float* k_w      = (const float*)d_in[2];
    const float* v_w      = (const float*)d_in[3];
    const float* o_w      = (const float*)d_in[4];
    const float* ln1_w    = (const float*)d_in[5];
    const float* ln2_w    = (const float*)d_in[6];
    const float* router_w = (const float*)d_in[7];
    const float* gate_w   = (const float*)d_in[8];
    const float* up_w     = (const float*)d_in[9];
    const float* down_w   = (const float*)d_in[10];

    unsigned char* base = nullptr;
    cudaGetSymbolAddress((void**)&base, g_scratch);

    int8_t* wq_attn = (int8_t*)(base + OFF_WQ_ATTN);
    int8_t* wq_gate = (int8_t*)(base + OFF_WQ_GATE);
    int8_t* wq_up   = (int8_t*)(base + OFF_WQ_UP);
    int8_t* wq_down = (int8_t*)(base + OFF_WQ_DOWN);
    float*  wsc     = (float*)(base + OFF_WSCALE);
    float*  part    = (float*)(base + OFF_PART);
    int8_t* xq1     = (int8_t*)(base + OFF_XQ1);
    float*  a1s     = (float*)(base + OFF_A1S);
    __nv_bfloat16* qkvb = (__nv_bfloat16*)(base + OFF_QKV);
    float*  hb      = (float*)(base + OFF_HB);
    int8_t* hqa     = (int8_t*)(base + OFF_HQA);
    float*  hsa     = (float*)(base + OFF_HSA);
    float*  x2      = (float*)(base + OFF_X2);
    int8_t* xq2     = (int8_t*)(base + OFF_XQ2);
    float*  a2s     = (float*)(base + OFF_A2S);
    int*    idx     = (int*)(base + OFF_IDX);
    int*    cnt     = (int*)(base + OFF_CNT);
    int*    seg     = (int*)(base + OFF_SEG);
    int*    cur     = (int*)(base + OFF_CUR);
    int*    perm    = (int*)(base + OFF_PERM);
    float*  gb      = (float*)(base + OFF_GB);
    float*  ub      = (float*)(base + OFF_UB);
    int8_t* hqm     = (int8_t*)(base + OFF_HQM);
    float*  hsm     = (float*)(base + OFF_HSM);
    float*  out     = (float*)d_out;

    const int LEN4 = (CH * CH) / 4;

    // ---- attention path first ----
    rmsnorm_quant<<<CT, 256>>>(x, ln1_w, xq1, a1s);
    absmean4<<<dim3(256, 4), 256>>>(q_w, k_w, v_w, o_w, part, LEN4);
    finalize_wscale<<<1, 32>>>(part, wsc, 0, 4);
    quantize4<<<dim3(256, 4), 256>>>(q_w, k_w, v_w, o_w, wq_attn, wsc, LEN4);
    gemm_imma<0><<<dim3(16, 32, 3), 256>>>(xq1, wq_attn, nullptr, qkvb, a1s, wsc, nullptr, nullptr, nullptr);

    cudaFuncSetAttribute(attn_wmma, cudaFuncAttributeMaxDynamicSharedMemorySize, ATTN_SMEM);
    attn_wmma<<<dim3(32, CB * CNH), 128, ATTN_SMEM>>>(
        qkvb, qkvb + (size_t)CT * CH, qkvb + 2 * (size_t)CT * CH, hb);

    // ---- MoE weight quant ----
    absmean_partial<<<dim3(256, 8), 256>>>(gate_w, part + 4 * 256, LEN4);
    absmean_partial<<<dim3(256, 8), 256>>>(up_w,   part + 12 * 256, LEN4);
    absmean_partial<<<dim3(256, 8), 256>>>(down_w, part + 20 * 256, LEN4);
    finalize_wscale<<<1, 32>>>(part, wsc, 4, 24);
    quantize_w<<<dim3(256, 8), 256>>>(gate_w, wq_gate, wsc, 4, LEN4);
    quantize_w<<<dim3(256, 8), 256>>>(up_w,   wq_up,   wsc, 12, LEN4);
    quantize_w<<<dim3(256, 8), 256>>>(down_w, wq_down, wsc, 20, LEN4);
    zero_ints<<<1, 32>>>(cnt, cur);

    // ---- o-proj + residual ----
    act_quant_rows<<<CT, 256>>>(hb, hqa, hsa);
    gemm_imma<1><<<dim3(16, 32, 1), 256>>>(hqa, wq_attn + 3 * (CH * CH), x2, nullptr, hsa, wsc + 3, x, nullptr, nullptr);

    // ---- MoE ----
    rmsnorm2_router<<<CT, 256>>>(x2, ln2_w, router_w, xq2, a2s, idx, cnt);
    build_offsets<<<1, 1>>>(cnt, seg);
    scatter_tokens<<<16, 256>>>(idx, seg, cur, perm);

    gemm_imma<2><<<dim3(16, 32, 8), 256>>>(xq2, wq_gate, gb, nullptr, a2s, wsc + 4, nullptr, perm, seg);
    gemm_imma<2><<<dim3(16, 32, 8), 256>>>(xq2, wq_up,   ub, nullptr, a2s, wsc + 12, nullptr, perm, seg);
    hh_quant<<<CT, 256>>>(gb, ub, hqm, hsm);
    gemm_imma<3><<<dim3(16, 32, 8), 256>>>(hqm, wq_down, out, nullptr, hsm, wsc + 20, x2, perm, seg);
}

// round 6
// speedup vs baseline: 1.5648x; 1.3189x over previous
#include <cuda_runtime.h>
#include <cuda_bf16.h>
#include <mma.h>
#include <math.h>
#include <stdint.h>

using namespace nvcuda;

#define CB 2
#define CS 2048
#define CH 1024
#define CNH 16
#define CHD 64
#define CE 8
#define CD 1024
#define CT (CB*CS)

#define MB (1024ull*1024ull)

// ---------------- scratch layout ----------------
static constexpr size_t OFF_WQ_ATTN = 0;               // 4 MB  int8: q,k,v,o
static constexpr size_t OFF_WQ_GATE = 4*MB;            // 8 MB (gate) — contiguous with up
static constexpr size_t OFF_WQ_UP   = 12*MB;           // 8 MB
static constexpr size_t OFF_WQ_DOWN = 20*MB;           // 8 MB
static constexpr size_t OFF_WSCALE  = 28*MB;           // 28 floats
static constexpr size_t OFF_PART    = 28*MB + 4096;    // 28*256 floats
static constexpr size_t OFF_XQ1     = 29*MB;           // 4 MB int8
static constexpr size_t OFF_A1S     = 33*MB;           // T floats
static constexpr size_t OFF_QKV     = 34*MB;           // 24 MB bf16: q,k,v [B,NH,S,HD]
static constexpr size_t OFF_HB      = 82*MB;           // 16 MB fp32 attention out [T,H]
static constexpr size_t OFF_HQA     = 98*MB;           // 4 MB int8
static constexpr size_t OFF_HSA     = 102*MB;          // T floats
static constexpr size_t OFF_X2      = 103*MB;          // 16 MB fp32
static constexpr size_t OFF_XQ2     = 119*MB;          // 4 MB int8
static constexpr size_t OFF_A2S     = 123*MB;          // T floats
static constexpr size_t OFF_IDX     = 123*MB + 64*1024;
static constexpr size_t OFF_CNT     = 123*MB + 128*1024;
static constexpr size_t OFF_SEG     = 123*MB + 129*1024;
static constexpr size_t OFF_CUR     = 123*MB + 130*1024;
static constexpr size_t OFF_PERM    = 124*MB;          // T ints
static constexpr size_t OFF_GB      = 125*MB;          // 16 MB fp32 (gate) — contiguous with ub
static constexpr size_t OFF_UB      = 141*MB;          // 16 MB fp32
static constexpr size_t OFF_HQM     = 157*MB;          // 4 MB int8
static constexpr size_t OFF_HSM     = 161*MB;          // T floats
static constexpr size_t SCRATCH_BYTES = 162*MB;

__device__ __align__(256) unsigned char g_scratch[SCRATCH_BYTES];

// ---------------- helpers ----------------
__device__ __forceinline__ float blk_reduce_sum(float v, float* red) {
    int tid = threadIdx.x;
    red[tid] = v; __syncthreads();
    #pragma unroll
    for (int s = 128; s > 0; s >>= 1) {
        if (tid < s) red[tid] += red[tid + s];
        __syncthreads();
    }
    float r = red[0]; __syncthreads();
    return r;
}

__device__ __forceinline__ float blk_reduce_max(float v, float* red) {
    int tid = threadIdx.x;
    red[tid] = v; __syncthreads();
    #pragma unroll
    for (int s = 128; s > 0; s >>= 1) {
        if (tid < s) red[tid] = fmaxf(red[tid], red[tid + s]);
        __syncthreads();
    }
    float r = red[0]; __syncthreads();
    return r;
}

// ---------------- weight quantization (float4 vectorized) ----------------
__global__ void absmean_partial(const float* __restrict__ w, float* __restrict__ part, int len4) {
    __shared__ float red[256];
    const float4* p = (const float4*)w + (size_t)blockIdx.y * len4;
    float s = 0.f;
    for (int i = blockIdx.x * 256 + threadIdx.x; i < len4; i += gridDim.x * 256) {
        float4 v = p[i];
        s += fabsf(v.x) + fabsf(v.y) + fabsf(v.z) + fabsf(v.w);
    }
    s = blk_reduce_sum(s, red);
    if (threadIdx.x == 0) part[(size_t)blockIdx.y * gridDim.x + blockIdx.x] = s;
}

__global__ void absmean4(const float* __restrict__ w0, const float* __restrict__ w1,
                         const float* __restrict__ w2, const float* __restrict__ w3,
                         float* __restrict__ part, int len4) {
    __shared__ float red[256];
    int sl = blockIdx.y;
    const float* p = sl == 0 ? w0 : sl == 1 ? w1 : sl == 2 ? w2 : w3;
    const float4* p4 = (const float4*)p;
    float s = 0.f;
    for (int i = blockIdx.x * 256 + threadIdx.x; i < len4; i += gridDim.x * 256) {
        float4 v = p4[i];
        s += fabsf(v.x) + fabsf(v.y) + fabsf(v.z) + fabsf(v.w);
    }
    s = blk_reduce_sum(s, red);
    if (threadIdx.x == 0) part[(size_t)sl * gridDim.x + blockIdx.x] = s;
}

__global__ void finalize_wscale(const float* __restrict__ part, float* __restrict__ wsc,
                                int i0, int n) {
    int i = i0 + threadIdx.x;
    if (threadIdx.x >= n) return;
    float s = 0.f;
    for (int j = 0; j < 256; j++) s += part[i * 256 + j];
    wsc[i] = fmaxf(s * (1.0f / (1024.f * 1024.f)), 1e-5f);
}

__device__ __forceinline__ char quant_tern(float v, float s) {
    float q = rintf(v * s);
    q = fminf(fmaxf(q, -1.f), 1.f);
    return (char)(int)q;
}

__global__ void quantize_w(const float* __restrict__ w, int8_t* __restrict__ wq,
                           const float* __restrict__ wsc, int widx0, int len4) {
    int slice = blockIdx.y;
    float s = 1.0f / wsc[widx0 + slice];
    const float4* p = (const float4*)w + (size_t)slice * len4;
    char4* q = (char4*)wq + (size_t)slice * len4;
    for (int i = blockIdx.x * 256 + threadIdx.x; i < len4; i += gridDim.x * 256) {
        float4 v = p[i];
        char4 o;
        o.x = quant_tern(v.x, s); o.y = quant_tern(v.y, s);
        o.z = quant_tern(v.z, s); o.w = quant_tern(v.w, s);
        q[i] = o;
    }
}

__global__ void quantize4(const float* __restrict__ w0, const float* __restrict__ w1,
                          const float* __restrict__ w2, const float* __restrict__ w3,
                          int8_t* __restrict__ wq, const float* __restrict__ wsc, int len4) {
    int sl = blockIdx.y;
    const float* p = sl == 0 ? w0 : sl == 1 ? w1 : sl == 2 ? w2 : w3;
    const float4* p4 = (const float4*)p;
    float s = 1.0f / wsc[sl];
    char4* q = (char4*)wq + (size_t)sl * len4;
    for (int i = blockIdx.x * 256 + threadIdx.x; i < len4; i += gridDim.x * 256) {
        float4 v = p4[i];
        char4 o;
        o.x = quant_tern(v.x, s); o.y = quant_tern(v.y, s);
        o.z = quant_tern(v.z, s); o.w = quant_tern(v.w, s);
        q[i] = o;
    }
}

// ---------------- activation rmsnorm + quant ----------------
__global__ void rmsnorm_quant(const float* __restrict__ x, const float* __restrict__ lnw,
                              int8_t* __restrict__ xq, float* __restrict__ ainv) {
    __shared__ float red[256];
    __shared__ float xs[CH];
    int t = blockIdx.x, tid = threadIdx.x;
    const float* xr = x + (size_t)t * CH;
    float v[4]; float ss = 0.f;
    #pragma unroll
    for (int i = 0; i < 4; i++) { v[i] = xr[tid + i * 256]; ss += v[i] * v[i]; }
    ss = blk_reduce_sum(ss, red);
    float r = rsqrtf(ss * (1.0f / CH) + 1e-5f);
    float amax = 0.f;
    #pragma unroll
    for (int i = 0; i < 4; i++) {
        float xn = v[i] * r * lnw[tid + i * 256];
        xs[tid + i * 256] = xn;
        amax = fmaxf(amax, fabsf(xn));
    }
    amax = blk_reduce_max(amax, red);
    float m = fmaxf(amax, 1e-5f);
    float s = 127.f / m;
    #pragma unroll
    for (int i = 0; i < 4; i++) {
        float qv = fminf(fmaxf(rintf(xs[tid + i * 256] * s), -128.f), 127.f);
        xq[(size_t)t * CH + tid + i * 256] = (int8_t)(int)qv;
    }
    if (tid == 0) ainv[t] = m * (1.0f / 127.f);
}

__global__ void act_quant_rows(const float* __restrict__ x, int8_t* __restrict__ xq,
                               float* __restrict__ ainv) {
    __shared__ float red[256];
    int t = blockIdx.x, tid = threadIdx.x;
    const float* xr = x + (size_t)t * CH;
    float v[4]; float amax = 0.f;
    #pragma unroll
    for (int i = 0; i < 4; i++) { v[i] = xr[tid + i * 256]; amax = fmaxf(amax, fabsf(v[i])); }
    amax = blk_reduce_max(amax, red);
    float m = fmaxf(amax, 1e-5f);
    float s = 127.f / m;
    #pragma unroll
    for (int i = 0; i < 4; i++) {
        float qv = fminf(fmaxf(rintf(v[i] * s), -128.f), 127.f);
        xq[(size_t)t * CH + tid + i * 256] = (int8_t)(int)qv;
    }
    if (tid == 0) ainv[t] = m * (1.0f / 127.f);
}

__global__ void rmsnorm2_router(const float* __restrict__ x, const float* __restrict__ lnw,
                                const float* __restrict__ rw, int8_t* __restrict__ xq,
                                float* __restrict__ ainv, int* __restrict__ idx,
                                int* __restrict__ counts) {
    __shared__ float red[256];
    __shared__ float xs[CH];
    __shared__ float logits[CE];
    int t = blockIdx.x, tid = threadIdx.x;
    const float* xr = x + (size_t)t * CH;
    float v[4]; float ss = 0.f;
    #pragma unroll
    for (int i = 0; i < 4; i++) { v[i] = xr[tid + i * 256]; ss += v[i] * v[i]; }
    ss = blk_reduce_sum(ss, red);
    float r = rsqrtf(ss * (1.0f / CH) + 1e-5f);
    float amax = 0.f;
    #pragma unroll
    for (int i = 0; i < 4; i++) {
        float xn = v[i] * r * lnw[tid + i * 256];
        xs[tid + i * 256] = xn;
        amax = fmaxf(amax, fabsf(xn));
    }
    amax = blk_reduce_max(amax, red);
    float m = fmaxf(amax, 1e-5f);
    float s = 127.f / m;
    #pragma unroll
    for (int i = 0; i < 4; i++) {
        float qv = fminf(fmaxf(rintf(xs[tid + i * 256] * s), -128.f), 127.f);
        xq[(size_t)t * CH + tid + i * 256] = (int8_t)(int)qv;
    }
    if (tid == 0) ainv[t] = m * (1.0f / 127.f);
    __syncthreads();

    int w = tid >> 5, lane = tid & 31;
    float acc = 0.f;
    for (int h = lane; h < CH; h += 32) acc += xs[h] * rw[w * CH + h];
    #pragma unroll
    for (int o = 16; o > 0; o >>= 1) acc += __shfl_down_sync(0xffffffffu, acc, o);
    if (lane == 0) logits[w] = acc;
    __syncthreads();
    if (tid == 0) {
        float best = logits[0]; int bi = 0;
        #pragma unroll
        for (int e = 1; e < CE; e++) if (logits[e] > best) { best = logits[e]; bi = e; }
        idx[t] = bi;
        atomicAdd(&counts[bi], 1);
    }
}

__global__ void zero_ints(int* __restrict__ counts, int* __restrict__ cursor) {
    if (threadIdx.x < CE) { counts[threadIdx.x] = 0; cursor[threadIdx.x] = 0; }
}

__global__ void build_offsets(const int* __restrict__ counts, int* __restrict__ seg) {
    if (threadIdx.x == 0) {
        int a = 0;
        for (int e = 0; e < CE; e++) { seg[e] = a; a += counts[e]; }
        seg[CE] = a;
    }
}

__global__ void scatter_tokens(const int* __restrict__ idx, const int* __restrict__ seg,
                               int* __restrict__ cursor, int* __restrict__ perm) {
    int t = blockIdx.x * 256 + threadIdx.x;
    if (t >= CT) return;
    int e = idx[t];
    int p = atomicAdd(&cursor[e], 1);
    perm[seg[e] + p] = t;
}

// ---------------- int8 x ternary GEMM (dp4a) — round-3 proven version ----------------
// MODE 0: QKV -> bf16 dest [3][B,NH,S,HD]
// MODE 1: O-proj. out = resid + val, [T,H] fp32
// MODE 2: MoE gate/up merged. z in [0,16): expert = z&7, half = z>>3; out[slot, D] fp32
// MODE 3: MoE down. out scattered: out[tok] = resid[tok] + val
template<int MODE>
__global__ void gemm_i8(const int8_t* __restrict__ A, const int8_t* __restrict__ Bw,
                        float* __restrict__ Out, __nv_bfloat16* __restrict__ OutB,
                        const float* __restrict__ ascale,
                        const float* __restrict__ wscale,
                        const float* __restrict__ resid,
                        const int* __restrict__ perm,
                        const int* __restrict__ seg) {
    int n0 = blockIdx.x * 64;
    int m0 = blockIdx.y * 64;
    int z = blockIdx.z;
    int e = (MODE == 2) ? (z & 7) : z;

    int off = 0, cnt = CT;
    if (MODE >= 2) {
        off = seg[e];
        cnt = seg[e + 1] - off;
        if (m0 >= cnt) return;
    }

    const int8_t* Bz = Bw;
    if (MODE == 0) Bz = Bw + (size_t)z * (CH * CH);
    if (MODE >= 2) Bz = Bw + (size_t)z * ((size_t)CD * CH);

    __shared__ int As[16][64];
    __shared__ int Bs[16][64];

    int tid = threadIdx.x;
    int trow = tid >> 4, tcol = tid & 15;
    int lr = tid >> 2, lk = tid & 3;

    const int8_t* arow;
    {
        int r = m0 + lr;
        if (MODE <= 1) {
            arow = A + (size_t)r * 1024;
        } else if (MODE == 2) {
            int rr = r < cnt - 1 ? r : cnt - 1;
            int tok = perm[off + rr];
            arow = A + (size_t)tok * 1024;
        } else {
            int rr = r < cnt - 1 ? r : cnt - 1;
            arow = A + (size_t)(off + rr) * 1024;
        }
    }
    const int8_t* brow = Bz + (size_t)(n0 + lr) * 1024;

    int acc[4][4];
    #pragma unroll
    for (int i = 0; i < 4; i++)
        #pragma unroll
        for (int j = 0; j < 4; j++) acc[i][j] = 0;

    for (int kt = 0; kt < 1024; kt += 64) {
        int4 av = *(const int4*)(arow + kt + lk * 16);
        int4 bv = *(const int4*)(brow + kt + lk * 16);
        __syncthreads();
        As[lk * 4 + 0][lr] = av.x; As[lk * 4 + 1][lr] = av.y;
        As[lk * 4 + 2][lr] = av.z; As[lk * 4 + 3][lr] = av.w;
        Bs[lk * 4 + 0][lr] = bv.x; Bs[lk * 4 + 1][lr] = bv.y;
        Bs[lk * 4 + 2][lr] = bv.z; Bs[lk * 4 + 3][lr] = bv.w;
        __syncthreads();
        #pragma unroll
        for (int kk = 0; kk < 16; kk++) {
            int4 a4 = *(const int4*)&As[kk][trow * 4];
            int4 b4 = *(const int4*)&Bs[kk][tcol * 4];
            acc[0][0] = __dp4a(a4.x, b4.x, acc[0][0]);
            acc[0][1] = __dp4a(a4.x, b4.y, acc[0][1]);
            acc[0][2] = __dp4a(a4.x, b4.z, acc[0][2]);
            acc[0][3] = __dp4a(a4.x, b4.w, acc[0][3]);
            acc[1][0] = __dp4a(a4.y, b4.x, acc[1][0]);
            acc[1][1] = __dp4a(a4.y, b4.y, acc[1][1]);
            acc[1][2] = __dp4a(a4.y, b4.z, acc[1][2]);
            acc[1][3] = __dp4a(a4.y, b4.w, acc[1][3]);
            acc[2][0] = __dp4a(a4.z, b4.x, acc[2][0]);
            acc[2][1] = __dp4a(a4.z, b4.y, acc[2][1]);
            acc[2][2] = __dp4a(a4.z, b4.z, acc[2][2]);
            acc[2][3] = __dp4a(a4.z, b4.w, acc[2][3]);
            acc[3][0] = __dp4a(a4.w, b4.x, acc[3][0]);
            acc[3][1] = __dp4a(a4.w, b4.y, acc[3][1]);
            acc[3][2] = __dp4a(a4.w, b4.z, acc[3][2]);
            acc[3][3] = __dp4a(a4.w, b4.w, acc[3][3]);
        }
    }

    float wS = wscale[(MODE == 0 || MODE >= 2) ? z : 0];

    #pragma unroll
    for (int i = 0; i < 4; i++) {
        int r = m0 + trow * 4 + i;
        if (MODE == 0) {
            float av = ascale[r] * wS;
            int b = r / CS, sr = r % CS;
            __nv_bfloat16* dst = OutB + (size_t)z * ((size_t)CT * CH);
            #pragma unroll
            for (int j = 0; j < 4; j++) {
                int n = n0 + tcol * 4 + j;
                int nh = n >> 6, d = n & 63;
                dst[(((size_t)b * CNH + nh) * CS + sr) * CHD + d] = __float2bfloat16(acc[i][j] * av);
            }
        } else if (MODE == 1) {
            float av = ascale[r] * wS;
            size_t rb = (size_t)r * CH + n0 + tcol * 4;
            #pragma unroll
            for (int j = 0; j < 4; j++)
                Out[rb + j] = resid[rb + j] + acc[i][j] * av;
        } else if (MODE == 2) {
            if (r < cnt) {
                int tok = perm[off + r];
                float av = ascale[tok] * wS;
                size_t rb = (size_t)(z >> 3) * ((size_t)CT * CD) + (size_t)(off + r) * CD + n0 + tcol * 4;
                #pragma unroll
                for (int j = 0; j < 4; j++)
                    Out[rb + j] = acc[i][j] * av;
            }
        } else {
            if (r < cnt) {
                int tok = perm[off + r];
                float av = ascale[off + r] * wS;
                size_t rb = (size_t)tok * CH + n0 + tcol * 4;
                #pragma unroll
                for (int j = 0; j < 4; j++)
                    Out[rb + j] = resid[rb + j] + acc[i][j] * av;
            }
        }
    }
}

// ---------------- attention: bf16 WMMA flash, 64q x 64k tiles (round-3 proven) ----------------
static constexpr int ALD = 72;
static constexpr int ATTN_SMEM = (64*ALD*4)*2 + (64*ALD*2)*4 + 3*64*4;  // 74496

__global__ void __launch_bounds__(128) attn_wmma(
        const __nv_bfloat16* __restrict__ Qg, const __nv_bfloat16* __restrict__ Kg,
        const __nv_bfloat16* __restrict__ Vg, float* __restrict__ Hout) {
    extern __shared__ char smraw[];
    float* Ss = (float*)smraw;                    // 64*72
    float* Os = Ss + 64*ALD;                      // 64*72
    __nv_bfloat16* Qs = (__nv_bfloat16*)(Os + 64*ALD);
    __nv_bfloat16* Ks = Qs + 64*ALD;
    __nv_bfloat16* Vs = Ks + 64*ALD;
    __nv_bfloat16* Ps = Vs + 64*ALD;
    float* m_s  = (float*)(Ps + 64*ALD);
    float* l_s  = m_s + 64;
    float* rs_s = l_s + 64;

    int bh = blockIdx.y;
    int q0 = blockIdx.x * 64;
    const __nv_bfloat16* Qb = Qg + (size_t)bh * CS * CHD;
    const __nv_bfloat16* Kb = Kg + (size_t)bh * CS * CHD;
    const __nv_bfloat16* Vb = Vg + (size_t)bh * CS * CHD;

    int tid = threadIdx.x;
    int w = tid >> 5, lane = tid & 31;

    for (int i = tid; i < 512; i += 128) {
        int row = i >> 3, c8 = (i & 7) * 8;
        *(uint4*)&Qs[row * ALD + c8] = *(const uint4*)(Qb + (size_t)(q0 + row) * CHD + c8);
    }
    for (int i = tid; i < 4096; i += 128) Os[(i >> 6) * ALD + (i & 63)] = 0.f;
    if (tid < 64) { m_s[tid] = -INFINITY; l_s[tid] = 0.f; }

    int nkt = blockIdx.x + 1;
    for (int kt = 0; kt < nkt; kt++) {
        int k0 = kt * 64;
        __syncthreads();
        for (int i = tid; i < 512; i += 128) {
            int row = i >> 3, c8 = (i & 7) * 8;
            *(uint4*)&Ks[row * ALD + c8] = *(const uint4*)(Kb + (size_t)(k0 + row) * CHD + c8);
            *(uint4*)&Vs[row * ALD + c8] = *(const uint4*)(Vb + (size_t)(k0 + row) * CHD + c8);
        }
        __syncthreads();

        // S = Q.K^T
        {
            wmma::fragment<wmma::accumulator, 16, 16, 16, float> c[4];
            #pragma unroll
            for (int j = 0; j < 4; j++) wmma::fill_fragment(c[j], 0.f);
            #pragma unroll
            for (int kk = 0; kk < 4; kk++) {
                wmma::fragment<wmma::matrix_a, 16, 16, 16, __nv_bfloat16, wmma::row_major> a;
                wmma::load_matrix_sync(a, Qs + (w * 16) * ALD + kk * 16, ALD);
                #pragma unroll
                for (int j = 0; j < 4; j++) {
                    wmma::fragment<wmma::matrix_b, 16, 16, 16, __nv_bfloat16, wmma::col_major> b;
                    wmma::load_matrix_sync(b, Ks + (j * 16) * ALD + kk * 16, ALD);
                    wmma::mma_sync(c[j], a, b, c[j]);
                }
            }
            #pragma unroll
            for (int j = 0; j < 4; j++)
                wmma::store_matrix_sync(Ss + (w * 16) * ALD + j * 16, c[j], ALD, wmma::mem_row_major);
        }
        __syncthreads();

        // online softmax: 2 lanes per row, 32 cols each
        {
            int r = w * 16 + (lane >> 1);
            int c0 = (lane & 1) * 32;
            int qglob = q0 + r;
            int climit = qglob - k0 - c0;
            const float* Srow = Ss + r * ALD + c0;
            float mx = -INFINITY;
            #pragma unroll 8
            for (int c = 0; c < 32; c++) {
                float v = Srow[c] * 0.125f;
                if (c <= climit) mx = fmaxf(mx, v);
            }
            mx = fmaxf(mx, __shfl_xor_sync(0xffffffffu, mx, 1));
            float mo = m_s[r];
            float mnew = fmaxf(mo, mx);
            float sum = 0.f;
            #pragma unroll 8
            for (int c = 0; c < 32; c++) {
                float p = 0.f;
                if (c <= climit) p = __expf(Srow[c] * 0.125f - mnew);
                Ps[r * ALD + c0 + c] = __float2bfloat16(p);
                sum += p;
            }
            sum += __shfl_xor_sync(0xffffffffu, sum, 1);
            if ((lane & 1) == 0) {
                float rs = __expf(mo - mnew);
                m_s[r] = mnew;
                l_s[r] = l_s[r] * rs + sum;
                rs_s[r] = rs;
            }
        }
        __syncthreads();

        // rescale O
        for (int i = tid; i < 4096; i += 128) {
            int r = i >> 6, c = i & 63;
            Os[r * ALD + c] *= rs_s[r];
        }
        __syncthreads();

        // O += P.V
        {
            #pragma unroll
            for (int j = 0; j < 4; j++) {
                wmma::fragment<wmma::accumulator, 16, 16, 16, float> c;
                wmma::load_matrix_sync(c, Os + (w * 16) * ALD + j * 16, ALD, wmma::mem_row_major);
                #pragma unroll
                for (int kk = 0; kk < 4; kk++) {
                    wmma::fragment<wmma::matrix_a, 16, 16, 16, __nv_bfloat16, wmma::row_major> a;
                    wmma::fragment<wmma::matrix_b, 16, 16, 16, __nv_bfloat16, wmma::row_major> b;
                    wmma::load_matrix_sync(a, Ps + (w * 16) * ALD + kk * 16, ALD);
                    wmma::load_matrix_sync(b, Vs + (kk * 16) * ALD + j * 16, ALD);
                    wmma::mma_sync(c, a, b, c);
                }
                wmma::store_matrix_sync(Os + (w * 16) * ALD + j * 16, c, ALD, wmma::mem_row_major);
            }
        }
    }
    __syncthreads();

    int b = bh / CNH, nh = bh % CNH;
    for (int i = tid; i < 4096; i += 128) {
        int r = i >> 6, c = i & 63;
        Hout[(((size_t)b * CS + q0 + r) * CNH + nh) * CHD + c] = Os[r * ALD + c] / l_s[r];
    }
}

// ---------------- MoE elementwise: hh = relu(g)^2 * u, then act_quant ----------------
__global__ void hh_quant(const float* __restrict__ g, const float* __restrict__ u,
                         int8_t* __restrict__ hq, float* __restrict__ hs) {
    __shared__ float red[256];
    __shared__ float hb[CD];
    int slot = blockIdx.x, tid = threadIdx.x;
    float amax = 0.f;
    #pragma unroll
    for (int i = 0; i < 4; i++) {
        int k = tid + i * 256;
        float gv = g[(size_t)slot * CD + k];
        float uv = u[(size_t)slot * CD + k];
        float rl = fmaxf(gv, 0.f);
        float h = rl * rl * uv;
        hb[k] = h;
        amax = fmaxf(amax, fabsf(h));
    }
    amax = blk_reduce_max(amax, red);
    float m = fmaxf(amax, 1e-5f);
    float s = 127.f / m;
    #pragma unroll
    for (int i = 0; i < 4; i++) {
        int k = tid + i * 256;
        float qv = fminf(fmaxf(rintf(hb[k] * s), -128.f), 127.f);
        hq[(size_t)slot * CD + k] = (int8_t)(int)qv;
    }
    if (tid == 0) hs[slot] = m * (1.0f / 127.f);
}

// ---------------- launch ----------------
extern "C" void kernel_launch(void* const* d_in, const int* in_sizes, int n_in,
                              void* d_out, int out_size) {
    const float* x        = (const float*)d_in[0];
    const float* q_w      = (const float*)d_in[1];
    const float* k_w      = (const float*)d_in[2];
    const float* v_w      = (const float*)d_in[3];
    const float* o_w      = (const float*)d_in[4];
    const float* ln1_w    = (const float*)d_in[5];
    const float* ln2_w    = (const float*)d_in[6];
    const float* router_w = (const float*)d_in[7];
    const float* gate_w   = (const float*)d_in[8];
    const float* up_w     = (const float*)d_in[9];
    const float* down_w   = (const float*)d_in[10];

    unsigned char* base = nullptr;
    cudaGetSymbolAddress((void**)&base, g_scratch);

    int8_t* wq_attn = (int8_t*)(base + OFF_WQ_ATTN);
    int8_t* wq_gate = (int8_t*)(base + OFF_WQ_GATE);   // gate+up contiguous (16 slices)
    int8_t* wq_up   = (int8_t*)(base + OFF_WQ_UP);
    int8_t* wq_down = (int8_t*)(base + OFF_WQ_DOWN);
    float*  wsc     = (float*)(base + OFF_WSCALE);
    float*  part    = (float*)(base + OFF_PART);
    int8_t* xq1     = (int8_t*)(base + OFF_XQ1);
    float*  a1s     = (float*)(base + OFF_A1S);
    __nv_bfloat16* qkvb = (__nv_bfloat16*)(base + OFF_QKV);
    float*  hb      = (float*)(base + OFF_HB);
    int8_t* hqa     = (int8_t*)(base + OFF_HQA);
    float*  hsa     = (float*)(base + OFF_HSA);
    float*  x2      = (float*)(base + OFF_X2);
    int8_t* xq2     = (int8_t*)(base + OFF_XQ2);
    float*  a2s     = (float*)(base + OFF_A2S);
    int*    idx     = (int*)(base + OFF_IDX);
    int*    cnt     = (int*)(base + OFF_CNT);
    int*    seg     = (int*)(base + OFF_SEG);
    int*    cur     = (int*)(base + OFF_CUR);
    int*    perm    = (int*)(base + OFF_PERM);
    float*  gb      = (float*)(base + OFF_GB);          // gb+ub contiguous
    float*  ub      = (float*)(base + OFF_UB);
    int8_t* hqm     = (int8_t*)(base + OFF_HQM);
    float*  hsm     = (float*)(base + OFF_HSM);
    float*  out     = (float*)d_out;

    const int LEN4 = (CH * CH) / 4;

    // ---- attention path first ----
    rmsnorm_quant<<<CT, 256>>>(x, ln1_w, xq1, a1s);
    absmean4<<<dim3(256, 4), 256>>>(q_w, k_w, v_w, o_w, part, LEN4);
    finalize_wscale<<<1, 32>>>(part, wsc, 0, 4);
    quantize4<<<dim3(256, 4), 256>>>(q_w, k_w, v_w, o_w, wq_attn, wsc, LEN4);
    gemm_i8<0><<<dim3(16, 64, 3), 256>>>(xq1, wq_attn, nullptr, qkvb, a1s, wsc, nullptr, nullptr, nullptr);

    cudaFuncSetAttribute(attn_wmma, cudaFuncAttributeMaxDynamicSharedMemorySize, ATTN_SMEM);
    attn_wmma<<<dim3(32, CB * CNH), 128, ATTN_SMEM>>>(
        qkvb, qkvb + (size_t)CT * CH, qkvb + 2 * (size_t)CT * CH, hb);

    // ---- MoE weight quant (vectorized) ----
    absmean_partial<<<dim3(256, 8), 256>>>(gate_w, part + 4 * 256, LEN4);
    absmean_partial<<<dim3(256, 8), 256>>>(up_w,   part + 12 * 256, LEN4);
    absmean_partial<<<dim3(256, 8), 256>>>(down_w, part + 20 * 256, LEN4);
    finalize_wscale<<<1, 32>>>(part, wsc, 4, 24);
    quantize_w<<<dim3(256, 8), 256>>>(gate_w, wq_gate, wsc, 4, LEN4);
    quantize_w<<<dim3(256, 8), 256>>>(up_w,   wq_up,   wsc, 12, LEN4);
    quantize_w<<<dim3(256, 8), 256>>>(down_w, wq_down, wsc, 20, LEN4);
    zero_ints<<<1, 32>>>(cnt, cur);

    // ---- o-proj + residual ----
    act_quant_rows<<<CT, 256>>>(hb, hqa, hsa);
    gemm_i8<1><<<dim3(16, 64, 1), 256>>>(hqa, wq_attn + 3 * (CH * CH), x2, nullptr, hsa, wsc + 3, x, nullptr, nullptr);

    // ---- MoE ----
    rmsnorm2_router<<<CT, 256>>>(x2, ln2_w, router_w, xq2, a2s, idx, cnt);
    build_offsets<<<1, 1>>>(cnt, seg);
    scatter_tokens<<<16, 256>>>(idx, seg, cur, perm);

    // gate+up merged: z in [0,16), weights contiguous at wq_gate, outputs contiguous at gb
    gemm_i8<2><<<dim3(16, 64, 16), 256>>>(xq2, wq_gate, gb, nullptr, a2s, wsc + 4, nullptr, perm, seg);
    hh_quant<<<CT, 256>>>(gb, ub, hqm, hsm);
    gemm_i8<3><<<dim3(16, 64, 8), 256>>>(hqm, wq_down, out, nullptr, hsm, wsc + 20, x2, perm, seg);
}

// round 7
// speedup vs baseline: 1.6830x; 1.0756x over previous
#include <cuda_runtime.h>
#include <cuda_bf16.h>
#include <math.h>
#include <stdint.h>

#define CB 2
#define CS 2048
#define CH 1024
#define CNH 16
#define CHD 64
#define CE 8
#define CD 1024
#define CT (CB*CS)

#define MB (1024ull*1024ull)

// ---------------- scratch layout ----------------
static constexpr size_t OFF_WQ_ATTN = 0;               // 4 MB  int8: q,k,v,o
static constexpr size_t OFF_WQ_GATE = 4*MB;            // 8 MB (gate) — contiguous with up
static constexpr size_t OFF_WQ_UP   = 12*MB;           // 8 MB
static constexpr size_t OFF_WQ_DOWN = 20*MB;           // 8 MB
static constexpr size_t OFF_WSCALE  = 28*MB;           // 28 floats
static constexpr size_t OFF_PART    = 28*MB + 4096;    // 28*256 floats
static constexpr size_t OFF_XQ1     = 29*MB;           // 4 MB int8
static constexpr size_t OFF_A1S     = 33*MB;           // T floats
static constexpr size_t OFF_QKV     = 34*MB;           // 24 MB bf16: q,k,v [B,NH,S,HD]
static constexpr size_t OFF_HB      = 82*MB;           // 16 MB fp32 attention out [T,H]
static constexpr size_t OFF_HQA     = 98*MB;           // 4 MB int8
static constexpr size_t OFF_HSA     = 102*MB;          // T floats
static constexpr size_t OFF_X2      = 103*MB;          // 16 MB fp32
static constexpr size_t OFF_XQ2     = 119*MB;          // 4 MB int8
static constexpr size_t OFF_A2S     = 123*MB;          // T floats
static constexpr size_t OFF_IDX     = 123*MB + 64*1024;
static constexpr size_t OFF_CNT     = 123*MB + 128*1024;
static constexpr size_t OFF_SEG     = 123*MB + 129*1024;
static constexpr size_t OFF_CUR     = 123*MB + 130*1024;
static constexpr size_t OFF_PERM    = 124*MB;          // T ints
static constexpr size_t OFF_GB      = 125*MB;          // 16 MB fp32 (gate) — contiguous with ub
static constexpr size_t OFF_UB      = 141*MB;          // 16 MB fp32
static constexpr size_t OFF_HQM     = 157*MB;          // 4 MB int8
static constexpr size_t OFF_HSM     = 161*MB;          // T floats
static constexpr size_t SCRATCH_BYTES = 162*MB;

__device__ __align__(256) unsigned char g_scratch[SCRATCH_BYTES];

#include <mma.h>
using namespace nvcuda;

// ---------------- helpers ----------------
__device__ __forceinline__ float blk_reduce_sum(float v, float* red) {
    int tid = threadIdx.x;
    red[tid] = v; __syncthreads();
    #pragma unroll
    for (int s = 128; s > 0; s >>= 1) {
        if (tid < s) red[tid] += red[tid + s];
        __syncthreads();
    }
    float r = red[0]; __syncthreads();
    return r;
}

__device__ __forceinline__ float blk_reduce_max(float v, float* red) {
    int tid = threadIdx.x;
    red[tid] = v; __syncthreads();
    #pragma unroll
    for (int s = 128; s > 0; s >>= 1) {
        if (tid < s) red[tid] = fmaxf(red[tid], red[tid + s]);
        __syncthreads();
    }
    float r = red[0]; __syncthreads();
    return r;
}

// ---------------- weight quantization (float4 vectorized) ----------------
__global__ void absmean_partial(const float* __restrict__ w, float* __restrict__ part, int len4) {
    __shared__ float red[256];
    const float4* p = (const float4*)w + (size_t)blockIdx.y * len4;
    float s = 0.f;
    for (int i = blockIdx.x * 256 + threadIdx.x; i < len4; i += gridDim.x * 256) {
        float4 v = p[i];
        s += fabsf(v.x) + fabsf(v.y) + fabsf(v.z) + fabsf(v.w);
    }
    s = blk_reduce_sum(s, red);
    if (threadIdx.x == 0) part[(size_t)blockIdx.y * gridDim.x + blockIdx.x] = s;
}

__global__ void absmean4(const float* __restrict__ w0, const float* __restrict__ w1,
                         const float* __restrict__ w2, const float* __restrict__ w3,
                         float* __restrict__ part, int len4) {
    __shared__ float red[256];
    int sl = blockIdx.y;
    const float* p = sl == 0 ? w0 : sl == 1 ? w1 : sl == 2 ? w2 : w3;
    const float4* p4 = (const float4*)p;
    float s = 0.f;
    for (int i = blockIdx.x * 256 + threadIdx.x; i < len4; i += gridDim.x * 256) {
        float4 v = p4[i];
        s += fabsf(v.x) + fabsf(v.y) + fabsf(v.z) + fabsf(v.w);
    }
    s = blk_reduce_sum(s, red);
    if (threadIdx.x == 0) part[(size_t)sl * gridDim.x + blockIdx.x] = s;
}

__global__ void finalize_wscale(const float* __restrict__ part, float* __restrict__ wsc,
                                int i0, int n) {
    int i = i0 + threadIdx.x;
    if (threadIdx.x >= n) return;
    float s = 0.f;
    for (int j = 0; j < 256; j++) s += part[i * 256 + j];
    wsc[i] = fmaxf(s * (1.0f / (1024.f * 1024.f)), 1e-5f);
}

__device__ __forceinline__ char quant_tern(float v, float s) {
    float q = rintf(v * s);
    q = fminf(fmaxf(q, -1.f), 1.f);
    return (char)(int)q;
}

__global__ void quantize_w(const float* __restrict__ w, int8_t* __restrict__ wq,
                           const float* __restrict__ wsc, int widx0, int len4) {
    int slice = blockIdx.y;
    float s = 1.0f / wsc[widx0 + slice];
    const float4* p = (const float4*)w + (size_t)slice * len4;
    char4* q = (char4*)wq + (size_t)slice * len4;
    for (int i = blockIdx.x * 256 + threadIdx.x; i < len4; i += gridDim.x * 256) {
        float4 v = p[i];
        char4 o;
        o.x = quant_tern(v.x, s); o.y = quant_tern(v.y, s);
        o.z = quant_tern(v.z, s); o.w = quant_tern(v.w, s);
        q[i] = o;
    }
}

__global__ void quantize4(const float* __restrict__ w0, const float* __restrict__ w1,
                          const float* __restrict__ w2, const float* __restrict__ w3,
                          int8_t* __restrict__ wq, const float* __restrict__ wsc, int len4) {
    int sl = blockIdx.y;
    const float* p = sl == 0 ? w0 : sl == 1 ? w1 : sl == 2 ? w2 : w3;
    const float4* p4 = (const float4*)p;
    float s = 1.0f / wsc[sl];
    char4* q = (char4*)wq + (size_t)sl * len4;
    for (int i = blockIdx.x * 256 + threadIdx.x; i < len4; i += gridDim.x * 256) {
        float4 v = p4[i];
        char4 o;
        o.x = quant_tern(v.x, s); o.y = quant_tern(v.y, s);
        o.z = quant_tern(v.z, s); o.w = quant_tern(v.w, s);
        q[i] = o;
    }
}

// ---------------- activation rmsnorm + quant ----------------
__global__ void rmsnorm_quant(const float* __restrict__ x, const float* __restrict__ lnw,
                              int8_t* __restrict__ xq, float* __restrict__ ainv) {
    __shared__ float red[256];
    __shared__ float xs[CH];
    int t = blockIdx.x, tid = threadIdx.x;
    const float* xr = x + (size_t)t * CH;
    float v[4]; float ss = 0.f;
    #pragma unroll
    for (int i = 0; i < 4; i++) { v[i] = xr[tid + i * 256]; ss += v[i] * v[i]; }
    ss = blk_reduce_sum(ss, red);
    float r = rsqrtf(ss * (1.0f / CH) + 1e-5f);
    float amax = 0.f;
    #pragma unroll
    for (int i = 0; i < 4; i++) {
        float xn = v[i] * r * lnw[tid + i * 256];
        xs[tid + i * 256] = xn;
        amax = fmaxf(amax, fabsf(xn));
    }
    amax = blk_reduce_max(amax, red);
    float m = fmaxf(amax, 1e-5f);
    float s = 127.f / m;
    #pragma unroll
    for (int i = 0; i < 4; i++) {
        float qv = fminf(fmaxf(rintf(xs[tid + i * 256] * s), -128.f), 127.f);
        xq[(size_t)t * CH + tid + i * 256] = (int8_t)(int)qv;
    }
    if (tid == 0) ainv[t] = m * (1.0f / 127.f);
}

__global__ void act_quant_rows(const float* __restrict__ x, int8_t* __restrict__ xq,
                               float* __restrict__ ainv) {
    __shared__ float red[256];
    int t = blockIdx.x, tid = threadIdx.x;
    const float* xr = x + (size_t)t * CH;
    float v[4]; float amax = 0.f;
    #pragma unroll
    for (int i = 0; i < 4; i++) { v[i] = xr[tid + i * 256]; amax = fmaxf(amax, fabsf(v[i])); }
    amax = blk_reduce_max(amax, red);
    float m = fmaxf(amax, 1e-5f);
    float s = 127.f / m;
    #pragma unroll
    for (int i = 0; i < 4; i++) {
        float qv = fminf(fmaxf(rintf(v[i] * s), -128.f), 127.f);
        xq[(size_t)t * CH + tid + i * 256] = (int8_t)(int)qv;
    }
    if (tid == 0) ainv[t] = m * (1.0f / 127.f);
}

__global__ void rmsnorm2_router(const float* __restrict__ x, const float* __restrict__ lnw,
                                const float* __restrict__ rw, int8_t* __restrict__ xq,
                                float* __restrict__ ainv, int* __restrict__ idx,
                                int* __restrict__ counts) {
    __shared__ float red[256];
    __shared__ float xs[CH];
    __shared__ float logits[CE];
    int t = blockIdx.x, tid = threadIdx.x;
    const float* xr = x + (size_t)t * CH;
    float v[4]; float ss = 0.f;
    #pragma unroll
    for (int i = 0; i < 4; i++) { v[i] = xr[tid + i * 256]; ss += v[i] * v[i]; }
    ss = blk_reduce_sum(ss, red);
    float r = rsqrtf(ss * (1.0f / CH) + 1e-5f);
    float amax = 0.f;
    #pragma unroll
    for (int i = 0; i < 4; i++) {
        float xn = v[i] * r * lnw[tid + i * 256];
        xs[tid + i * 256] = xn;
        amax = fmaxf(amax, fabsf(xn));
    }
    amax = blk_reduce_max(amax, red);
    float m = fmaxf(amax, 1e-5f);
    float s = 127.f / m;
    #pragma unroll
    for (int i = 0; i < 4; i++) {
        float qv = fminf(fmaxf(rintf(xs[tid + i * 256] * s), -128.f), 127.f);
        xq[(size_t)t * CH + tid + i * 256] = (int8_t)(int)qv;
    }
    if (tid == 0) ainv[t] = m * (1.0f / 127.f);
    __syncthreads();

    int w = tid >> 5, lane = tid & 31;
    float acc = 0.f;
    for (int h = lane; h < CH; h += 32) acc += xs[h] * rw[w * CH + h];
    #pragma unroll
    for (int o = 16; o > 0; o >>= 1) acc += __shfl_down_sync(0xffffffffu, acc, o);
    if (lane == 0) logits[w] = acc;
    __syncthreads();
    if (tid == 0) {
        float best = logits[0]; int bi = 0;
        #pragma unroll
        for (int e = 1; e < CE; e++) if (logits[e] > best) { best = logits[e]; bi = e; }
        idx[t] = bi;
        atomicAdd(&counts[bi], 1);
    }
}

__global__ void zero_ints(int* __restrict__ counts, int* __restrict__ cursor) {
    if (threadIdx.x < CE) { counts[threadIdx.x] = 0; cursor[threadIdx.x] = 0; }
}

__global__ void build_offsets(const int* __restrict__ counts, int* __restrict__ seg) {
    if (threadIdx.x == 0) {
        int a = 0;
        for (int e = 0; e < CE; e++) { seg[e] = a; a += counts[e]; }
        seg[CE] = a;
    }
}

__global__ void scatter_tokens(const int* __restrict__ idx, const int* __restrict__ seg,
                               int* __restrict__ cursor, int* __restrict__ perm) {
    int t = blockIdx.x * 256 + threadIdx.x;
    if (t >= CT) return;
    int e = idx[t];
    int p = atomicAdd(&cursor[e], 1);
    perm[seg[e] + p] = t;
}

// ---------------- int8 x ternary GEMM via mma.sync m16n8k32 (IMMA) ----------------
// 128x64 block tile, 256 thr / 8 warps in 4(M)x2(N); warp tile 32x32.
// K staged 64 per iteration with register prefetch. Accum s32 (exact).
// Epilogue writes straight from accumulator registers (documented layout).
// MODE 0: QKV -> bf16 dest [3][B,NH,S,HD]
// MODE 1: O-proj. out = resid + val, [T,H] fp32
// MODE 2: MoE gate/up merged. z in [0,16): expert = z&7, half = z>>3
// MODE 3: MoE down. out[tok] = resid[tok] + val
__device__ __forceinline__ void mma_s8(int* c, const int* a, const int* b) {
    asm volatile(
        "mma.sync.aligned.m16n8k32.row.col.s32.s8.s8.s32 "
        "{%0,%1,%2,%3}, {%4,%5,%6,%7}, {%8,%9}, {%0,%1,%2,%3};"
        : "+r"(c[0]), "+r"(c[1]), "+r"(c[2]), "+r"(c[3])
        : "r"(a[0]), "r"(a[1]), "r"(a[2]), "r"(a[3]), "r"(b[0]), "r"(b[1]));
}

template<int MODE>
__global__ void __launch_bounds__(256) gemm_mma(
        const int8_t* __restrict__ A, const int8_t* __restrict__ Bw,
        float* __restrict__ Out, __nv_bfloat16* __restrict__ OutB,
        const float* __restrict__ ascale,
        const float* __restrict__ wscale,
        const float* __restrict__ resid,
        const int* __restrict__ perm,
        const int* __restrict__ seg) {
    int n0 = blockIdx.x * 64;
    int m0 = blockIdx.y * 128;
    int z = blockIdx.z;
    int e = (MODE == 2) ? (z & 7) : z;

    int off = 0, cnt = CT;
    if (MODE >= 2) {
        off = seg[e];
        cnt = seg[e + 1] - off;
        if (m0 >= cnt) return;
    }

    const int8_t* Bz = Bw;
    if (MODE == 0) Bz = Bw + (size_t)z * (CH * CH);
    if (MODE >= 2) Bz = Bw + (size_t)z * ((size_t)CD * CH);
    const int8_t* brow0 = Bz + (size_t)n0 * 1024;

    __shared__ __align__(16) int8_t As[128][80];
    __shared__ __align__(16) int8_t Bs[64][80];
    __shared__ const int8_t* aptr[128];
    __shared__ float rowsc[128];
    __shared__ int dstrow[128];

    int tid = threadIdx.x;
    if (tid < 128) {
        int r = m0 + tid;
        if (MODE <= 1) {
            aptr[tid] = A + (size_t)r * 1024;
            rowsc[tid] = ascale[r];
        } else if (MODE == 2) {
            int rr = r < cnt - 1 ? r : cnt - 1;
            int tok = perm[off + rr];
            aptr[tid] = A + (size_t)tok * 1024;
            rowsc[tid] = ascale[tok];
            dstrow[tid] = off + r;
        } else {
            int rr = r < cnt - 1 ? r : cnt - 1;
            aptr[tid] = A + (size_t)(off + rr) * 1024;
            rowsc[tid] = ascale[off + rr];
            dstrow[tid] = perm[off + rr];
        }
    }
    __syncthreads();

    // global-load assignments
    int ar = tid >> 1, ao = (tid & 1) * 32;           // A: 128 rows, 2 thr/row, 32B each
    int brr = tid >> 2, bo = (tid & 3) * 16;          // B: 64 rows, 4 thr/row, 16B each
    const int8_t* pA = aptr[ar];
    const int8_t* pB = brow0 + (size_t)brr * 1024;

    int4 pa0 = *(const int4*)(pA + ao);
    int4 pa1 = *(const int4*)(pA + ao + 16);
    int4 pb  = *(const int4*)(pB + bo);

    int w = tid >> 5, lane = tid & 31;
    int warpM = w & 3, warpN = w >> 2;
    int gid = lane >> 2, tig = lane & 3;

    int c[2][4][4];
    #pragma unroll
    for (int i = 0; i < 2; i++)
        #pragma unroll
        for (int j = 0; j < 4; j++)
            #pragma unroll
            for (int k = 0; k < 4; k++) c[i][j][k] = 0;

    int rowA0 = warpM * 32 + gid;         // + wm*16 (+8)
    int rowB0 = warpN * 32 + gid;         // + nt*8
    int kcol = tig * 4;

    for (int kt = 0; kt < 1024; kt += 64) {
        __syncthreads();
        *(int4*)&As[ar][ao]      = pa0;
        *(int4*)&As[ar][ao + 16] = pa1;
        *(int4*)&Bs[brr][bo]     = pb;
        __syncthreads();
        if (kt + 64 < 1024) {
            pa0 = *(const int4*)(pA + kt + 64 + ao);
            pa1 = *(const int4*)(pA + kt + 64 + ao + 16);
            pb  = *(const int4*)(pB + kt + 64 + bo);
        }
        #pragma unroll
        for (int ks = 0; ks < 2; ks++) {
            int kb = ks * 32 + kcol;
            int a[2][4];
            #pragma unroll
            for (int wm = 0; wm < 2; wm++) {
                int rA = rowA0 + wm * 16;
                a[wm][0] = *(const int*)&As[rA][kb];
                a[wm][1] = *(const int*)&As[rA + 8][kb];
                a[wm][2] = *(const int*)&As[rA][kb + 16];
                a[wm][3] = *(const int*)&As[rA + 8][kb + 16];
            }
            int b[4][2];
            #pragma unroll
            for (int nt = 0; nt < 4; nt++) {
                int rB = rowB0 + nt * 8;
                b[nt][0] = *(const int*)&Bs[rB][kb];
                b[nt][1] = *(const int*)&Bs[rB][kb + 16];
            }
            #pragma unroll
            for (int wm = 0; wm < 2; wm++)
                #pragma unroll
                for (int nt = 0; nt < 4; nt++)
                    mma_s8(c[wm][nt], a[wm], b[nt]);
        }
    }

    float wS = wscale[(MODE == 0 || MODE >= 2) ? z : 0];

    // epilogue straight from registers:
    // c[wm][nt][0] = (r0, col), [1] = (r0, col+1), [2] = (r1, col), [3] = (r1, col+1)
    // r0 = warpM*32 + wm*16 + gid, r1 = r0 + 8, col = warpN*32 + nt*8 + tig*2 (local)
    #pragma unroll
    for (int wm = 0; wm < 2; wm++) {
        int r0 = warpM * 32 + wm * 16 + gid;
        int r1 = r0 + 8;
        float av0 = rowsc[r0] * wS;
        float av1 = rowsc[r1] * wS;
        #pragma unroll
        for (int nt = 0; nt < 4; nt++) {
            int colL = warpN * 32 + nt * 8 + tig * 2;
            int* cc = c[wm][nt];
            if (MODE == 0) {
                int nh = n0 >> 6;
                int gr0 = m0 + r0, gr1 = m0 + r1;
                int b0 = gr0 / CS, sr0 = gr0 % CS;
                int b1 = gr1 / CS, sr1 = gr1 % CS;
                __nv_bfloat16* base = OutB + (size_t)z * ((size_t)CT * CH);
                __nv_bfloat162 o0 = {__float2bfloat16(cc[0] * av0), __float2bfloat16(cc[1] * av0)};
                __nv_bfloat162 o1 = {__float2bfloat16(cc[2] * av1), __float2bfloat16(cc[3] * av1)};
                *(__nv_bfloat162*)(base + (((size_t)b0 * CNH + nh) * CS + sr0) * CHD + colL) = o0;
                *(__nv_bfloat162*)(base + (((size_t)b1 * CNH + nh) * CS + sr1) * CHD + colL) = o1;
            } else if (MODE == 1) {
                size_t rb0 = (size_t)(m0 + r0) * CH + n0 + colL;
                size_t rb1 = (size_t)(m0 + r1) * CH + n0 + colL;
                float2 rv0 = *(const float2*)(resid + rb0);
                float2 rv1 = *(const float2*)(resid + rb1);
                float2 o0 = {rv0.x + cc[0] * av0, rv0.y + cc[1] * av0};
                float2 o1 = {rv1.x + cc[2] * av1, rv1.y + cc[3] * av1};
                *(float2*)(Out + rb0) = o0;
                *(float2*)(Out + rb1) = o1;
            } else if (MODE == 2) {
                size_t half = (size_t)(z >> 3) * ((size_t)CT * CD);
                if (m0 + r0 < cnt) {
                    size_t rb = half + (size_t)dstrow[r0] * CD + n0 + colL;
                    float2 o = {cc[0] * av0, cc[1] * av0};
                    *(float2*)(Out + rb) = o;
                }
                if (m0 + r1 < cnt) {
                    size_t rb = half + (size_t)dstrow[r1] * CD + n0 + colL;
                    float2 o = {cc[2] * av1, cc[3] * av1};
                    *(float2*)(Out + rb) = o;
                }
            } else {
                if (m0 + r0 < cnt) {
                    size_t rb = (size_t)dstrow[r0] * CH + n0 + colL;
                    float2 rv = *(const float2*)(resid + rb);
                    float2 o = {rv.x + cc[0] * av0, rv.y + cc[1] * av0};
                    *(float2*)(Out + rb) = o;
                }
                if (m0 + r1 < cnt) {
                    size_t rb = (size_t)dstrow[r1] * CH + n0 + colL;
                    float2 rv = *(const float2*)(resid + rb);
                    float2 o = {rv.x + cc[2] * av1, rv.y + cc[3] * av1};
                    *(float2*)(Out + rb) = o;
                }
            }
        }
    }
}

// ---------------- attention: bf16 WMMA flash, 64q x 64k tiles (round-3 proven) ----------------
static constexpr int ALD = 72;
static constexpr int ATTN_SMEM = (64*ALD*4)*2 + (64*ALD*2)*4 + 3*64*4;  // 74496

__global__ void __launch_bounds__(128) attn_wmma(
        const __nv_bfloat16* __restrict__ Qg, const __nv_bfloat16* __restrict__ Kg,
        const __nv_bfloat16* __restrict__ Vg, float* __restrict__ Hout) {
    extern __shared__ char smraw[];
    float* Ss = (float*)smraw;                    // 64*72
    float* Os = Ss + 64*ALD;                      // 64*72
    __nv_bfloat16* Qs = (__nv_bfloat16*)(Os + 64*ALD);
    __nv_bfloat16* Ks = Qs + 64*ALD;
    __nv_bfloat16* Vs = Ks + 64*ALD;
    __nv_bfloat16* Ps = Vs + 64*ALD;
    float* m_s  = (float*)(Ps + 64*ALD);
    float* l_s  = m_s + 64;
    float* rs_s = l_s + 64;

    int bh = blockIdx.y;
    int q0 = blockIdx.x * 64;
    const __nv_bfloat16* Qb = Qg + (size_t)bh * CS * CHD;
    const __nv_bfloat16* Kb = Kg + (size_t)bh * CS * CHD;
    const __nv_bfloat16* Vb = Vg + (size_t)bh * CS * CHD;

    int tid = threadIdx.x;
    int w = tid >> 5, lane = tid & 31;

    for (int i = tid; i < 512; i += 128) {
        int row = i >> 3, c8 = (i & 7) * 8;
        *(uint4*)&Qs[row * ALD + c8] = *(const uint4*)(Qb + (size_t)(q0 + row) * CHD + c8);
    }
    for (int i = tid; i < 4096; i += 128) Os[(i >> 6) * ALD + (i & 63)] = 0.f;
    if (tid < 64) { m_s[tid] = -INFINITY; l_s[tid] = 0.f; }

    int nkt = blockIdx.x + 1;
    for (int kt = 0; kt < nkt; kt++) {
        int k0 = kt * 64;
        __syncthreads();
        for (int i = tid; i < 512; i += 128) {
            int row = i >> 3, c8 = (i & 7) * 8;
            *(uint4*)&Ks[row * ALD + c8] = *(const uint4*)(Kb + (size_t)(k0 + row) * CHD + c8);
            *(uint4*)&Vs[row * ALD + c8] = *(const uint4*)(Vb + (size_t)(k0 + row) * CHD + c8);
        }
        __syncthreads();

        // S = Q.K^T
        {
            wmma::fragment<wmma::accumulator, 16, 16, 16, float> c[4];
            #pragma unroll
            for (int j = 0; j < 4; j++) wmma::fill_fragment(c[j], 0.f);
            #pragma unroll
            for (int kk = 0; kk < 4; kk++) {
                wmma::fragment<wmma::matrix_a, 16, 16, 16, __nv_bfloat16, wmma::row_major> a;
                wmma::load_matrix_sync(a, Qs + (w * 16) * ALD + kk * 16, ALD);
                #pragma unroll
                for (int j = 0; j < 4; j++) {
                    wmma::fragment<wmma::matrix_b, 16, 16, 16, __nv_bfloat16, wmma::col_major> b;
                    wmma::load_matrix_sync(b, Ks + (j * 16) * ALD + kk * 16, ALD);
                    wmma::mma_sync(c[j], a, b, c[j]);
                }
            }
            #pragma unroll
            for (int j = 0; j < 4; j++)
                wmma::store_matrix_sync(Ss + (w * 16) * ALD + j * 16, c[j], ALD, wmma::mem_row_major);
        }
        __syncthreads();

        // online softmax: 2 lanes per row, 32 cols each
        {
            int r = w * 16 + (lane >> 1);
            int c0 = (lane & 1) * 32;
            int qglob = q0 + r;
            int climit = qglob - k0 - c0;
            const float* Srow = Ss + r * ALD + c0;
            float mx = -INFINITY;
            #pragma unroll 8
            for (int c = 0; c < 32; c++) {
                float v = Srow[c] * 0.125f;
                if (c <= climit) mx = fmaxf(mx, v);
            }
            mx = fmaxf(mx, __shfl_xor_sync(0xffffffffu, mx, 1));
            float mo = m_s[r];
            float mnew = fmaxf(mo, mx);
            float sum = 0.f;
            #pragma unroll 8
            for (int c = 0; c < 32; c++) {
                float p = 0.f;
                if (c <= climit) p = __expf(Srow[c] * 0.125f - mnew);
                Ps[r * ALD + c0 + c] = __float2bfloat16(p);
                sum += p;
            }
            sum += __shfl_xor_sync(0xffffffffu, sum, 1);
            if ((lane & 1) == 0) {
                float rs = __expf(mo - mnew);
                m_s[r] = mnew;
                l_s[r] = l_s[r] * rs + sum;
                rs_s[r] = rs;
            }
        }
        __syncthreads();

        // rescale O
        for (int i = tid; i < 4096; i += 128) {
            int r = i >> 6, c = i & 63;
            Os[r * ALD + c] *= rs_s[r];
        }
        __syncthreads();

        // O += P.V
        {
            #pragma unroll
            for (int j = 0; j < 4; j++) {
                wmma::fragment<wmma::accumulator, 16, 16, 16, float> c;
                wmma::load_matrix_sync(c, Os + (w * 16) * ALD + j * 16, ALD, wmma::mem_row_major);
                #pragma unroll
                for (int kk = 0; kk < 4; kk++) {
                    wmma::fragment<wmma::matrix_a, 16, 16, 16, __nv_bfloat16, wmma::row_major> a;
                    wmma::fragment<wmma::matrix_b, 16, 16, 16, __nv_bfloat16, wmma::row_major> b;
                    wmma::load_matrix_sync(a, Ps + (w * 16) * ALD + kk * 16, ALD);
                    wmma::load_matrix_sync(b, Vs + (kk * 16) * ALD + j * 16, ALD);
                    wmma::mma_sync(c, a, b, c);
                }
                wmma::store_matrix_sync(Os + (w * 16) * ALD + j * 16, c, ALD, wmma::mem_row_major);
            }
        }
    }
    __syncthreads();

    int b = bh / CNH, nh = bh % CNH;
    for (int i = tid; i < 4096; i += 128) {
        int r = i >> 6, c = i & 63;
        Hout[(((size_t)b * CS + q0 + r) * CNH + nh) * CHD + c] = Os[r * ALD + c] / l_s[r];
    }
}

// ---------------- MoE elementwise: hh = relu(g)^2 * u, then act_quant ----------------
__global__ void hh_quant(const float* __restrict__ g, const float* __restrict__ u,
                         int8_t* __restrict__ hq, float* __restrict__ hs) {
    __shared__ float red[256];
    __shared__ float hb[CD];
    int slot = blockIdx.x, tid = threadIdx.x;
    float amax = 0.f;
    #pragma unroll
    for (int i = 0; i < 4; i++) {
        int k = tid + i * 256;
        float gv = g[(size_t)slot * CD + k];
        float uv = u[(size_t)slot * CD + k];
        float rl = fmaxf(gv, 0.f);
        float h = rl * rl * uv;
        hb[k] = h;
        amax = fmaxf(amax, fabsf(h));
    }
    amax = blk_reduce_max(amax, red);
    float m = fmaxf(amax, 1e-5f);
    float s = 127.f / m;
    #pragma unroll
    for (int i = 0; i < 4; i++) {
        int k = tid + i * 256;
        float qv = fminf(fmaxf(rintf(hb[k] * s), -128.f), 127.f);
        hq[(size_t)slot * CD + k] = (int8_t)(int)qv;
    }
    if (tid == 0) hs[slot] = m * (1.0f / 127.f);
}

// ---------------- launch ----------------
extern "C" void kernel_launch(void* const* d_in, const int* in_sizes, int n_in,
                              void* d_out, int out_size) {
    const float* x        = (const float*)d_in[0];
    const float* q_w      = (const float*)d_in[1];
    const float* k_w      = (const float*)d_in[2];
    const float* v_w      = (const float*)d_in[3];
    const float* o_w      = (const float*)d_in[4];
    const float* ln1_w    = (const float*)d_in[5];
    const float* ln2_w    = (const float*)d_in[6];
    const float* router_w = (const float*)d_in[7];
    const float* gate_w   = (const float*)d_in[8];
    const float* up_w     = (const float*)d_in[9];
    const float* down_w   = (const float*)d_in[10];

    unsigned char* base = nullptr;
    cudaGetSymbolAddress((void**)&base, g_scratch);

    int8_t* wq_attn = (int8_t*)(base + OFF_WQ_ATTN);
    int8_t* wq_gate = (int8_t*)(base + OFF_WQ_GATE);   // gate+up contiguous (16 slices)
    int8_t* wq_up   = (int8_t*)(base + OFF_WQ_UP);
    int8_t* wq_down = (int8_t*)(base + OFF_WQ_DOWN);
    float*  wsc     = (float*)(base + OFF_WSCALE);
    float*  part    = (float*)(base + OFF_PART);
    int8_t* xq1     = (int8_t*)(base + OFF_XQ1);
    float*  a1s     = (float*)(base + OFF_A1S);
    __nv_bfloat16* qkvb = (__nv_bfloat16*)(base + OFF_QKV);
    float*  hb      = (float*)(base + OFF_HB);
    int8_t* hqa     = (int8_t*)(base + OFF_HQA);
    float*  hsa     = (float*)(base + OFF_HSA);
    float*  x2      = (float*)(base + OFF_X2);
    int8_t* xq2     = (int8_t*)(base + OFF_XQ2);
    float*  a2s     = (float*)(base + OFF_A2S);
    int*    idx     = (int*)(base + OFF_IDX);
    int*    cnt     = (int*)(base + OFF_CNT);
    int*    seg     = (int*)(base + OFF_SEG);
    int*    cur     = (int*)(base + OFF_CUR);
    int*    perm    = (int*)(base + OFF_PERM);
    float*  gb      = (float*)(base + OFF_GB);          // gb+ub contiguous
    float*  ub      = (float*)(base + OFF_UB);
    int8_t* hqm     = (int8_t*)(base + OFF_HQM);
    float*  hsm     = (float*)(base + OFF_HSM);
    float*  out     = (float*)d_out;

    const int LEN4 = (CH * CH) / 4;

    // ---- attention path first ----
    rmsnorm_quant<<<CT, 256>>>(x, ln1_w, xq1, a1s);
    absmean4<<<dim3(256, 4), 256>>>(q_w, k_w, v_w, o_w, part, LEN4);
    finalize_wscale<<<1, 32>>>(part, wsc, 0, 4);
    quantize4<<<dim3(256, 4), 256>>>(q_w, k_w, v_w, o_w, wq_attn, wsc, LEN4);
    gemm_mma<0><<<dim3(16, 32, 3), 256>>>(xq1, wq_attn, nullptr, qkvb, a1s, wsc, nullptr, nullptr, nullptr);

    cudaFuncSetAttribute(attn_wmma, cudaFuncAttributeMaxDynamicSharedMemorySize, ATTN_SMEM);
    attn_wmma<<<dim3(32, CB * CNH), 128, ATTN_SMEM>>>(
        qkvb, qkvb + (size_t)CT * CH, qkvb + 2 * (size_t)CT * CH, hb);

    // ---- MoE weight quant (vectorized) ----
    absmean_partial<<<dim3(256, 8), 256>>>(gate_w, part + 4 * 256, LEN4);
    absmean_partial<<<dim3(256, 8), 256>>>(up_w,   part + 12 * 256, LEN4);
    absmean_partial<<<dim3(256, 8), 256>>>(down_w, part + 20 * 256, LEN4);
    finalize_wscale<<<1, 32>>>(part, wsc, 4, 24);
    quantize_w<<<dim3(256, 8), 256>>>(gate_w, wq_gate, wsc, 4, LEN4);
    quantize_w<<<dim3(256, 8), 256>>>(up_w,   wq_up,   wsc, 12, LEN4);
    quantize_w<<<dim3(256, 8), 256>>>(down_w, wq_down, wsc, 20, LEN4);
    zero_ints<<<1, 32>>>(cnt, cur);

    // ---- o-proj + residual ----
    act_quant_rows<<<CT, 256>>>(hb, hqa, hsa);
    gemm_mma<1><<<dim3(16, 32, 1), 256>>>(hqa, wq_attn + 3 * (CH * CH), x2, nullptr, hsa, wsc + 3, x, nullptr, nullptr);

    // ---- MoE ----
    rmsnorm2_router<<<CT, 256>>>(x2, ln2_w, router_w, xq2, a2s, idx, cnt);
    build_offsets<<<1, 1>>>(cnt, seg);
    scatter_tokens<<<16, 256>>>(idx, seg, cur, perm);

    // gate+up merged: z in [0,16)
    gemm_mma<2><<<dim3(16, 32, 16), 256>>>(xq2, wq_gate, gb, nullptr, a2s, wsc + 4, nullptr, perm, seg);
    hh_quant<<<CT, 256>>>(gb, ub, hqm, hsm);
    gemm_mma<3><<<dim3(16, 32, 8), 256>>>(hqm, wq_down, out, nullptr, hsm, wsc + 20, x2, perm, seg);
}

// round 8
// speedup vs baseline: 2.4657x; 1.4650x over previous
#include <cuda_runtime.h>
#include <cuda_bf16.h>
#include <math.h>
#include <stdint.h>

#define CB 2
#define CS 2048
#define CH 1024
#define CNH 16
#define CHD 64
#define CE 8
#define CD 1024
#define CT (CB*CS)

#define MB (1024ull*1024ull)

// ---------------- scratch layout ----------------
static constexpr size_t OFF_WQ_ATTN = 0;               // 4 MB  int8: q,k,v,o
static constexpr size_t OFF_WQ_GATE = 4*MB;            // 8 MB (gate) — contiguous with up
static constexpr size_t OFF_WQ_UP   = 12*MB;           // 8 MB
static constexpr size_t OFF_WQ_DOWN = 20*MB;           // 8 MB
static constexpr size_t OFF_WSCALE  = 28*MB;           // 28 floats
static constexpr size_t OFF_PART    = 28*MB + 4096;    // 28*256 floats
static constexpr size_t OFF_XQ1     = 29*MB;           // 4 MB int8
static constexpr size_t OFF_A1S     = 33*MB;           // T floats
static constexpr size_t OFF_QKV     = 34*MB;           // 24 MB bf16: q,k,v [B,NH,S,HD]
static constexpr size_t OFF_HB      = 82*MB;           // 16 MB fp32 attention out [T,H]
static constexpr size_t OFF_HQA     = 98*MB;           // 4 MB int8
static constexpr size_t OFF_HSA     = 102*MB;          // T floats
static constexpr size_t OFF_X2      = 103*MB;          // 16 MB fp32
static constexpr size_t OFF_XQ2     = 119*MB;          // 4 MB int8
static constexpr size_t OFF_A2S     = 123*MB;          // T floats
static constexpr size_t OFF_IDX     = 123*MB + 64*1024;
static constexpr size_t OFF_CNT     = 123*MB + 128*1024;
static constexpr size_t OFF_SEG     = 123*MB + 129*1024;
static constexpr size_t OFF_CUR     = 123*MB + 130*1024;
static constexpr size_t OFF_PERM    = 124*MB;          // T ints
static constexpr size_t OFF_GB      = 125*MB;          // 16 MB fp32 (gate) — contiguous with ub
static constexpr size_t OFF_UB      = 141*MB;          // 16 MB fp32
static constexpr size_t OFF_HQM     = 157*MB;          // 4 MB int8
static constexpr size_t OFF_HSM     = 161*MB;          // T floats
static constexpr size_t SCRATCH_BYTES = 162*MB;

__device__ __align__(256) unsigned char g_scratch[SCRATCH_BYTES];

// ---------------- helpers ----------------
__device__ __forceinline__ float blk_reduce_sum(float v, float* red) {
    int tid = threadIdx.x;
    red[tid] = v; __syncthreads();
    #pragma unroll
    for (int s = 128; s > 0; s >>= 1) {
        if (tid < s) red[tid] += red[tid + s];
        __syncthreads();
    }
    float r = red[0]; __syncthreads();
    return r;
}

__device__ __forceinline__ float blk_reduce_max(float v, float* red) {
    int tid = threadIdx.x;
    red[tid] = v; __syncthreads();
    #pragma unroll
    for (int s = 128; s > 0; s >>= 1) {
        if (tid < s) red[tid] = fmaxf(red[tid], red[tid + s]);
        __syncthreads();
    }
    float r = red[0]; __syncthreads();
    return r;
}

// ---------------- weight quantization (float4 vectorized) ----------------
__global__ void absmean_partial(const float* __restrict__ w, float* __restrict__ part, int len4) {
    __shared__ float red[256];
    const float4* p = (const float4*)w + (size_t)blockIdx.y * len4;
    float s = 0.f;
    for (int i = blockIdx.x * 256 + threadIdx.x; i < len4; i += gridDim.x * 256) {
        float4 v = p[i];
        s += fabsf(v.x) + fabsf(v.y) + fabsf(v.z) + fabsf(v.w);
    }
    s = blk_reduce_sum(s, red);
    if (threadIdx.x == 0) part[(size_t)blockIdx.y * gridDim.x + blockIdx.x] = s;
}

__global__ void absmean4(const float* __restrict__ w0, const float* __restrict__ w1,
                         const float* __restrict__ w2, const float* __restrict__ w3,
                         float* __restrict__ part, int len4) {
    __shared__ float red[256];
    int sl = blockIdx.y;
    const float* p = sl == 0 ? w0 : sl == 1 ? w1 : sl == 2 ? w2 : w3;
    const float4* p4 = (const float4*)p;
    float s = 0.f;
    for (int i = blockIdx.x * 256 + threadIdx.x; i < len4; i += gridDim.x * 256) {
        float4 v = p4[i];
        s += fabsf(v.x) + fabsf(v.y) + fabsf(v.z) + fabsf(v.w);
    }
    s = blk_reduce_sum(s, red);
    if (threadIdx.x == 0) part[(size_t)sl * gridDim.x + blockIdx.x] = s;
}

__global__ void finalize_wscale(const float* __restrict__ part, float* __restrict__ wsc,
                                int i0, int n) {
    int i = i0 + threadIdx.x;
    if (threadIdx.x >= n) return;
    float s = 0.f;
    for (int j = 0; j < 256; j++) s += part[i * 256 + j];
    wsc[i] = fmaxf(s * (1.0f / (1024.f * 1024.f)), 1e-5f);
}

__device__ __forceinline__ char quant_tern(float v, float s) {
    float q = rintf(v * s);
    q = fminf(fmaxf(q, -1.f), 1.f);
    return (char)(int)q;
}

__global__ void quantize_w(const float* __restrict__ w, int8_t* __restrict__ wq,
                           const float* __restrict__ wsc, int widx0, int len4) {
    int slice = blockIdx.y;
    float s = 1.0f / wsc[widx0 + slice];
    const float4* p = (const float4*)w + (size_t)slice * len4;
    char4* q = (char4*)wq + (size_t)slice * len4;
    for (int i = blockIdx.x * 256 + threadIdx.x; i < len4; i += gridDim.x * 256) {
        float4 v = p[i];
        char4 o;
        o.x = quant_tern(v.x, s); o.y = quant_tern(v.y, s);
        o.z = quant_tern(v.z, s); o.w = quant_tern(v.w, s);
        q[i] = o;
    }
}

// fused finalize + quantize for the 4 attention matrices (each block reduces partials itself)
__global__ void quantizeF4(const float* __restrict__ w0, const float* __restrict__ w1,
                           const float* __restrict__ w2, const float* __restrict__ w3,
                           int8_t* __restrict__ wq, const float* __restrict__ part,
                           float* __restrict__ wsc, int len4) {
    __shared__ float red[256];
    int sl = blockIdx.y;
    int tid = threadIdx.x;
    float total = blk_reduce_sum(part[sl * 256 + tid], red);
    float mean = fmaxf(total * (1.0f / (1024.f * 1024.f)), 1e-5f);
    if (blockIdx.x == 0 && tid == 0) wsc[sl] = mean;
    float s = 1.0f / mean;
    const float* p = sl == 0 ? w0 : sl == 1 ? w1 : sl == 2 ? w2 : w3;
    const float4* p4 = (const float4*)p;
    char4* q = (char4*)wq + (size_t)sl * len4;
    for (int i = blockIdx.x * 256 + tid; i < len4; i += gridDim.x * 256) {
        float4 v = p4[i];
        char4 o;
        o.x = quant_tern(v.x, s); o.y = quant_tern(v.y, s);
        o.z = quant_tern(v.z, s); o.w = quant_tern(v.w, s);
        q[i] = o;
    }
}

// ---------------- activation rmsnorm + quant ----------------
__global__ void rmsnorm_quant(const float* __restrict__ x, const float* __restrict__ lnw,
                              int8_t* __restrict__ xq, float* __restrict__ ainv) {
    __shared__ float red[256];
    __shared__ float xs[CH];
    int t = blockIdx.x, tid = threadIdx.x;
    const float* xr = x + (size_t)t * CH;
    float v[4]; float ss = 0.f;
    #pragma unroll
    for (int i = 0; i < 4; i++) { v[i] = xr[tid + i * 256]; ss += v[i] * v[i]; }
    ss = blk_reduce_sum(ss, red);
    float r = rsqrtf(ss * (1.0f / CH) + 1e-5f);
    float amax = 0.f;
    #pragma unroll
    for (int i = 0; i < 4; i++) {
        float xn = v[i] * r * lnw[tid + i * 256];
        xs[tid + i * 256] = xn;
        amax = fmaxf(amax, fabsf(xn));
    }
    amax = blk_reduce_max(amax, red);
    float m = fmaxf(amax, 1e-5f);
    float s = 127.f / m;
    #pragma unroll
    for (int i = 0; i < 4; i++) {
        float qv = fminf(fmaxf(rintf(xs[tid + i * 256] * s), -128.f), 127.f);
        xq[(size_t)t * CH + tid + i * 256] = (int8_t)(int)qv;
    }
    if (tid == 0) ainv[t] = m * (1.0f / 127.f);
}

__global__ void act_quant_rows(const float* __restrict__ x, int8_t* __restrict__ xq,
                               float* __restrict__ ainv) {
    __shared__ float red[256];
    int t = blockIdx.x, tid = threadIdx.x;
    const float* xr = x + (size_t)t * CH;
    float v[4]; float amax = 0.f;
    #pragma unroll
    for (int i = 0; i < 4; i++) { v[i] = xr[tid + i * 256]; amax = fmaxf(amax, fabsf(v[i])); }
    amax = blk_reduce_max(amax, red);
    float m = fmaxf(amax, 1e-5f);
    float s = 127.f / m;
    #pragma unroll
    for (int i = 0; i < 4; i++) {
        float qv = fminf(fmaxf(rintf(v[i] * s), -128.f), 127.f);
        xq[(size_t)t * CH + tid + i * 256] = (int8_t)(int)qv;
    }
    if (tid == 0) ainv[t] = m * (1.0f / 127.f);
}

__global__ void rmsnorm2_router(const float* __restrict__ x, const float* __restrict__ lnw,
                                const float* __restrict__ rw, int8_t* __restrict__ xq,
                                float* __restrict__ ainv, int* __restrict__ idx,
                                int* __restrict__ counts) {
    __shared__ float red[256];
    __shared__ float xs[CH];
    __shared__ float logits[CE];
    int t = blockIdx.x, tid = threadIdx.x;
    const float* xr = x + (size_t)t * CH;
    float v[4]; float ss = 0.f;
    #pragma unroll
    for (int i = 0; i < 4; i++) { v[i] = xr[tid + i * 256]; ss += v[i] * v[i]; }
    ss = blk_reduce_sum(ss, red);
    float r = rsqrtf(ss * (1.0f / CH) + 1e-5f);
    float amax = 0.f;
    #pragma unroll
    for (int i = 0; i < 4; i++) {
        float xn = v[i] * r * lnw[tid + i * 256];
        xs[tid + i * 256] = xn;
        amax = fmaxf(amax, fabsf(xn));
    }
    amax = blk_reduce_max(amax, red);
    float m = fmaxf(amax, 1e-5f);
    float s = 127.f / m;
    #pragma unroll
    for (int i = 0; i < 4; i++) {
        float qv = fminf(fmaxf(rintf(xs[tid + i * 256] * s), -128.f), 127.f);
        xq[(size_t)t * CH + tid + i * 256] = (int8_t)(int)qv;
    }
    if (tid == 0) ainv[t] = m * (1.0f / 127.f);
    __syncthreads();

    int w = tid >> 5, lane = tid & 31;
    float acc = 0.f;
    for (int h = lane; h < CH; h += 32) acc += xs[h] * rw[w * CH + h];
    #pragma unroll
    for (int o = 16; o > 0; o >>= 1) acc += __shfl_down_sync(0xffffffffu, acc, o);
    if (lane == 0) logits[w] = acc;
    __syncthreads();
    if (tid == 0) {
        float best = logits[0]; int bi = 0;
        #pragma unroll
        for (int e = 1; e < CE; e++) if (logits[e] > best) { best = logits[e]; bi = e; }
        idx[t] = bi;
        atomicAdd(&counts[bi], 1);
    }
}

__global__ void zero_ints(int* __restrict__ counts, int* __restrict__ cursor) {
    if (threadIdx.x < CE) { counts[threadIdx.x] = 0; cursor[threadIdx.x] = 0; }
}

__global__ void build_offsets(const int* __restrict__ counts, int* __restrict__ seg) {
    if (threadIdx.x == 0) {
        int a = 0;
        for (int e = 0; e < CE; e++) { seg[e] = a; a += counts[e]; }
        seg[CE] = a;
    }
}

__global__ void scatter_tokens(const int* __restrict__ idx, const int* __restrict__ seg,
                               int* __restrict__ cursor, int* __restrict__ perm) {
    int t = blockIdx.x * 256 + threadIdx.x;
    if (t >= CT) return;
    int e = idx[t];
    int p = atomicAdd(&cursor[e], 1);
    perm[seg[e] + p] = t;
}

// ---------------- int8 x ternary GEMM via mma.sync m16n8k32 (round-7 proven) ----------------
__device__ __forceinline__ void mma_s8(int* c, const int* a, const int* b) {
    asm volatile(
        "mma.sync.aligned.m16n8k32.row.col.s32.s8.s8.s32 "
        "{%0,%1,%2,%3}, {%4,%5,%6,%7}, {%8,%9}, {%0,%1,%2,%3};"
        : "+r"(c[0]), "+r"(c[1]), "+r"(c[2]), "+r"(c[3])
        : "r"(a[0]), "r"(a[1]), "r"(a[2]), "r"(a[3]), "r"(b[0]), "r"(b[1]));
}

template<int MODE>
__global__ void __launch_bounds__(256) gemm_mma(
        const int8_t* __restrict__ A, const int8_t* __restrict__ Bw,
        float* __restrict__ Out, __nv_bfloat16* __restrict__ OutB,
        const float* __restrict__ ascale,
        const float* __restrict__ wscale,
        const float* __restrict__ resid,
        const int* __restrict__ perm,
        const int* __restrict__ seg) {
    int n0 = blockIdx.x * 64;
    int m0 = blockIdx.y * 128;
    int z = blockIdx.z;
    int e = (MODE == 2) ? (z & 7) : z;

    int off = 0, cnt = CT;
    if (MODE >= 2) {
        off = seg[e];
        cnt = seg[e + 1] - off;
        if (m0 >= cnt) return;
    }

    const int8_t* Bz = Bw;
    if (MODE == 0) Bz = Bw + (size_t)z * (CH * CH);
    if (MODE >= 2) Bz = Bw + (size_t)z * ((size_t)CD * CH);
    const int8_t* brow0 = Bz + (size_t)n0 * 1024;

    __shared__ __align__(16) int8_t As[128][80];
    __shared__ __align__(16) int8_t Bs[64][80];
    __shared__ const int8_t* aptr[128];
    __shared__ float rowsc[128];
    __shared__ int dstrow[128];

    int tid = threadIdx.x;
    if (tid < 128) {
        int r = m0 + tid;
        if (MODE <= 1) {
            aptr[tid] = A + (size_t)r * 1024;
            rowsc[tid] = ascale[r];
        } else if (MODE == 2) {
            int rr = r < cnt - 1 ? r : cnt - 1;
            int tok = perm[off + rr];
            aptr[tid] = A + (size_t)tok * 1024;
            rowsc[tid] = ascale[tok];
            dstrow[tid] = off + r;
        } else {
            int rr = r < cnt - 1 ? r : cnt - 1;
            aptr[tid] = A + (size_t)(off + rr) * 1024;
            rowsc[tid] = ascale[off + rr];
            dstrow[tid] = perm[off + rr];
        }
    }
    __syncthreads();

    int ar = tid >> 1, ao = (tid & 1) * 32;
    int brr = tid >> 2, bo = (tid & 3) * 16;
    const int8_t* pA = aptr[ar];
    const int8_t* pB = brow0 + (size_t)brr * 1024;

    int4 pa0 = *(const int4*)(pA + ao);
    int4 pa1 = *(const int4*)(pA + ao + 16);
    int4 pb  = *(const int4*)(pB + bo);

    int w = tid >> 5, lane = tid & 31;
    int warpM = w & 3, warpN = w >> 2;
    int gid = lane >> 2, tig = lane & 3;

    int c[2][4][4];
    #pragma unroll
    for (int i = 0; i < 2; i++)
        #pragma unroll
        for (int j = 0; j < 4; j++)
            #pragma unroll
            for (int k = 0; k < 4; k++) c[i][j][k] = 0;

    int rowA0 = warpM * 32 + gid;
    int rowB0 = warpN * 32 + gid;
    int kcol = tig * 4;

    for (int kt = 0; kt < 1024; kt += 64) {
        __syncthreads();
        *(int4*)&As[ar][ao]      = pa0;
        *(int4*)&As[ar][ao + 16] = pa1;
        *(int4*)&Bs[brr][bo]     = pb;
        __syncthreads();
        if (kt + 64 < 1024) {
            pa0 = *(const int4*)(pA + kt + 64 + ao);
            pa1 = *(const int4*)(pA + kt + 64 + ao + 16);
            pb  = *(const int4*)(pB + kt + 64 + bo);
        }
        #pragma unroll
        for (int ks = 0; ks < 2; ks++) {
            int kb = ks * 32 + kcol;
            int a[2][4];
            #pragma unroll
            for (int wm = 0; wm < 2; wm++) {
                int rA = rowA0 + wm * 16;
                a[wm][0] = *(const int*)&As[rA][kb];
                a[wm][1] = *(const int*)&As[rA + 8][kb];
                a[wm][2] = *(const int*)&As[rA][kb + 16];
                a[wm][3] = *(const int*)&As[rA + 8][kb + 16];
            }
            int b[4][2];
            #pragma unroll
            for (int nt = 0; nt < 4; nt++) {
                int rB = rowB0 + nt * 8;
                b[nt][0] = *(const int*)&Bs[rB][kb];
                b[nt][1] = *(const int*)&Bs[rB][kb + 16];
            }
            #pragma unroll
            for (int wm = 0; wm < 2; wm++)
                #pragma unroll
                for (int nt = 0; nt < 4; nt++)
                    mma_s8(c[wm][nt], a[wm], b[nt]);
        }
    }

    float wS = wscale[(MODE == 0 || MODE >= 2) ? z : 0];

    #pragma unroll
    for (int wm = 0; wm < 2; wm++) {
        int r0 = warpM * 32 + wm * 16 + gid;
        int r1 = r0 + 8;
        float av0 = rowsc[r0] * wS;
        float av1 = rowsc[r1] * wS;
        #pragma unroll
        for (int nt = 0; nt < 4; nt++) {
            int colL = warpN * 32 + nt * 8 + tig * 2;
            int* cc = c[wm][nt];
            if (MODE == 0) {
                int nh = n0 >> 6;
                int gr0 = m0 + r0, gr1 = m0 + r1;
                int b0 = gr0 / CS, sr0 = gr0 % CS;
                int b1 = gr1 / CS, sr1 = gr1 % CS;
                __nv_bfloat16* base = OutB + (size_t)z * ((size_t)CT * CH);
                __nv_bfloat162 o0 = {__float2bfloat16(cc[0] * av0), __float2bfloat16(cc[1] * av0)};
                __nv_bfloat162 o1 = {__float2bfloat16(cc[2] * av1), __float2bfloat16(cc[3] * av1)};
                *(__nv_bfloat162*)(base + (((size_t)b0 * CNH + nh) * CS + sr0) * CHD + colL) = o0;
                *(__nv_bfloat162*)(base + (((size_t)b1 * CNH + nh) * CS + sr1) * CHD + colL) = o1;
            } else if (MODE == 1) {
                size_t rb0 = (size_t)(m0 + r0) * CH + n0 + colL;
                size_t rb1 = (size_t)(m0 + r1) * CH + n0 + colL;
                float2 rv0 = *(const float2*)(resid + rb0);
                float2 rv1 = *(const float2*)(resid + rb1);
                float2 o0 = {rv0.x + cc[0] * av0, rv0.y + cc[1] * av0};
                float2 o1 = {rv1.x + cc[2] * av1, rv1.y + cc[3] * av1};
                *(float2*)(Out + rb0) = o0;
                *(float2*)(Out + rb1) = o1;
            } else if (MODE == 2) {
                size_t half = (size_t)(z >> 3) * ((size_t)CT * CD);
                if (m0 + r0 < cnt) {
                    size_t rb = half + (size_t)dstrow[r0] * CD + n0 + colL;
                    float2 o = {cc[0] * av0, cc[1] * av0};
                    *(float2*)(Out + rb) = o;
                }
                if (m0 + r1 < cnt) {
                    size_t rb = half + (size_t)dstrow[r1] * CD + n0 + colL;
                    float2 o = {cc[2] * av1, cc[3] * av1};
                    *(float2*)(Out + rb) = o;
                }
            } else {
                if (m0 + r0 < cnt) {
                    size_t rb = (size_t)dstrow[r0] * CH + n0 + colL;
                    float2 rv = *(const float2*)(resid + rb);
                    float2 o = {rv.x + cc[0] * av0, rv.y + cc[1] * av0};
                    *(float2*)(Out + rb) = o;
                }
                if (m0 + r1 < cnt) {
                    size_t rb = (size_t)dstrow[r1] * CH + n0 + colL;
                    float2 rv = *(const float2*)(resid + rb);
                    float2 o = {rv.x + cc[2] * av1, rv.y + cc[3] * av1};
                    *(float2*)(Out + rb) = o;
                }
            }
        }
    }
}

// ---------------- attention: FA2-style, register-resident, mma.sync bf16 ----------------
__device__ __forceinline__ void mma_bf16(float* c, const uint32_t* a, uint32_t b0, uint32_t b1) {
    asm volatile(
        "mma.sync.aligned.m16n8k16.row.col.f32.bf16.bf16.f32 "
        "{%0,%1,%2,%3}, {%4,%5,%6,%7}, {%8,%9}, {%0,%1,%2,%3};"
        : "+f"(c[0]), "+f"(c[1]), "+f"(c[2]), "+f"(c[3])
        : "r"(a[0]), "r"(a[1]), "r"(a[2]), "r"(a[3]), "r"(b0), "r"(b1));
}

__device__ __forceinline__ void ldmx4t(uint32_t& r0, uint32_t& r1, uint32_t& r2, uint32_t& r3,
                                       uint32_t addr) {
    asm volatile("ldmatrix.sync.aligned.m8n8.x4.trans.shared.b16 {%0,%1,%2,%3}, [%4];"
        : "=r"(r0), "=r"(r1), "=r"(r2), "=r"(r3) : "r"(addr));
}

__device__ __forceinline__ uint32_t pack_bf2(float a, float b) {
    __nv_bfloat162 t = __floats2bfloat162_rn(a, b);
    return *(uint32_t*)&t;
}

static constexpr int KLD = 72;

__global__ void __launch_bounds__(128) attn_fa2(
        const __nv_bfloat16* __restrict__ Qg, const __nv_bfloat16* __restrict__ Kg,
        const __nv_bfloat16* __restrict__ Vg, float* __restrict__ Hout) {
    __shared__ __align__(16) __nv_bfloat16 Ks[64][KLD];
    __shared__ __align__(16) __nv_bfloat16 Vs[64][KLD];

    int bh = blockIdx.y;
    int q0 = blockIdx.x * 64;
    const __nv_bfloat16* Qb = Qg + (size_t)bh * CS * CHD;
    const __nv_bfloat16* Kb = Kg + (size_t)bh * CS * CHD;
    const __nv_bfloat16* Vb = Vg + (size_t)bh * CS * CHD;

    int tid = threadIdx.x;
    int w = tid >> 5, lane = tid & 31;
    int gid = lane >> 2, tig = lane & 3;

    int qr0 = q0 + w * 16 + gid;    // global q row (first of pair)
    int qr1 = qr0 + 8;

    // Q fragments (A operand, 4 k-steps of 16)
    uint32_t qf[4][4];
    #pragma unroll
    for (int k = 0; k < 4; k++) {
        const __nv_bfloat16* p0 = Qb + (size_t)qr0 * CHD + k * 16 + 2 * tig;
        const __nv_bfloat16* p1 = Qb + (size_t)qr1 * CHD + k * 16 + 2 * tig;
        qf[k][0] = *(const uint32_t*)p0;
        qf[k][1] = *(const uint32_t*)p1;
        qf[k][2] = *(const uint32_t*)(p0 + 8);
        qf[k][3] = *(const uint32_t*)(p1 + 8);
    }

    float o[8][4];
    #pragma unroll
    for (int nt = 0; nt < 8; nt++)
        #pragma unroll
        for (int j = 0; j < 4; j++) o[nt][j] = 0.f;
    float m0 = -INFINITY, m1 = -INFINITY, l0 = 0.f, l1 = 0.f;

    int nkt = blockIdx.x + 1;
    for (int kt = 0; kt < nkt; kt++) {
        int k0 = kt * 64;
        __syncthreads();
        for (int i = tid; i < 512; i += 128) {
            int row = i >> 3, c8 = (i & 7) * 8;
            *(uint4*)&Ks[row][c8] = *(const uint4*)(Kb + (size_t)(k0 + row) * CHD + c8);
            *(uint4*)&Vs[row][c8] = *(const uint4*)(Vb + (size_t)(k0 + row) * CHD + c8);
        }
        __syncthreads();

        // S = Q.K^T : s[nt] covers key cols nt*8..nt*8+7
        float s[8][4];
        #pragma unroll
        for (int nt = 0; nt < 8; nt++)
            #pragma unroll
            for (int j = 0; j < 4; j++) s[nt][j] = 0.f;
        #pragma unroll
        for (int k = 0; k < 4; k++) {
            #pragma unroll
            for (int nt = 0; nt < 8; nt++) {
                uint32_t b0 = *(const uint32_t*)&Ks[nt * 8 + gid][k * 16 + 2 * tig];
                uint32_t b1 = *(const uint32_t*)&Ks[nt * 8 + gid][k * 16 + 8 + 2 * tig];
                mma_bf16(s[nt], qf[k], b0, b1);
            }
        }

        // scale + causal mask + row max (registers + 2 shuffles)
        bool diag = (kt == blockIdx.x);
        float rmax0 = -INFINITY, rmax1 = -INFINITY;
        #pragma unroll
        for (int nt = 0; nt < 8; nt++) {
            int cg = k0 + nt * 8 + 2 * tig;
            #pragma unroll
            for (int j = 0; j < 2; j++) {
                float v0 = s[nt][j] * 0.125f;
                float v1 = s[nt][2 + j] * 0.125f;
                if (diag && cg + j > qr0) v0 = -INFINITY;
                if (diag && cg + j > qr1) v1 = -INFINITY;
                s[nt][j] = v0; s[nt][2 + j] = v1;
                rmax0 = fmaxf(rmax0, v0); rmax1 = fmaxf(rmax1, v1);
            }
        }
        rmax0 = fmaxf(rmax0, __shfl_xor_sync(0xffffffffu, rmax0, 1));
        rmax0 = fmaxf(rmax0, __shfl_xor_sync(0xffffffffu, rmax0, 2));
        rmax1 = fmaxf(rmax1, __shfl_xor_sync(0xffffffffu, rmax1, 1));
        rmax1 = fmaxf(rmax1, __shfl_xor_sync(0xffffffffu, rmax1, 2));

        float mn0 = fmaxf(m0, rmax0), mn1 = fmaxf(m1, rmax1);
        float sum0 = 0.f, sum1 = 0.f;
        #pragma unroll
        for (int nt = 0; nt < 8; nt++) {
            s[nt][0] = __expf(s[nt][0] - mn0);
            s[nt][1] = __expf(s[nt][1] - mn0);
            s[nt][2] = __expf(s[nt][2] - mn1);
            s[nt][3] = __expf(s[nt][3] - mn1);
            sum0 += s[nt][0] + s[nt][1];
            sum1 += s[nt][2] + s[nt][3];
        }
        sum0 += __shfl_xor_sync(0xffffffffu, sum0, 1);
        sum0 += __shfl_xor_sync(0xffffffffu, sum0, 2);
        sum1 += __shfl_xor_sync(0xffffffffu, sum1, 1);
        sum1 += __shfl_xor_sync(0xffffffffu, sum1, 2);

        float rs0 = __expf(m0 - mn0), rs1 = __expf(m1 - mn1);
        m0 = mn0; m1 = mn1;
        l0 = l0 * rs0 + sum0;
        l1 = l1 * rs1 + sum1;
        #pragma unroll
        for (int nt = 0; nt < 8; nt++) {
            o[nt][0] *= rs0; o[nt][1] *= rs0;
            o[nt][2] *= rs1; o[nt][3] *= rs1;
        }

        // O += P.V  (P repacked from s registers; V via ldmatrix.trans)
        #pragma unroll
        for (int kb = 0; kb < 4; kb++) {
            uint32_t pf[4];
            pf[0] = pack_bf2(s[2 * kb][0], s[2 * kb][1]);
            pf[1] = pack_bf2(s[2 * kb][2], s[2 * kb][3]);
            pf[2] = pack_bf2(s[2 * kb + 1][0], s[2 * kb + 1][1]);
            pf[3] = pack_bf2(s[2 * kb + 1][2], s[2 * kb + 1][3]);
            #pragma unroll
            for (int nb = 0; nb < 4; nb++) {
                uint32_t v0, v1, v2, v3;
                uint32_t addr = (uint32_t)__cvta_generic_to_shared(
                    &Vs[kb * 16 + (lane & 15)][nb * 16 + ((lane >> 4) << 3)]);
                ldmx4t(v0, v1, v2, v3, addr);
                mma_bf16(o[2 * nb], pf, v0, v1);
                mma_bf16(o[2 * nb + 1], pf, v2, v3);
            }
        }
    }

    // write out [B,S,NH,HD]
    float inv0 = 1.0f / l0, inv1 = 1.0f / l1;
    int b = bh / CNH, nh = bh % CNH;
    #pragma unroll
    for (int nt = 0; nt < 8; nt++) {
        int col = nt * 8 + 2 * tig;
        float2 w0v = {o[nt][0] * inv0, o[nt][1] * inv0};
        float2 w1v = {o[nt][2] * inv1, o[nt][3] * inv1};
        *(float2*)(Hout + (((size_t)b * CS + qr0) * CNH + nh) * CHD + col) = w0v;
        *(float2*)(Hout + (((size_t)b * CS + qr1) * CNH + nh) * CHD + col) = w1v;
    }
}

// ---------------- MoE elementwise: hh = relu(g)^2 * u, then act_quant ----------------
__global__ void hh_quant(const float* __restrict__ g, const float* __restrict__ u,
                         int8_t* __restrict__ hq, float* __restrict__ hs) {
    __shared__ float red[256];
    __shared__ float hb[CD];
    int slot = blockIdx.x, tid = threadIdx.x;
    float amax = 0.f;
    #pragma unroll
    for (int i = 0; i < 4; i++) {
        int k = tid + i * 256;
        float gv = g[(size_t)slot * CD + k];
        float uv = u[(size_t)slot * CD + k];
        float rl = fmaxf(gv, 0.f);
        float h = rl * rl * uv;
        hb[k] = h;
        amax = fmaxf(amax, fabsf(h));
    }
    amax = blk_reduce_max(amax, red);
    float m = fmaxf(amax, 1e-5f);
    float s = 127.f / m;
    #pragma unroll
    for (int i = 0; i < 4; i++) {
        int k = tid + i * 256;
        float qv = fminf(fmaxf(rintf(hb[k] * s), -128.f), 127.f);
        hq[(size_t)slot * CD + k] = (int8_t)(int)qv;
    }
    if (tid == 0) hs[slot] = m * (1.0f / 127.f);
}

// ---------------- launch ----------------
extern "C" void kernel_launch(void* const* d_in, const int* in_sizes, int n_in,
                              void* d_out, int out_size) {
    const float* x        = (const float*)d_in[0];
    const float* q_w      = (const float*)d_in[1];
    const float* k_w      = (const float*)d_in[2];
    const float* v_w      = (const float*)d_in[3];
    const float* o_w      = (const float*)d_in[4];
    const float* ln1_w    = (const float*)d_in[5];
    const float* ln2_w    = (const float*)d_in[6];
    const float* router_w = (const float*)d_in[7];
    const float* gate_w   = (const float*)d_in[8];
    const float* up_w     = (const float*)d_in[9];
    const float* down_w   = (const float*)d_in[10];

    unsigned char* base = nullptr;
    cudaGetSymbolAddress((void**)&base, g_scratch);

    int8_t* wq_attn = (int8_t*)(base + OFF_WQ_ATTN);
    int8_t* wq_gate = (int8_t*)(base + OFF_WQ_GATE);
    int8_t* wq_up   = (int8_t*)(base + OFF_WQ_UP);
    int8_t* wq_down = (int8_t*)(base + OFF_WQ_DOWN);
    float*  wsc     = (float*)(base + OFF_WSCALE);
    float*  part    = (float*)(base + OFF_PART);
    int8_t* xq1     = (int8_t*)(base + OFF_XQ1);
    float*  a1s     = (float*)(base + OFF_A1S);
    __nv_bfloat16* qkvb = (__nv_bfloat16*)(base + OFF_QKV);
    float*  hb      = (float*)(base + OFF_HB);
    int8_t* hqa     = (int8_t*)(base + OFF_HQA);
    float*  hsa     = (float*)(base + OFF_HSA);
    float*  x2      = (float*)(base + OFF_X2);
    int8_t* xq2     = (int8_t*)(base + OFF_XQ2);
    float*  a2s     = (float*)(base + OFF_A2S);
    int*    idx     = (int*)(base + OFF_IDX);
    int*    cnt     = (int*)(base + OFF_CNT);
    int*    seg     = (int*)(base + OFF_SEG);
    int*    cur     = (int*)(base + OFF_CUR);
    int*    perm    = (int*)(base + OFF_PERM);
    float*  gb      = (float*)(base + OFF_GB);
    float*  ub      = (float*)(base + OFF_UB);
    int8_t* hqm     = (int8_t*)(base + OFF_HQM);
    float*  hsm     = (float*)(base + OFF_HSM);
    float*  out     = (float*)d_out;

    const int LEN4 = (CH * CH) / 4;

    // ---- attention path (gemm_mma<0> lands in ncu capture slot #3) ----
    rmsnorm_quant<<<CT, 256>>>(x, ln1_w, xq1, a1s);
    absmean4<<<dim3(256, 4), 256>>>(q_w, k_w, v_w, o_w, part, LEN4);
    quantizeF4<<<dim3(256, 4), 256>>>(q_w, k_w, v_w, o_w, wq_attn, part, wsc, LEN4);
    gemm_mma<0><<<dim3(16, 32, 3), 256>>>(xq1, wq_attn, nullptr, qkvb, a1s, wsc, nullptr, nullptr, nullptr);

    attn_fa2<<<dim3(32, CB * CNH), 128>>>(
        qkvb, qkvb + (size_t)CT * CH, qkvb + 2 * (size_t)CT * CH, hb);

    // ---- MoE weight quant ----
    absmean_partial<<<dim3(256, 8), 256>>>(gate_w, part + 4 * 256, LEN4);
    absmean_partial<<<dim3(256, 8), 256>>>(up_w,   part + 12 * 256, LEN4);
    absmean_partial<<<dim3(256, 8), 256>>>(down_w, part + 20 * 256, LEN4);
    finalize_wscale<<<1, 32>>>(part, wsc, 4, 24);
    quantize_w<<<dim3(256, 8), 256>>>(gate_w, wq_gate, wsc, 4, LEN4);
    quantize_w<<<dim3(256, 8), 256>>>(up_w,   wq_up,   wsc, 12, LEN4);
    quantize_w<<<dim3(256, 8), 256>>>(down_w, wq_down, wsc, 20, LEN4);
    zero_ints<<<1, 32>>>(cnt, cur);

    // ---- o-proj + residual ----
    act_quant_rows<<<CT, 256>>>(hb, hqa, hsa);
    gemm_mma<1><<<dim3(16, 32, 1), 256>>>(hqa, wq_attn + 3 * (CH * CH), x2, nullptr, hsa, wsc + 3, x, nullptr, nullptr);

    // ---- MoE ----
    rmsnorm2_router<<<CT, 256>>>(x2, ln2_w, router_w, xq2, a2s, idx, cnt);
    build_offsets<<<1, 1>>>(cnt, seg);
    scatter_tokens<<<16, 256>>>(idx, seg, cur, perm);

    gemm_mma<2><<<dim3(16, 32, 16), 256>>>(xq2, wq_gate, gb, nullptr, a2s, wsc + 4, nullptr, perm, seg);
    hh_quant<<<CT, 256>>>(gb, ub, hqm, hsm);
    gemm_mma<3><<<dim3(16, 32, 8), 256>>>(hqm, wq_down, out, nullptr, hsm, wsc + 20, x2, perm, seg);
}

// round 10
// speedup vs baseline: 2.4788x; 1.0053x over previous
#include <cuda_runtime.h>
#include <cuda_bf16.h>
#include <math.h>
#include <stdint.h>

#define CB 2
#define CS 2048
#define CH 1024
#define CNH 16
#define CHD 64
#define CE 8
#define CD 1024
#define CT (CB*CS)

#define MB (1024ull*1024ull)

// ---------------- scratch layout ----------------
static constexpr size_t OFF_WQ_ATTN = 0;               // 4 MB  int8: q,k,v,o
static constexpr size_t OFF_WQ_GATE = 4*MB;            // 8 MB (gate) — contiguous with up
static constexpr size_t OFF_WQ_UP   = 12*MB;           // 8 MB
static constexpr size_t OFF_WQ_DOWN = 20*MB;           // 8 MB
static constexpr size_t OFF_WSCALE  = 28*MB;           // 28 floats
static constexpr size_t OFF_PART    = 28*MB + 4096;    // 28*256 floats
static constexpr size_t OFF_XQ1     = 29*MB;           // 4 MB int8
static constexpr size_t OFF_A1S     = 33*MB;           // T floats
static constexpr size_t OFF_QKV     = 34*MB;           // 24 MB bf16: q,k,v [B,NH,S,HD]
static constexpr size_t OFF_HB      = 82*MB;           // 16 MB fp32 attention out [T,H]
static constexpr size_t OFF_HQA     = 98*MB;           // 4 MB int8
static constexpr size_t OFF_HSA     = 102*MB;          // T floats
static constexpr size_t OFF_X2      = 103*MB;          // 16 MB fp32
static constexpr size_t OFF_XQ2     = 119*MB;          // 4 MB int8
static constexpr size_t OFF_A2S     = 123*MB;          // T floats
static constexpr size_t OFF_IDX     = 123*MB + 64*1024;
static constexpr size_t OFF_CNT     = 123*MB + 128*1024;
static constexpr size_t OFF_SEG     = 123*MB + 129*1024;
static constexpr size_t OFF_CUR     = 123*MB + 130*1024;
static constexpr size_t OFF_PERM    = 124*MB;          // T ints
static constexpr size_t OFF_GB      = 125*MB;          // 16 MB fp32 (gate) — contiguous with ub
static constexpr size_t OFF_UB      = 141*MB;          // 16 MB fp32
static constexpr size_t OFF_HQM     = 157*MB;          // 4 MB int8
static constexpr size_t OFF_HSM     = 161*MB;          // T floats
static constexpr size_t SCRATCH_BYTES = 162*MB;

__device__ __align__(256) unsigned char g_scratch[SCRATCH_BYTES];

// ---------------- reductions ----------------
__device__ __forceinline__ float blk_reduce_sum(float v, float* red) {
    int tid = threadIdx.x;
    red[tid] = v; __syncthreads();
    #pragma unroll
    for (int s = 128; s > 0; s >>= 1) {
        if (tid < s) red[tid] += red[tid + s];
        __syncthreads();
    }
    float r = red[0]; __syncthreads();
    return r;
}

__device__ __forceinline__ float blk_reduce_max(float v, float* red) {
    int tid = threadIdx.x;
    red[tid] = v; __syncthreads();
    #pragma unroll
    for (int s = 128; s > 0; s >>= 1) {
        if (tid < s) red[tid] = fmaxf(red[tid], red[tid + s]);
        __syncthreads();
    }
    float r = red[0]; __syncthreads();
    return r;
}

// ---------------- weight quantization (4x float4 ILP; len4 = 262144 = 256*1024) ----------------
__device__ __forceinline__ float abs4(float4 v) {
    return fabsf(v.x) + fabsf(v.y) + fabsf(v.z) + fabsf(v.w);
}

__global__ void absmean_partial(const float* __restrict__ w, float* __restrict__ part, int len4) {
    __shared__ float red[256];
    const float4* p = (const float4*)w + (size_t)blockIdx.y * len4;
    int i = blockIdx.x * 1024 + threadIdx.x;
    float4 v0 = p[i], v1 = p[i + 256], v2 = p[i + 512], v3 = p[i + 768];
    float s = (abs4(v0) + abs4(v1)) + (abs4(v2) + abs4(v3));
    s = blk_reduce_sum(s, red);
    if (threadIdx.x == 0) part[(size_t)blockIdx.y * gridDim.x + blockIdx.x] = s;
}

__global__ void absmean4(const float* __restrict__ w0, const float* __restrict__ w1,
                         const float* __restrict__ w2, const float* __restrict__ w3,
                         float* __restrict__ part, int len4) {
    __shared__ float red[256];
    int sl = blockIdx.y;
    const float* p = sl == 0 ? w0 : sl == 1 ? w1 : sl == 2 ? w2 : w3;
    const float4* p4 = (const float4*)p;
    int i = blockIdx.x * 1024 + threadIdx.x;
    float4 v0 = p4[i], v1 = p4[i + 256], v2 = p4[i + 512], v3 = p4[i + 768];
    float s = (abs4(v0) + abs4(v1)) + (abs4(v2) + abs4(v3));
    s = blk_reduce_sum(s, red);
    if (threadIdx.x == 0) part[(size_t)sl * gridDim.x + blockIdx.x] = s;
}

__global__ void finalize_wscale(const float* __restrict__ part, float* __restrict__ wsc,
                                int i0, int n) {
    int i = i0 + threadIdx.x;
    if (threadIdx.x >= n) return;
    float s = 0.f;
    for (int j = 0; j < 256; j++) s += part[i * 256 + j];
    wsc[i] = fmaxf(s * (1.0f / (1024.f * 1024.f)), 1e-5f);
}

__device__ __forceinline__ char quant_tern(float v, float s) {
    float q = rintf(v * s);
    q = fminf(fmaxf(q, -1.f), 1.f);
    return (char)(int)q;
}

__device__ __forceinline__ char4 qt4(float4 v, float s) {
    char4 o;
    o.x = quant_tern(v.x, s); o.y = quant_tern(v.y, s);
    o.z = quant_tern(v.z, s); o.w = quant_tern(v.w, s);
    return o;
}

__global__ void quantize_w(const float* __restrict__ w, int8_t* __restrict__ wq,
                           const float* __restrict__ wsc, int widx0, int len4) {
    int slice = blockIdx.y;
    float s = 1.0f / wsc[widx0 + slice];
    const float4* p = (const float4*)w + (size_t)slice * len4;
    char4* q = (char4*)wq + (size_t)slice * len4;
    int i = blockIdx.x * 1024 + threadIdx.x;
    float4 v0 = p[i], v1 = p[i + 256], v2 = p[i + 512], v3 = p[i + 768];
    q[i] = qt4(v0, s); q[i + 256] = qt4(v1, s);
    q[i + 512] = qt4(v2, s); q[i + 768] = qt4(v3, s);
}

// fused finalize + quantize for the 4 attention matrices
__global__ void quantizeF4(const float* __restrict__ w0, const float* __restrict__ w1,
                           const float* __restrict__ w2, const float* __restrict__ w3,
                           int8_t* __restrict__ wq, const float* __restrict__ part,
                           float* __restrict__ wsc, int len4) {
    __shared__ float red[256];
    int sl = blockIdx.y;
    int tid = threadIdx.x;
    float total = blk_reduce_sum(part[sl * 256 + tid], red);
    float mean = fmaxf(total * (1.0f / (1024.f * 1024.f)), 1e-5f);
    if (blockIdx.x == 0 && tid == 0) wsc[sl] = mean;
    float s = 1.0f / mean;
    const float* p = sl == 0 ? w0 : sl == 1 ? w1 : sl == 2 ? w2 : w3;
    const float4* p4 = (const float4*)p;
    char4* q = (char4*)wq + (size_t)sl * len4;
    int i = blockIdx.x * 1024 + tid;
    float4 v0 = p4[i], v1 = p4[i + 256], v2 = p4[i + 512], v3 = p4[i + 768];
    q[i] = qt4(v0, s); q[i + 256] = qt4(v1, s);
    q[i + 512] = qt4(v2, s); q[i + 768] = qt4(v3, s);
}

// ---------------- activation rmsnorm + quant ----------------
__global__ void rmsnorm_quant(const float* __restrict__ x, const float* __restrict__ lnw,
                              int8_t* __restrict__ xq, float* __restrict__ ainv) {
    __shared__ float red[256];
    __shared__ float xs[CH];
    int t = blockIdx.x, tid = threadIdx.x;
    const float* xr = x + (size_t)t * CH;
    float v[4]; float ss = 0.f;
    #pragma unroll
    for (int i = 0; i < 4; i++) { v[i] = xr[tid + i * 256]; ss += v[i] * v[i]; }
    ss = blk_reduce_sum(ss, red);
    float r = rsqrtf(ss * (1.0f / CH) + 1e-5f);
    float amax = 0.f;
    #pragma unroll
    for (int i = 0; i < 4; i++) {
        float xn = v[i] * r * lnw[tid + i * 256];
        xs[tid + i * 256] = xn;
        amax = fmaxf(amax, fabsf(xn));
    }
    amax = blk_reduce_max(amax, red);
    float m = fmaxf(amax, 1e-5f);
    float s = 127.f / m;
    #pragma unroll
    for (int i = 0; i < 4; i++) {
        float qv = fminf(fmaxf(rintf(xs[tid + i * 256] * s), -128.f), 127.f);
        xq[(size_t)t * CH + tid + i * 256] = (int8_t)(int)qv;
    }
    if (tid == 0) ainv[t] = m * (1.0f / 127.f);
}

__global__ void act_quant_rows(const float* __restrict__ x, int8_t* __restrict__ xq,
                               float* __restrict__ ainv) {
    __shared__ float red[256];
    int t = blockIdx.x, tid = threadIdx.x;
    const float* xr = x + (size_t)t * CH;
    float v[4]; float amax = 0.f;
    #pragma unroll
    for (int i = 0; i < 4; i++) { v[i] = xr[tid + i * 256]; amax = fmaxf(amax, fabsf(v[i])); }
    amax = blk_reduce_max(amax, red);
    float m = fmaxf(amax, 1e-5f);
    float s = 127.f / m;
    #pragma unroll
    for (int i = 0; i < 4; i++) {
        float qv = fminf(fmaxf(rintf(v[i] * s), -128.f), 127.f);
        xq[(size_t)t * CH + tid + i * 256] = (int8_t)(int)qv;
    }
    if (tid == 0) ainv[t] = m * (1.0f / 127.f);
}

__global__ void rmsnorm2_router(const float* __restrict__ x, const float* __restrict__ lnw,
                                const float* __restrict__ rw, int8_t* __restrict__ xq,
                                float* __restrict__ ainv, int* __restrict__ idx,
                                int* __restrict__ counts) {
    __shared__ float red[256];
    __shared__ float xs[CH];
    __shared__ float logits[CE];
    int t = blockIdx.x, tid = threadIdx.x;
    const float* xr = x + (size_t)t * CH;
    float v[4]; float ss = 0.f;
    #pragma unroll
    for (int i = 0; i < 4; i++) { v[i] = xr[tid + i * 256]; ss += v[i] * v[i]; }
    ss = blk_reduce_sum(ss, red);
    float r = rsqrtf(ss * (1.0f / CH) + 1e-5f);
    float amax = 0.f;
    #pragma unroll
    for (int i = 0; i < 4; i++) {
        float xn = v[i] * r * lnw[tid + i * 256];
        xs[tid + i * 256] = xn;
        amax = fmaxf(amax, fabsf(xn));
    }
    amax = blk_reduce_max(amax, red);
    float m = fmaxf(amax, 1e-5f);
    float s = 127.f / m;
    #pragma unroll
    for (int i = 0; i < 4; i++) {
        float qv = fminf(fmaxf(rintf(xs[tid + i * 256] * s), -128.f), 127.f);
        xq[(size_t)t * CH + tid + i * 256] = (int8_t)(int)qv;
    }
    if (tid == 0) ainv[t] = m * (1.0f / 127.f);
    __syncthreads();

    int w = tid >> 5, lane = tid & 31;
    float acc = 0.f;
    for (int h = lane; h < CH; h += 32) acc += xs[h] * rw[w * CH + h];
    #pragma unroll
    for (int o = 16; o > 0; o >>= 1) acc += __shfl_down_sync(0xffffffffu, acc, o);
    if (lane == 0) logits[w] = acc;
    __syncthreads();
    if (tid == 0) {
        float best = logits[0]; int bi = 0;
        #pragma unroll
        for (int e = 1; e < CE; e++) if (logits[e] > best) { best = logits[e]; bi = e; }
        idx[t] = bi;
        atomicAdd(&counts[bi], 1);
    }
}

__global__ void zero_ints(int* __restrict__ counts, int* __restrict__ cursor) {
    if (threadIdx.x < CE) { counts[threadIdx.x] = 0; cursor[threadIdx.x] = 0; }
}

__global__ void build_offsets(const int* __restrict__ counts, int* __restrict__ seg) {
    if (threadIdx.x == 0) {
        int a = 0;
        for (int e = 0; e < CE; e++) { seg[e] = a; a += counts[e]; }
        seg[CE] = a;
    }
}

__global__ void scatter_tokens(const int* __restrict__ idx, const int* __restrict__ seg,
                               int* __restrict__ cursor, int* __restrict__ perm) {
    int t = blockIdx.x * 256 + threadIdx.x;
    if (t >= CT) return;
    int e = idx[t];
    int p = atomicAdd(&cursor[e], 1);
    perm[seg[e] + p] = t;
}

// ---------------- int8 x ternary GEMM via mma.sync m16n8k32, double-buffered smem ----------------
__device__ __forceinline__ void mma_s8(int* c, const int* a, const int* b) {
    asm volatile(
        "mma.sync.aligned.m16n8k32.row.col.s32.s8.s8.s32 "
        "{%0,%1,%2,%3}, {%4,%5,%6,%7}, {%8,%9}, {%0,%1,%2,%3};"
        : "+r"(c[0]), "+r"(c[1]), "+r"(c[2]), "+r"(c[3])
        : "r"(a[0]), "r"(a[1]), "r"(a[2]), "r"(a[3]), "r"(b[0]), "r"(b[1]));
}

template<int MODE>
__global__ void __launch_bounds__(256) gemm_mma(
        const int8_t* __restrict__ A, const int8_t* __restrict__ Bw,
        float* __restrict__ Out, __nv_bfloat16* __restrict__ OutB,
        const float* __restrict__ ascale,
        const float* __restrict__ wscale,
        const float* __restrict__ resid,
        const int* __restrict__ perm,
        const int* __restrict__ seg) {
    int n0 = blockIdx.x * 64;
    int m0 = blockIdx.y * 128;
    int z = blockIdx.z;
    int e = (MODE == 2) ? (z & 7) : z;

    int off = 0, cnt = CT;
    if (MODE >= 2) {
        off = seg[e];
        cnt = seg[e + 1] - off;
        if (m0 >= cnt) return;
    }

    const int8_t* Bz = Bw;
    if (MODE == 0) Bz = Bw + (size_t)z * (CH * CH);
    if (MODE >= 2) Bz = Bw + (size_t)z * ((size_t)CD * CH);
    const int8_t* brow0 = Bz + (size_t)n0 * 1024;

    __shared__ __align__(16) int8_t As[2][128][80];
    __shared__ __align__(16) int8_t Bs[2][64][80];
    __shared__ const int8_t* aptr[128];
    __shared__ float rowsc[128];
    __shared__ int dstrow[128];

    int tid = threadIdx.x;
    if (tid < 128) {
        int r = m0 + tid;
        if (MODE <= 1) {
            aptr[tid] = A + (size_t)r * 1024;
            rowsc[tid] = ascale[r];
        } else if (MODE == 2) {
            int rr = r < cnt - 1 ? r : cnt - 1;
            int tok = perm[off + rr];
            aptr[tid] = A + (size_t)tok * 1024;
            rowsc[tid] = ascale[tok];
            dstrow[tid] = off + r;
        } else {
            int rr = r < cnt - 1 ? r : cnt - 1;
            aptr[tid] = A + (size_t)(off + rr) * 1024;
            rowsc[tid] = ascale[off + rr];
            dstrow[tid] = perm[off + rr];
        }
    }
    __syncthreads();

    int ar = tid >> 1, ao = (tid & 1) * 32;
    int brr = tid >> 2, bo = (tid & 3) * 16;
    const int8_t* pA = aptr[ar];
    const int8_t* pB = brow0 + (size_t)brr * 1024;

    int w = tid >> 5, lane = tid & 31;
    int warpM = w & 3, warpN = w >> 2;
    int gid = lane >> 2, tig = lane & 3;

    int c[2][4][4];
    #pragma unroll
    for (int i = 0; i < 2; i++)
        #pragma unroll
        for (int j = 0; j < 4; j++)
            #pragma unroll
            for (int k = 0; k < 4; k++) c[i][j][k] = 0;

    int rowA0 = warpM * 32 + gid;
    int rowB0 = warpN * 32 + gid;
    int kcol = tig * 4;

    // prologue: stage 0 into buffer 0
    {
        int4 pa0 = *(const int4*)(pA + ao);
        int4 pa1 = *(const int4*)(pA + ao + 16);
        int4 pb  = *(const int4*)(pB + bo);
        *(int4*)&As[0][ar][ao]      = pa0;
        *(int4*)&As[0][ar][ao + 16] = pa1;
        *(int4*)&Bs[0][brr][bo]     = pb;
    }
    __syncthreads();

    #pragma unroll 1
    for (int kt = 0; kt < 16; kt++) {
        int cur = kt & 1, nxt = cur ^ 1;
        int4 pa0, pa1, pb;
        if (kt < 15) {
            int base = (kt + 1) * 64;
            pa0 = *(const int4*)(pA + base + ao);
            pa1 = *(const int4*)(pA + base + ao + 16);
            pb  = *(const int4*)(pB + base + bo);
        }
        #pragma unroll
        for (int ks = 0; ks < 2; ks++) {
            int kb = ks * 32 + kcol;
            int a[2][4];
            #pragma unroll
            for (int wm = 0; wm < 2; wm++) {
                int rA = rowA0 + wm * 16;
                a[wm][0] = *(const int*)&As[cur][rA][kb];
                a[wm][1] = *(const int*)&As[cur][rA + 8][kb];
                a[wm][2] = *(const int*)&As[cur][rA][kb + 16];
                a[wm][3] = *(const int*)&As[cur][rA + 8][kb + 16];
            }
            int b[4][2];
            #pragma unroll
            for (int nt = 0; nt < 4; nt++) {
                int rB = rowB0 + nt * 8;
                b[nt][0] = *(const int*)&Bs[cur][rB][kb];
                b[nt][1] = *(const int*)&Bs[cur][rB][kb + 16];
            }
            #pragma unroll
            for (int wm = 0; wm < 2; wm++)
                #pragma unroll
                for (int nt = 0; nt < 4; nt++)
                    mma_s8(c[wm][nt], a[wm], b[nt]);
        }
        if (kt < 15) {
            *(int4*)&As[nxt][ar][ao]      = pa0;
            *(int4*)&As[nxt][ar][ao + 16] = pa1;
            *(int4*)&Bs[nxt][brr][bo]     = pb;
            __syncthreads();
        }
    }

    float wS = wscale[(MODE == 0 || MODE >= 2) ? z : 0];

    #pragma unroll
    for (int wm = 0; wm < 2; wm++) {
        int r0 = warpM * 32 + wm * 16 + gid;
        int r1 = r0 + 8;
        float av0 = rowsc[r0] * wS;
        float av1 = rowsc[r1] * wS;
        #pragma unroll
        for (int nt = 0; nt < 4; nt++) {
            int colL = warpN * 32 + nt * 8 + tig * 2;
            int* cc = c[wm][nt];
            if (MODE == 0) {
                int nh = n0 >> 6;
                int gr0 = m0 + r0, gr1 = m0 + r1;
                int b0 = gr0 / CS, sr0 = gr0 % CS;
                int b1 = gr1 / CS, sr1 = gr1 % CS;
                __nv_bfloat16* base = OutB + (size_t)z * ((size_t)CT * CH);
                __nv_bfloat162 o0 = {__float2bfloat16(cc[0] * av0), __float2bfloat16(cc[1] * av0)};
                __nv_bfloat162 o1 = {__float2bfloat16(cc[2] * av1), __float2bfloat16(cc[3] * av1)};
                *(__nv_bfloat162*)(base + (((size_t)b0 * CNH + nh) * CS + sr0) * CHD + colL) = o0;
                *(__nv_bfloat162*)(base + (((size_t)b1 * CNH + nh) * CS + sr1) * CHD + colL) = o1;
            } else if (MODE == 1) {
                size_t rb0 = (size_t)(m0 + r0) * CH + n0 + colL;
                size_t rb1 = (size_t)(m0 + r1) * CH + n0 + colL;
                float2 rv0 = *(const float2*)(resid + rb0);
                float2 rv1 = *(const float2*)(resid + rb1);
                float2 o0 = {rv0.x + cc[0] * av0, rv0.y + cc[1] * av0};
                float2 o1 = {rv1.x + cc[2] * av1, rv1.y + cc[3] * av1};
                *(float2*)(Out + rb0) = o0;
                *(float2*)(Out + rb1) = o1;
            } else if (MODE == 2) {
                size_t half = (size_t)(z >> 3) * ((size_t)CT * CD);
                if (m0 + r0 < cnt) {
                    size_t rb = half + (size_t)dstrow[r0] * CD + n0 + colL;
                    float2 o = {cc[0] * av0, cc[1] * av0};
                    *(float2*)(Out + rb) = o;
                }
                if (m0 + r1 < cnt) {
                    size_t rb = half + (size_t)dstrow[r1] * CD + n0 + colL;
                    float2 o = {cc[2] * av1, cc[3] * av1};
                    *(float2*)(Out + rb) = o;
                }
            } else {
                if (m0 + r0 < cnt) {
                    size_t rb = (size_t)dstrow[r0] * CH + n0 + colL;
                    float2 rv = *(const float2*)(resid + rb);
                    float2 o = {rv.x + cc[0] * av0, rv.y + cc[1] * av0};
                    *(float2*)(Out + rb) = o;
                }
                if (m0 + r1 < cnt) {
                    size_t rb = (size_t)dstrow[r1] * CH + n0 + colL;
                    float2 rv = *(const float2*)(resid + rb);
                    float2 o = {rv.x + cc[2] * av1, rv.y + cc[3] * av1};
                    *(float2*)(Out + rb) = o;
                }
            }
        }
    }
}

// ---------------- attention: FA2-style, register-resident (round-8 proven) ----------------
__device__ __forceinline__ void mma_bf16(float* c, const uint32_t* a, uint32_t b0, uint32_t b1) {
    asm volatile(
        "mma.sync.aligned.m16n8k16.row.col.f32.bf16.bf16.f32 "
        "{%0,%1,%2,%3}, {%4,%5,%6,%7}, {%8,%9}, {%0,%1,%2,%3};"
        : "+f"(c[0]), "+f"(c[1]), "+f"(c[2]), "+f"(c[3])
        : "r"(a[0]), "r"(a[1]), "r"(a[2]), "r"(a[3]), "r"(b0), "r"(b1));
}

__device__ __forceinline__ void ldmx4t(uint32_t& r0, uint32_t& r1, uint32_t& r2, uint32_t& r3,
                                       uint32_t addr) {
    asm volatile("ldmatrix.sync.aligned.m8n8.x4.trans.shared.b16 {%0,%1,%2,%3}, [%4];"
        : "=r"(r0), "=r"(r1), "=r"(r2), "=r"(r3) : "r"(addr));
}

__device__ __forceinline__ uint32_t pack_bf2(float a, float b) {
    __nv_bfloat162 t = __floats2bfloat162_rn(a, b);
    return *(uint32_t*)&t;
}

static constexpr int KLD = 72;

__global__ void __launch_bounds__(128) attn_fa2(
        const __nv_bfloat16* __restrict__ Qg, const __nv_bfloat16* __restrict__ Kg,
        const __nv_bfloat16* __restrict__ Vg, float* __restrict__ Hout) {
    __shared__ __align__(16) __nv_bfloat16 Ks[64][KLD];
    __shared__ __align__(16) __nv_bfloat16 Vs[64][KLD];

    int bh = blockIdx.y;
    int q0 = blockIdx.x * 64;
    const __nv_bfloat16* Qb = Qg + (size_t)bh * CS * CHD;
    const __nv_bfloat16* Kb = Kg + (size_t)bh * CS * CHD;
    const __nv_bfloat16* Vb = Vg + (size_t)bh * CS * CHD;

    int tid = threadIdx.x;
    int w = tid >> 5, lane = tid & 31;
    int gid = lane >> 2, tig = lane & 3;

    int qr0 = q0 + w * 16 + gid;
    int qr1 = qr0 + 8;

    uint32_t qf[4][4];
    #pragma unroll
    for (int k = 0; k < 4; k++) {
        const __nv_bfloat16* p0 = Qb + (size_t)qr0 * CHD + k * 16 + 2 * tig;
        const __nv_bfloat16* p1 = Qb + (size_t)qr1 * CHD + k * 16 + 2 * tig;
        qf[k][0] = *(const uint32_t*)p0;
        qf[k][1] = *(const uint32_t*)p1;
        qf[k][2] = *(const uint32_t*)(p0 + 8);
        qf[k][3] = *(const uint32_t*)(p1 + 8);
    }

    float o[8][4];
    #pragma unroll
    for (int nt = 0; nt < 8; nt++)
        #pragma unroll
        for (int j = 0; j < 4; j++) o[nt][j] = 0.f;
    float m0 = -INFINITY, m1 = -INFINITY, l0 = 0.f, l1 = 0.f;

    int nkt = blockIdx.x + 1;
    for (int kt = 0; kt < nkt; kt++) {
        int k0 = kt * 64;
        __syncthreads();
        for (int i = tid; i < 512; i += 128) {
            int row = i >> 3, c8 = (i & 7) * 8;
            *(uint4*)&Ks[row][c8] = *(const uint4*)(Kb + (size_t)(k0 + row) * CHD + c8);
            *(uint4*)&Vs[row][c8] = *(const uint4*)(Vb + (size_t)(k0 + row) * CHD + c8);
        }
        __syncthreads();

        float s[8][4];
        #pragma unroll
        for (int nt = 0; nt < 8; nt++)
            #pragma unroll
            for (int j = 0; j < 4; j++) s[nt][j] = 0.f;
        #pragma unroll
        for (int k = 0; k < 4; k++) {
            #pragma unroll
            for (int nt = 0; nt < 8; nt++) {
                uint32_t b0 = *(const uint32_t*)&Ks[nt * 8 + gid][k * 16 + 2 * tig];
                uint32_t b1 = *(const uint32_t*)&Ks[nt * 8 + gid][k * 16 + 8 + 2 * tig];
                mma_bf16(s[nt], qf[k], b0, b1);
            }
        }

        bool diag = (kt == blockIdx.x);
        float rmax0 = -INFINITY, rmax1 = -INFINITY;
        #pragma unroll
        for (int nt = 0; nt < 8; nt++) {
            int cg = k0 + nt * 8 + 2 * tig;
            #pragma unroll
            for (int j = 0; j < 2; j++) {
                float v0 = s[nt][j] * 0.125f;
                float v1 = s[nt][2 + j] * 0.125f;
                if (diag && cg + j > qr0) v0 = -INFINITY;
                if (diag && cg + j > qr1) v1 = -INFINITY;
                s[nt][j] = v0; s[nt][2 + j] = v1;
                rmax0 = fmaxf(rmax0, v0); rmax1 = fmaxf(rmax1, v1);
            }
        }
        rmax0 = fmaxf(rmax0, __shfl_xor_sync(0xffffffffu, rmax0, 1));
        rmax0 = fmaxf(rmax0, __shfl_xor_sync(0xffffffffu, rmax0, 2));
        rmax1 = fmaxf(rmax1, __shfl_xor_sync(0xffffffffu, rmax1, 1));
        rmax1 = fmaxf(rmax1, __shfl_xor_sync(0xffffffffu, rmax1, 2));

        float mn0 = fmaxf(m0, rmax0), mn1 = fmaxf(m1, rmax1);
        float sum0 = 0.f, sum1 = 0.f;
        #pragma unroll
        for (int nt = 0; nt < 8; nt++) {
            s[nt][0] = __expf(s[nt][0] - mn0);
            s[nt][1] = __expf(s[nt][1] - mn0);
            s[nt][2] = __expf(s[nt][2] - mn1);
            s[nt][3] = __expf(s[nt][3] - mn1);
            sum0 += s[nt][0] + s[nt][1];
            sum1 += s[nt][2] + s[nt][3];
        }
        sum0 += __shfl_xor_sync(0xffffffffu, sum0, 1);
        sum0 += __shfl_xor_sync(0xffffffffu, sum0, 2);
        sum1 += __shfl_xor_sync(0xffffffffu, sum1, 1);
        sum1 += __shfl_xor_sync(0xffffffffu, sum1, 2);

        float rs0 = __expf(m0 - mn0), rs1 = __expf(m1 - mn1);
        m0 = mn0; m1 = mn1;
        l0 = l0 * rs0 + sum0;
        l1 = l1 * rs1 + sum1;
        #pragma unroll
        for (int nt = 0; nt < 8; nt++) {
            o[nt][0] *= rs0; o[nt][1] *= rs0;
            o[nt][2] *= rs1; o[nt][3] *= rs1;
        }

        #pragma unroll
        for (int kb = 0; kb < 4; kb++) {
            uint32_t pf[4];
            pf[0] = pack_bf2(s[2 * kb][0], s[2 * kb][1]);
            pf[1] = pack_bf2(s[2 * kb][2], s[2 * kb][3]);
            pf[2] = pack_bf2(s[2 * kb + 1][0], s[2 * kb + 1][1]);
            pf[3] = pack_bf2(s[2 * kb + 1][2], s[2 * kb + 1][3]);
            #pragma unroll
            for (int nb = 0; nb < 4; nb++) {
                uint32_t v0, v1, v2, v3;
                uint32_t addr = (uint32_t)__cvta_generic_to_shared(
                    &Vs[kb * 16 + (lane & 15)][nb * 16 + ((lane >> 4) << 3)]);
                ldmx4t(v0, v1, v2, v3, addr);
                mma_bf16(o[2 * nb], pf, v0, v1);
                mma_bf16(o[2 * nb + 1], pf, v2, v3);
            }
        }
    }

    float inv0 = 1.0f / l0, inv1 = 1.0f / l1;
    int b = bh / CNH, nh = bh % CNH;
    #pragma unroll
    for (int nt = 0; nt < 8; nt++) {
        int col = nt * 8 + 2 * tig;
        float2 w0v = {o[nt][0] * inv0, o[nt][1] * inv0};
        float2 w1v = {o[nt][2] * inv1, o[nt][3] * inv1};
        *(float2*)(Hout + (((size_t)b * CS + qr0) * CNH + nh) * CHD + col) = w0v;
        *(float2*)(Hout + (((size_t)b * CS + qr1) * CNH + nh) * CHD + col) = w1v;
    }
}

// ---------------- MoE elementwise: hh = relu(g)^2 * u, then act_quant ----------------
__global__ void hh_quant(const float* __restrict__ g, const float* __restrict__ u,
                         int8_t* __restrict__ hq, float* __restrict__ hs) {
    __shared__ float red[256];
    __shared__ float hb[CD];
    int slot = blockIdx.x, tid = threadIdx.x;
    float amax = 0.f;
    #pragma unroll
    for (int i = 0; i < 4; i++) {
        int k = tid + i * 256;
        float gv = g[(size_t)slot * CD + k];
        float uv = u[(size_t)slot * CD + k];
        float rl = fmaxf(gv, 0.f);
        float h = rl * rl * uv;
        hb[k] = h;
        amax = fmaxf(amax, fabsf(h));
    }
    amax = blk_reduce_max(amax, red);
    float m = fmaxf(amax, 1e-5f);
    float s = 127.f / m;
    #pragma unroll
    for (int i = 0; i < 4; i++) {
        int k = tid + i * 256;
        float qv = fminf(fmaxf(rintf(hb[k] * s), -128.f), 127.f);
        hq[(size_t)slot * CD + k] = (int8_t)(int)qv;
    }
    if (tid == 0) hs[slot] = m * (1.0f / 127.f);
}

// ---------------- launch ----------------
extern "C" void kernel_launch(void* const* d_in, const int* in_sizes, int n_in,
                              void* d_out, int out_size) {
    const float* x        = (const float*)d_in[0];
    const float* q_w      = (const float*)d_in[1];
    const float* k_w      = (const float*)d_in[2];
    const float* v_w      = (const float*)d_in[3];
    const float* o_w      = (const float*)d_in[4];
    const float* ln1_w    = (const float*)d_in[5];
    const float* ln2_w    = (const float*)d_in[6];
    const float* router_w = (const float*)d_in[7];
    const float* gate_w   = (const float*)d_in[8];
    const float* up_w     = (const float*)d_in[9];
    const float* down_w   = (const float*)d_in[10];

    unsigned char* base = nullptr;
    cudaGetSymbolAddress((void**)&base, g_scratch);

    int8_t* wq_attn = (int8_t*)(base + OFF_WQ_ATTN);
    int8_t* wq_gate = (int8_t*)(base + OFF_WQ_GATE);
    int8_t* wq_up   = (int8_t*)(base + OFF_WQ_UP);
    int8_t* wq_down = (int8_t*)(base + OFF_WQ_DOWN);
    float*  wsc     = (float*)(base + OFF_WSCALE);
    float*  part    = (float*)(base + OFF_PART);
    int8_t* xq1     = (int8_t*)(base + OFF_XQ1);
    float*  a1s     = (float*)(base + OFF_A1S);
    __nv_bfloat16* qkvb = (__nv_bfloat16*)(base + OFF_QKV);
    float*  hb      = (float*)(base + OFF_HB);
    int8_t* hqa     = (int8_t*)(base + OFF_HQA);
    float*  hsa     = (float*)(base + OFF_HSA);
    float*  x2      = (float*)(base + OFF_X2);
    int8_t* xq2     = (int8_t*)(base + OFF_XQ2);
    float*  a2s     = (float*)(base + OFF_A2S);
    int*    idx     = (int*)(base + OFF_IDX);
    int*    cnt     = (int*)(base + OFF_CNT);
    int*    seg     = (int*)(base + OFF_SEG);
    int*    cur     = (int*)(base + OFF_CUR);
    int*    perm    = (int*)(base + OFF_PERM);
    float*  gb      = (float*)(base + OFF_GB);
    float*  ub      = (float*)(base + OFF_UB);
    int8_t* hqm     = (int8_t*)(base + OFF_HQM);
    float*  hsm     = (float*)(base + OFF_HSM);
    float*  out     = (float*)d_out;

    const int LEN4 = (CH * CH) / 4;

    // ---- attention path ----
    rmsnorm_quant<<<CT, 256>>>(x, ln1_w, xq1, a1s);
    absmean4<<<dim3(256, 4), 256>>>(q_w, k_w, v_w, o_w, part, LEN4);
    quantizeF4<<<dim3(256, 4), 256>>>(q_w, k_w, v_w, o_w, wq_attn, part, wsc, LEN4);
    gemm_mma<0><<<dim3(16, 32, 3), 256>>>(xq1, wq_attn, nullptr, qkvb, a1s, wsc, nullptr, nullptr, nullptr);

    attn_fa2<<<dim3(32, CB * CNH), 128>>>(
        qkvb, qkvb + (size_t)CT * CH, qkvb + 2 * (size_t)CT * CH, hb);

    // ---- MoE weight quant ----
    absmean_partial<<<dim3(256, 8), 256>>>(gate_w, part + 4 * 256, LEN4);
    absmean_partial<<<dim3(256, 8), 256>>>(up_w,   part + 12 * 256, LEN4);
    absmean_partial<<<dim3(256, 8), 256>>>(down_w, part + 20 * 256, LEN4);
    finalize_wscale<<<1, 32>>>(part, wsc, 4, 24);
    quantize_w<<<dim3(256, 8), 256>>>(gate_w, wq_gate, wsc, 4, LEN4);
    quantize_w<<<dim3(256, 8), 256>>>(up_w,   wq_up,   wsc, 12, LEN4);
    quantize_w<<<dim3(256, 8), 256>>>(down_w, wq_down, wsc, 20, LEN4);
    zero_ints<<<1, 32>>>(cnt, cur);

    // ---- o-proj + residual ----
    act_quant_rows<<<CT, 256>>>(hb, hqa, hsa);
    gemm_mma<1><<<dim3(16, 32, 1), 256>>>(hqa, wq_attn + 3 * (CH * CH), x2, nullptr, hsa, wsc + 3, x, nullptr, nullptr);

    // ---- MoE ----
    rmsnorm2_router<<<CT, 256>>>(x2, ln2_w, router_w, xq2, a2s, idx, cnt);
    build_offsets<<<1, 1>>>(cnt, seg);
    scatter_tokens<<<16, 256>>>(idx, seg, cur, perm);

    gemm_mma<2><<<dim3(16, 32, 16), 256>>>(xq2, wq_gate, gb, nullptr, a2s, wsc + 4, nullptr, perm, seg);
    hh_quant<<<CT, 256>>>(gb, ub, hqm, hsm);
    gemm_mma<3><<<dim3(16, 32, 8), 256>>>(hqm, wq_down, out, nullptr, hsm, wsc + 20, x2, perm, seg);
}

// round 11
// speedup vs baseline: 2.5265x; 1.0192x over previous
#include <cuda_runtime.h>
#include <cuda_bf16.h>
#include <math.h>
#include <stdint.h>

#define CB 2
#define CS 2048
#define CH 1024
#define CNH 16
#define CHD 64
#define CE 8
#define CD 1024
#define CT (CB*CS)

#define MB (1024ull*1024ull)

// ---------------- scratch layout ----------------
static constexpr size_t OFF_WQ_ATTN = 0;               // 4 MB  int8: q,k,v,o
static constexpr size_t OFF_WQ_GATE = 4*MB;            // 8 MB (gate) — contiguous with up
static constexpr size_t OFF_WQ_UP   = 12*MB;           // 8 MB
static constexpr size_t OFF_WQ_DOWN = 20*MB;           // 8 MB
static constexpr size_t OFF_WSCALE  = 28*MB;           // 28 floats
static constexpr size_t OFF_PART    = 28*MB + 4096;    // 28*256 floats
static constexpr size_t OFF_XQ1     = 29*MB;           // 4 MB int8
static constexpr size_t OFF_A1S     = 33*MB;           // T floats
static constexpr size_t OFF_QKV     = 34*MB;           // 24 MB bf16: q,k,v [B,NH,S,HD]
static constexpr size_t OFF_HB      = 82*MB;           // 16 MB fp32 attention out [T,H]
static constexpr size_t OFF_HQA     = 98*MB;           // 4 MB int8
static constexpr size_t OFF_HSA     = 102*MB;          // T floats
static constexpr size_t OFF_X2      = 103*MB;          // 16 MB fp32
static constexpr size_t OFF_XQ2     = 119*MB;          // 4 MB int8
static constexpr size_t OFF_A2S     = 123*MB;          // T floats
static constexpr size_t OFF_IDX     = 123*MB + 64*1024;
static constexpr size_t OFF_CNT     = 123*MB + 128*1024;
static constexpr size_t OFF_SEG     = 123*MB + 129*1024;
static constexpr size_t OFF_CUR     = 123*MB + 130*1024;
static constexpr size_t OFF_PERM    = 124*MB;          // T ints
static constexpr size_t OFF_GB      = 125*MB;          // 16 MB fp32 (gate) — contiguous with ub
static constexpr size_t OFF_UB      = 141*MB;          // 16 MB fp32
static constexpr size_t OFF_HQM     = 157*MB;          // 4 MB int8
static constexpr size_t OFF_HSM     = 161*MB;          // T floats
static constexpr size_t SCRATCH_BYTES = 162*MB;

__device__ __align__(256) unsigned char g_scratch[SCRATCH_BYTES];

// ---------------- reductions ----------------
__device__ __forceinline__ float blk_reduce_sum(float v, float* red) {
    int tid = threadIdx.x;
    red[tid] = v; __syncthreads();
    #pragma unroll
    for (int s = 128; s > 0; s >>= 1) {
        if (tid < s) red[tid] += red[tid + s];
        __syncthreads();
    }
    float r = red[0]; __syncthreads();
    return r;
}

__device__ __forceinline__ float blk_reduce_max(float v, float* red) {
    int tid = threadIdx.x;
    red[tid] = v; __syncthreads();
    #pragma unroll
    for (int s = 128; s > 0; s >>= 1) {
        if (tid < s) red[tid] = fmaxf(red[tid], red[tid + s]);
        __syncthreads();
    }
    float r = red[0]; __syncthreads();
    return r;
}

// ---------------- weight quantization (4x float4 ILP; len4 = 262144 = 256*1024) ----------------
__device__ __forceinline__ float abs4(float4 v) {
    return fabsf(v.x) + fabsf(v.y) + fabsf(v.z) + fabsf(v.w);
}

__global__ void absmean_partial(const float* __restrict__ w, float* __restrict__ part, int len4) {
    __shared__ float red[256];
    const float4* p = (const float4*)w + (size_t)blockIdx.y * len4;
    int i = blockIdx.x * 1024 + threadIdx.x;
    float4 v0 = p[i], v1 = p[i + 256], v2 = p[i + 512], v3 = p[i + 768];
    float s = (abs4(v0) + abs4(v1)) + (abs4(v2) + abs4(v3));
    s = blk_reduce_sum(s, red);
    if (threadIdx.x == 0) part[(size_t)blockIdx.y * gridDim.x + blockIdx.x] = s;
}

__global__ void absmean4(const float* __restrict__ w0, const float* __restrict__ w1,
                         const float* __restrict__ w2, const float* __restrict__ w3,
                         float* __restrict__ part, int len4) {
    __shared__ float red[256];
    int sl = blockIdx.y;
    const float* p = sl == 0 ? w0 : sl == 1 ? w1 : sl == 2 ? w2 : w3;
    const float4* p4 = (const float4*)p;
    int i = blockIdx.x * 1024 + threadIdx.x;
    float4 v0 = p4[i], v1 = p4[i + 256], v2 = p4[i + 512], v3 = p4[i + 768];
    float s = (abs4(v0) + abs4(v1)) + (abs4(v2) + abs4(v3));
    s = blk_reduce_sum(s, red);
    if (threadIdx.x == 0) part[(size_t)sl * gridDim.x + blockIdx.x] = s;
}

__global__ void finalize_wscale(const float* __restrict__ part, float* __restrict__ wsc,
                                int i0, int n) {
    int i = i0 + threadIdx.x;
    if (threadIdx.x >= n) return;
    float s = 0.f;
    for (int j = 0; j < 256; j++) s += part[i * 256 + j];
    wsc[i] = fmaxf(s * (1.0f / (1024.f * 1024.f)), 1e-5f);
}

__device__ __forceinline__ char quant_tern(float v, float s) {
    float q = rintf(v * s);
    q = fminf(fmaxf(q, -1.f), 1.f);
    return (char)(int)q;
}

__device__ __forceinline__ char4 qt4(float4 v, float s) {
    char4 o;
    o.x = quant_tern(v.x, s); o.y = quant_tern(v.y, s);
    o.z = quant_tern(v.z, s); o.w = quant_tern(v.w, s);
    return o;
}

__global__ void quantize_w(const float* __restrict__ w, int8_t* __restrict__ wq,
                           const float* __restrict__ wsc, int widx0, int len4) {
    int slice = blockIdx.y;
    float s = 1.0f / wsc[widx0 + slice];
    const float4* p = (const float4*)w + (size_t)slice * len4;
    char4* q = (char4*)wq + (size_t)slice * len4;
    int i = blockIdx.x * 1024 + threadIdx.x;
    float4 v0 = p[i], v1 = p[i + 256], v2 = p[i + 512], v3 = p[i + 768];
    q[i] = qt4(v0, s); q[i + 256] = qt4(v1, s);
    q[i + 512] = qt4(v2, s); q[i + 768] = qt4(v3, s);
}

// fused finalize + quantize for the 4 attention matrices
__global__ void quantizeF4(const float* __restrict__ w0, const float* __restrict__ w1,
                           const float* __restrict__ w2, const float* __restrict__ w3,
                           int8_t* __restrict__ wq, const float* __restrict__ part,
                           float* __restrict__ wsc, int len4) {
    __shared__ float red[256];
    int sl = blockIdx.y;
    int tid = threadIdx.x;
    float total = blk_reduce_sum(part[sl * 256 + tid], red);
    float mean = fmaxf(total * (1.0f / (1024.f * 1024.f)), 1e-5f);
    if (blockIdx.x == 0 && tid == 0) wsc[sl] = mean;
    float s = 1.0f / mean;
    const float* p = sl == 0 ? w0 : sl == 1 ? w1 : sl == 2 ? w2 : w3;
    const float4* p4 = (const float4*)p;
    char4* q = (char4*)wq + (size_t)sl * len4;
    int i = blockIdx.x * 1024 + tid;
    float4 v0 = p4[i], v1 = p4[i + 256], v2 = p4[i + 512], v3 = p4[i + 768];
    q[i] = qt4(v0, s); q[i + 256] = qt4(v1, s);
    q[i + 512] = qt4(v2, s); q[i + 768] = qt4(v3, s);
}

// ---------------- activation rmsnorm + quant ----------------
__global__ void rmsnorm_quant(const float* __restrict__ x, const float* __restrict__ lnw,
                              int8_t* __restrict__ xq, float* __restrict__ ainv) {
    __shared__ float red[256];
    __shared__ float xs[CH];
    int t = blockIdx.x, tid = threadIdx.x;
    const float* xr = x + (size_t)t * CH;
    float v[4]; float ss = 0.f;
    #pragma unroll
    for (int i = 0; i < 4; i++) { v[i] = xr[tid + i * 256]; ss += v[i] * v[i]; }
    ss = blk_reduce_sum(ss, red);
    float r = rsqrtf(ss * (1.0f / CH) + 1e-5f);
    float amax = 0.f;
    #pragma unroll
    for (int i = 0; i < 4; i++) {
        float xn = v[i] * r * lnw[tid + i * 256];
        xs[tid + i * 256] = xn;
        amax = fmaxf(amax, fabsf(xn));
    }
    amax = blk_reduce_max(amax, red);
    float m = fmaxf(amax, 1e-5f);
    float s = 127.f / m;
    #pragma unroll
    for (int i = 0; i < 4; i++) {
        float qv = fminf(fmaxf(rintf(xs[tid + i * 256] * s), -128.f), 127.f);
        xq[(size_t)t * CH + tid + i * 256] = (int8_t)(int)qv;
    }
    if (tid == 0) ainv[t] = m * (1.0f / 127.f);
}

__global__ void act_quant_rows(const float* __restrict__ x, int8_t* __restrict__ xq,
                               float* __restrict__ ainv) {
    __shared__ float red[256];
    int t = blockIdx.x, tid = threadIdx.x;
    const float* xr = x + (size_t)t * CH;
    float v[4]; float amax = 0.f;
    #pragma unroll
    for (int i = 0; i < 4; i++) { v[i] = xr[tid + i * 256]; amax = fmaxf(amax, fabsf(v[i])); }
    amax = blk_reduce_max(amax, red);
    float m = fmaxf(amax, 1e-5f);
    float s = 127.f / m;
    #pragma unroll
    for (int i = 0; i < 4; i++) {
        float qv = fminf(fmaxf(rintf(v[i] * s), -128.f), 127.f);
        xq[(size_t)t * CH + tid + i * 256] = (int8_t)(int)qv;
    }
    if (tid == 0) ainv[t] = m * (1.0f / 127.f);
}

__global__ void rmsnorm2_router(const float* __restrict__ x, const float* __restrict__ lnw,
                                const float* __restrict__ rw, int8_t* __restrict__ xq,
                                float* __restrict__ ainv, int* __restrict__ idx,
                                int* __restrict__ counts) {
    __shared__ float red[256];
    __shared__ float xs[CH];
    __shared__ float logits[CE];
    int t = blockIdx.x, tid = threadIdx.x;
    const float* xr = x + (size_t)t * CH;
    float v[4]; float ss = 0.f;
    #pragma unroll
    for (int i = 0; i < 4; i++) { v[i] = xr[tid + i * 256]; ss += v[i] * v[i]; }
    ss = blk_reduce_sum(ss, red);
    float r = rsqrtf(ss * (1.0f / CH) + 1e-5f);
    float amax = 0.f;
    #pragma unroll
    for (int i = 0; i < 4; i++) {
        float xn = v[i] * r * lnw[tid + i * 256];
        xs[tid + i * 256] = xn;
        amax = fmaxf(amax, fabsf(xn));
    }
    amax = blk_reduce_max(amax, red);
    float m = fmaxf(amax, 1e-5f);
    float s = 127.f / m;
    #pragma unroll
    for (int i = 0; i < 4; i++) {
        float qv = fminf(fmaxf(rintf(xs[tid + i * 256] * s), -128.f), 127.f);
        xq[(size_t)t * CH + tid + i * 256] = (int8_t)(int)qv;
    }
    if (tid == 0) ainv[t] = m * (1.0f / 127.f);
    __syncthreads();

    int w = tid >> 5, lane = tid & 31;
    float acc = 0.f;
    for (int h = lane; h < CH; h += 32) acc += xs[h] * rw[w * CH + h];
    #pragma unroll
    for (int o = 16; o > 0; o >>= 1) acc += __shfl_down_sync(0xffffffffu, acc, o);
    if (lane == 0) logits[w] = acc;
    __syncthreads();
    if (tid == 0) {
        float best = logits[0]; int bi = 0;
        #pragma unroll
        for (int e = 1; e < CE; e++) if (logits[e] > best) { best = logits[e]; bi = e; }
        idx[t] = bi;
        atomicAdd(&counts[bi], 1);
    }
}

__global__ void zero_ints(int* __restrict__ counts, int* __restrict__ cursor) {
    if (threadIdx.x < CE) { counts[threadIdx.x] = 0; cursor[threadIdx.x] = 0; }
}

__global__ void build_offsets(const int* __restrict__ counts, int* __restrict__ seg) {
    if (threadIdx.x == 0) {
        int a = 0;
        for (int e = 0; e < CE; e++) { seg[e] = a; a += counts[e]; }
        seg[CE] = a;
    }
}

__global__ void scatter_tokens(const int* __restrict__ idx, const int* __restrict__ seg,
                               int* __restrict__ cursor, int* __restrict__ perm) {
    int t = blockIdx.x * 256 + threadIdx.x;
    if (t >= CT) return;
    int e = idx[t];
    int p = atomicAdd(&cursor[e], 1);
    perm[seg[e] + p] = t;
}

// ---------------- int8 x ternary GEMM via mma.sync m16n8k32, double-buffered smem ----------------
__device__ __forceinline__ void mma_s8(int* c, const int* a, const int* b) {
    asm volatile(
        "mma.sync.aligned.m16n8k32.row.col.s32.s8.s8.s32 "
        "{%0,%1,%2,%3}, {%4,%5,%6,%7}, {%8,%9}, {%0,%1,%2,%3};"
        : "+r"(c[0]), "+r"(c[1]), "+r"(c[2]), "+r"(c[3])
        : "r"(a[0]), "r"(a[1]), "r"(a[2]), "r"(a[3]), "r"(b[0]), "r"(b[1]));
}

template<int MODE>
__global__ void __launch_bounds__(256) gemm_mma(
        const int8_t* __restrict__ A, const int8_t* __restrict__ Bw,
        float* __restrict__ Out, __nv_bfloat16* __restrict__ OutB,
        const float* __restrict__ ascale,
        const float* __restrict__ wscale,
        const float* __restrict__ resid,
        const int* __restrict__ perm,
        const int* __restrict__ seg) {
    int n0 = blockIdx.x * 64;
    int m0 = blockIdx.y * 128;
    int z = blockIdx.z;
    int e = (MODE == 2) ? (z & 7) : z;

    int off = 0, cnt = CT;
    if (MODE >= 2) {
        off = seg[e];
        cnt = seg[e + 1] - off;
        if (m0 >= cnt) return;
    }

    const int8_t* Bz = Bw;
    if (MODE == 0) Bz = Bw + (size_t)z * (CH * CH);
    if (MODE >= 2) Bz = Bw + (size_t)z * ((size_t)CD * CH);
    const int8_t* brow0 = Bz + (size_t)n0 * 1024;

    __shared__ __align__(16) int8_t As[2][128][80];
    __shared__ __align__(16) int8_t Bs[2][64][80];
    __shared__ const int8_t* aptr[128];
    __shared__ float rowsc[128];
    __shared__ int dstrow[128];

    int tid = threadIdx.x;
    if (tid < 128) {
        int r = m0 + tid;
        if (MODE <= 1) {
            aptr[tid] = A + (size_t)r * 1024;
            rowsc[tid] = ascale[r];
        } else if (MODE == 2) {
            int rr = r < cnt - 1 ? r : cnt - 1;
            int tok = perm[off + rr];
            aptr[tid] = A + (size_t)tok * 1024;
            rowsc[tid] = ascale[tok];
            dstrow[tid] = off + r;
        } else {
            int rr = r < cnt - 1 ? r : cnt - 1;
            aptr[tid] = A + (size_t)(off + rr) * 1024;
            rowsc[tid] = ascale[off + rr];
            dstrow[tid] = perm[off + rr];
        }
    }
    __syncthreads();

    int ar = tid >> 1, ao = (tid & 1) * 32;
    int brr = tid >> 2, bo = (tid & 3) * 16;
    const int8_t* pA = aptr[ar];
    const int8_t* pB = brow0 + (size_t)brr * 1024;

    int w = tid >> 5, lane = tid & 31;
    int warpM = w & 3, warpN = w >> 2;
    int gid = lane >> 2, tig = lane & 3;

    int c[2][4][4];
    #pragma unroll
    for (int i = 0; i < 2; i++)
        #pragma unroll
        for (int j = 0; j < 4; j++)
            #pragma unroll
            for (int k = 0; k < 4; k++) c[i][j][k] = 0;

    int rowA0 = warpM * 32 + gid;
    int rowB0 = warpN * 32 + gid;
    int kcol = tig * 4;

    // prologue: stage 0 into buffer 0
    {
        int4 pa0 = *(const int4*)(pA + ao);
        int4 pa1 = *(const int4*)(pA + ao + 16);
        int4 pb  = *(const int4*)(pB + bo);
        *(int4*)&As[0][ar][ao]      = pa0;
        *(int4*)&As[0][ar][ao + 16] = pa1;
        *(int4*)&Bs[0][brr][bo]     = pb;
    }
    __syncthreads();

    #pragma unroll 1
    for (int kt = 0; kt < 16; kt++) {
        int cur = kt & 1, nxt = cur ^ 1;
        int4 pa0, pa1, pb;
        if (kt < 15) {
            int base = (kt + 1) * 64;
            pa0 = *(const int4*)(pA + base + ao);
            pa1 = *(const int4*)(pA + base + ao + 16);
            pb  = *(const int4*)(pB + base + bo);
        }
        #pragma unroll
        for (int ks = 0; ks < 2; ks++) {
            int kb = ks * 32 + kcol;
            int a[2][4];
            #pragma unroll
            for (int wm = 0; wm < 2; wm++) {
                int rA = rowA0 + wm * 16;
                a[wm][0] = *(const int*)&As[cur][rA][kb];
                a[wm][1] = *(const int*)&As[cur][rA + 8][kb];
                a[wm][2] = *(const int*)&As[cur][rA][kb + 16];
                a[wm][3] = *(const int*)&As[cur][rA + 8][kb + 16];
            }
            int b[4][2];
            #pragma unroll
            for (int nt = 0; nt < 4; nt++) {
                int rB = rowB0 + nt * 8;
                b[nt][0] = *(const int*)&Bs[cur][rB][kb];
                b[nt][1] = *(const int*)&Bs[cur][rB][kb + 16];
            }
            #pragma unroll
            for (int wm = 0; wm < 2; wm++)
                #pragma unroll
                for (int nt = 0; nt < 4; nt++)
                    mma_s8(c[wm][nt], a[wm], b[nt]);
        }
        if (kt < 15) {
            *(int4*)&As[nxt][ar][ao]      = pa0;
            *(int4*)&As[nxt][ar][ao + 16] = pa1;
            *(int4*)&Bs[nxt][brr][bo]     = pb;
            __syncthreads();
        }
    }

    float wS = wscale[(MODE == 0 || MODE >= 2) ? z : 0];

    #pragma unroll
    for (int wm = 0; wm < 2; wm++) {
        int r0 = warpM * 32 + wm * 16 + gid;
        int r1 = r0 + 8;
        float av0 = rowsc[r0] * wS;
        float av1 = rowsc[r1] * wS;
        #pragma unroll
        for (int nt = 0; nt < 4; nt++) {
            int colL = warpN * 32 + nt * 8 + tig * 2;
            int* cc = c[wm][nt];
            if (MODE == 0) {
                int nh = n0 >> 6;
                int gr0 = m0 + r0, gr1 = m0 + r1;
                int b0 = gr0 / CS, sr0 = gr0 % CS;
                int b1 = gr1 / CS, sr1 = gr1 % CS;
                __nv_bfloat16* base = OutB + (size_t)z * ((size_t)CT * CH);
                __nv_bfloat162 o0 = {__float2bfloat16(cc[0] * av0), __float2bfloat16(cc[1] * av0)};
                __nv_bfloat162 o1 = {__float2bfloat16(cc[2] * av1), __float2bfloat16(cc[3] * av1)};
                *(__nv_bfloat162*)(base + (((size_t)b0 * CNH + nh) * CS + sr0) * CHD + colL) = o0;
                *(__nv_bfloat162*)(base + (((size_t)b1 * CNH + nh) * CS + sr1) * CHD + colL) = o1;
            } else if (MODE == 1) {
                size_t rb0 = (size_t)(m0 + r0) * CH + n0 + colL;
                size_t rb1 = (size_t)(m0 + r1) * CH + n0 + colL;
                float2 rv0 = *(const float2*)(resid + rb0);
                float2 rv1 = *(const float2*)(resid + rb1);
                float2 o0 = {rv0.x + cc[0] * av0, rv0.y + cc[1] * av0};
                float2 o1 = {rv1.x + cc[2] * av1, rv1.y + cc[3] * av1};
                *(float2*)(Out + rb0) = o0;
                *(float2*)(Out + rb1) = o1;
            } else if (MODE == 2) {
                size_t half = (size_t)(z >> 3) * ((size_t)CT * CD);
                if (m0 + r0 < cnt) {
                    size_t rb = half + (size_t)dstrow[r0] * CD + n0 + colL;
                    float2 o = {cc[0] * av0, cc[1] * av0};
                    *(float2*)(Out + rb) = o;
                }
                if (m0 + r1 < cnt) {
                    size_t rb = half + (size_t)dstrow[r1] * CD + n0 + colL;
                    float2 o = {cc[2] * av1, cc[3] * av1};
                    *(float2*)(Out + rb) = o;
                }
            } else {
                if (m0 + r0 < cnt) {
                    size_t rb = (size_t)dstrow[r0] * CH + n0 + colL;
                    float2 rv = *(const float2*)(resid + rb);
                    float2 o = {rv.x + cc[0] * av0, rv.y + cc[1] * av0};
                    *(float2*)(Out + rb) = o;
                }
                if (m0 + r1 < cnt) {
                    size_t rb = (size_t)dstrow[r1] * CH + n0 + colL;
                    float2 rv = *(const float2*)(resid + rb);
                    float2 o = {rv.x + cc[2] * av1, rv.y + cc[3] * av1};
                    *(float2*)(Out + rb) = o;
                }
            }
        }
    }
}

// ---------------- attention: FA2-style, register-resident (round-8 proven) ----------------
__device__ __forceinline__ void mma_bf16(float* c, const uint32_t* a, uint32_t b0, uint32_t b1) {
    asm volatile(
        "mma.sync.aligned.m16n8k16.row.col.f32.bf16.bf16.f32 "
        "{%0,%1,%2,%3}, {%4,%5,%6,%7}, {%8,%9}, {%0,%1,%2,%3};"
        : "+f"(c[0]), "+f"(c[1]), "+f"(c[2]), "+f"(c[3])
        : "r"(a[0]), "r"(a[1]), "r"(a[2]), "r"(a[3]), "r"(b0), "r"(b1));
}

__device__ __forceinline__ void ldmx4t(uint32_t& r0, uint32_t& r1, uint32_t& r2, uint32_t& r3,
                                       uint32_t addr) {
    asm volatile("ldmatrix.sync.aligned.m8n8.x4.trans.shared.b16 {%0,%1,%2,%3}, [%4];"
        : "=r"(r0), "=r"(r1), "=r"(r2), "=r"(r3) : "r"(addr));
}

__device__ __forceinline__ uint32_t pack_bf2(float a, float b) {
    __nv_bfloat162 t = __floats2bfloat162_rn(a, b);
    return *(uint32_t*)&t;
}

static constexpr int KLD = 72;

__global__ void __launch_bounds__(128) attn_fa2(
        const __nv_bfloat16* __restrict__ Qg, const __nv_bfloat16* __restrict__ Kg,
        const __nv_bfloat16* __restrict__ Vg, float* __restrict__ Hout) {
    __shared__ __align__(16) __nv_bfloat16 Ks[64][KLD];
    __shared__ __align__(16) __nv_bfloat16 Vs[64][KLD];

    int bh = blockIdx.y;
    int q0 = blockIdx.x * 64;
    const __nv_bfloat16* Qb = Qg + (size_t)bh * CS * CHD;
    const __nv_bfloat16* Kb = Kg + (size_t)bh * CS * CHD;
    const __nv_bfloat16* Vb = Vg + (size_t)bh * CS * CHD;

    int tid = threadIdx.x;
    int w = tid >> 5, lane = tid & 31;
    int gid = lane >> 2, tig = lane & 3;

    int qr0 = q0 + w * 16 + gid;
    int qr1 = qr0 + 8;

    uint32_t qf[4][4];
    #pragma unroll
    for (int k = 0; k < 4; k++) {
        const __nv_bfloat16* p0 = Qb + (size_t)qr0 * CHD + k * 16 + 2 * tig;
        const __nv_bfloat16* p1 = Qb + (size_t)qr1 * CHD + k * 16 + 2 * tig;
        qf[k][0] = *(const uint32_t*)p0;
        qf[k][1] = *(const uint32_t*)p1;
        qf[k][2] = *(const uint32_t*)(p0 + 8);
        qf[k][3] = *(const uint32_t*)(p1 + 8);
    }

    float o[8][4];
    #pragma unroll
    for (int nt = 0; nt < 8; nt++)
        #pragma unroll
        for (int j = 0; j < 4; j++) o[nt][j] = 0.f;
    float m0 = -INFINITY, m1 = -INFINITY, l0 = 0.f, l1 = 0.f;

    int nkt = blockIdx.x + 1;
    for (int kt = 0; kt < nkt; kt++) {
        int k0 = kt * 64;
        __syncthreads();
        for (int i = tid; i < 512; i += 128) {
            int row = i >> 3, c8 = (i & 7) * 8;
            *(uint4*)&Ks[row][c8] = *(const uint4*)(Kb + (size_t)(k0 + row) * CHD + c8);
            *(uint4*)&Vs[row][c8] = *(const uint4*)(Vb + (size_t)(k0 + row) * CHD + c8);
        }
        __syncthreads();

        float s[8][4];
        #pragma unroll
        for (int nt = 0; nt < 8; nt++)
            #pragma unroll
            for (int j = 0; j < 4; j++) s[nt][j] = 0.f;
        #pragma unroll
        for (int k = 0; k < 4; k++) {
            #pragma unroll
            for (int nt = 0; nt < 8; nt++) {
                uint32_t b0 = *(const uint32_t*)&Ks[nt * 8 + gid][k * 16 + 2 * tig];
                uint32_t b1 = *(const uint32_t*)&Ks[nt * 8 + gid][k * 16 + 8 + 2 * tig];
                mma_bf16(s[nt], qf[k], b0, b1);
            }
        }

        bool diag = (kt == blockIdx.x);
        float rmax0 = -INFINITY, rmax1 = -INFINITY;
        #pragma unroll
        for (int nt = 0; nt < 8; nt++) {
            int cg = k0 + nt * 8 + 2 * tig;
            #pragma unroll
            for (int j = 0; j < 2; j++) {
                float v0 = s[nt][j] * 0.125f;
                float v1 = s[nt][2 + j] * 0.125f;
                if (diag && cg + j > qr0) v0 = -INFINITY;
                if (diag && cg + j > qr1) v1 = -INFINITY;
                s[nt][j] = v0; s[nt][2 + j] = v1;
                rmax0 = fmaxf(rmax0, v0); rmax1 = fmaxf(rmax1, v1);
            }
        }
        rmax0 = fmaxf(rmax0, __shfl_xor_sync(0xffffffffu, rmax0, 1));
        rmax0 = fmaxf(rmax0, __shfl_xor_sync(0xffffffffu, rmax0, 2));
        rmax1 = fmaxf(rmax1, __shfl_xor_sync(0xffffffffu, rmax1, 1));
        rmax1 = fmaxf(rmax1, __shfl_xor_sync(0xffffffffu, rmax1, 2));

        float mn0 = fmaxf(m0, rmax0), mn1 = fmaxf(m1, rmax1);
        float sum0 = 0.f, sum1 = 0.f;
        #pragma unroll
        for (int nt = 0; nt < 8; nt++) {
            s[nt][0] = __expf(s[nt][0] - mn0);
            s[nt][1] = __expf(s[nt][1] - mn0);
            s[nt][2] = __expf(s[nt][2] - mn1);
            s[nt][3] = __expf(s[nt][3] - mn1);
            sum0 += s[nt][0] + s[nt][1];
            sum1 += s[nt][2] + s[nt][3];
        }
        sum0 += __shfl_xor_sync(0xffffffffu, sum0, 1);
        sum0 += __shfl_xor_sync(0xffffffffu, sum0, 2);
        sum1 += __shfl_xor_sync(0xffffffffu, sum1, 1);
        sum1 += __shfl_xor_sync(0xffffffffu, sum1, 2);

        float rs0 = __expf(m0 - mn0), rs1 = __expf(m1 - mn1);
        m0 = mn0; m1 = mn1;
        l0 = l0 * rs0 + sum0;
        l1 = l1 * rs1 + sum1;
        #pragma unroll
        for (int nt = 0; nt < 8; nt++) {
            o[nt][0] *= rs0; o[nt][1] *= rs0;
            o[nt][2] *= rs1; o[nt][3] *= rs1;
        }

        #pragma unroll
        for (int kb = 0; kb < 4; kb++) {
            uint32_t pf[4];
            pf[0] = pack_bf2(s[2 * kb][0], s[2 * kb][1]);
            pf[1] = pack_bf2(s[2 * kb][2], s[2 * kb][3]);
            pf[2] = pack_bf2(s[2 * kb + 1][0], s[2 * kb + 1][1]);
            pf[3] = pack_bf2(s[2 * kb + 1][2], s[2 * kb + 1][3]);
            #pragma unroll
            for (int nb = 0; nb < 4; nb++) {
                uint32_t v0, v1, v2, v3;
                uint32_t addr = (uint32_t)__cvta_generic_to_shared(
                    &Vs[kb * 16 + (lane & 15)][nb * 16 + ((lane >> 4) << 3)]);
                ldmx4t(v0, v1, v2, v3, addr);
                mma_bf16(o[2 * nb], pf, v0, v1);
                mma_bf16(o[2 * nb + 1], pf, v2, v3);
            }
        }
    }

    float inv0 = 1.0f / l0, inv1 = 1.0f / l1;
    int b = bh / CNH, nh = bh % CNH;
    #pragma unroll
    for (int nt = 0; nt < 8; nt++) {
        int col = nt * 8 + 2 * tig;
        float2 w0v = {o[nt][0] * inv0, o[nt][1] * inv0};
        float2 w1v = {o[nt][2] * inv1, o[nt][3] * inv1};
        *(float2*)(Hout + (((size_t)b * CS + qr0) * CNH + nh) * CHD + col) = w0v;
        *(float2*)(Hout + (((size_t)b * CS + qr1) * CNH + nh) * CHD + col) = w1v;
    }
}

// ---------------- MoE elementwise: hh = relu(g)^2 * u, then act_quant ----------------
__global__ void hh_quant(const float* __restrict__ g, const float* __restrict__ u,
                         int8_t* __restrict__ hq, float* __restrict__ hs) {
    __shared__ float red[256];
    __shared__ float hb[CD];
    int slot = blockIdx.x, tid = threadIdx.x;
    float amax = 0.f;
    #pragma unroll
    for (int i = 0; i < 4; i++) {
        int k = tid + i * 256;
        float gv = g[(size_t)slot * CD + k];
        float uv = u[(size_t)slot * CD + k];
        float rl = fmaxf(gv, 0.f);
        float h = rl * rl * uv;
        hb[k] = h;
        amax = fmaxf(amax, fabsf(h));
    }
    amax = blk_reduce_max(amax, red);
    float m = fmaxf(amax, 1e-5f);
    float s = 127.f / m;
    #pragma unroll
    for (int i = 0; i < 4; i++) {
        int k = tid + i * 256;
        float qv = fminf(fmaxf(rintf(hb[k] * s), -128.f), 127.f);
        hq[(size_t)slot * CD + k] = (int8_t)(int)qv;
    }
    if (tid == 0) hs[slot] = m * (1.0f / 127.f);
}

// ---------------- launch (fork-join dual stream) ----------------
extern "C" void kernel_launch(void* const* d_in, const int* in_sizes, int n_in,
                              void* d_out, int out_size) {
    const float* x        = (const float*)d_in[0];
    const float* q_w      = (const float*)d_in[1];
    const float* k_w      = (const float*)d_in[2];
    const float* v_w      = (const float*)d_in[3];
    const float* o_w      = (const float*)d_in[4];
    const float* ln1_w    = (const float*)d_in[5];
    const float* ln2_w    = (const float*)d_in[6];
    const float* router_w = (const float*)d_in[7];
    const float* gate_w   = (const float*)d_in[8];
    const float* up_w     = (const float*)d_in[9];
    const float* down_w   = (const float*)d_in[10];

    unsigned char* base = nullptr;
    cudaGetSymbolAddress((void**)&base, g_scratch);

    int8_t* wq_attn = (int8_t*)(base + OFF_WQ_ATTN);
    int8_t* wq_gate = (int8_t*)(base + OFF_WQ_GATE);
    int8_t* wq_up   = (int8_t*)(base + OFF_WQ_UP);
    int8_t* wq_down = (int8_t*)(base + OFF_WQ_DOWN);
    float*  wsc     = (float*)(base + OFF_WSCALE);
    float*  part    = (float*)(base + OFF_PART);
    int8_t* xq1     = (int8_t*)(base + OFF_XQ1);
    float*  a1s     = (float*)(base + OFF_A1S);
    __nv_bfloat16* qkvb = (__nv_bfloat16*)(base + OFF_QKV);
    float*  hb      = (float*)(base + OFF_HB);
    int8_t* hqa     = (int8_t*)(base + OFF_HQA);
    float*  hsa     = (float*)(base + OFF_HSA);
    float*  x2      = (float*)(base + OFF_X2);
    int8_t* xq2     = (int8_t*)(base + OFF_XQ2);
    float*  a2s     = (float*)(base + OFF_A2S);
    int*    idx     = (int*)(base + OFF_IDX);
    int*    cnt     = (int*)(base + OFF_CNT);
    int*    seg     = (int*)(base + OFF_SEG);
    int*    cur     = (int*)(base + OFF_CUR);
    int*    perm    = (int*)(base + OFF_PERM);
    float*  gb      = (float*)(base + OFF_GB);
    float*  ub      = (float*)(base + OFF_UB);
    int8_t* hqm     = (int8_t*)(base + OFF_HQM);
    float*  hsm     = (float*)(base + OFF_HSM);
    float*  out     = (float*)d_out;

    const int LEN4 = (CH * CH) / 4;

    // fork-join side stream (created per call; not destroyed during active capture)
    cudaStream_t s2;
    cudaStreamCreateWithFlags(&s2, cudaStreamNonBlocking);
    cudaEvent_t evFork, evB, evJoin;
    cudaEventCreateWithFlags(&evFork, cudaEventDisableTiming);
    cudaEventCreateWithFlags(&evB, cudaEventDisableTiming);
    cudaEventCreateWithFlags(&evJoin, cudaEventDisableTiming);

    cudaEventRecord(evFork, 0);
    cudaStreamWaitEvent(s2, evFork, 0);

    // ---- side stream: activation quant, then MoE weight quant (independent) ----
    rmsnorm_quant<<<CT, 256, 0, s2>>>(x, ln1_w, xq1, a1s);
    cudaEventRecord(evB, s2);
    absmean_partial<<<dim3(256, 8), 256, 0, s2>>>(gate_w, part + 4 * 256, LEN4);
    absmean_partial<<<dim3(256, 8), 256, 0, s2>>>(up_w,   part + 12 * 256, LEN4);
    absmean_partial<<<dim3(256, 8), 256, 0, s2>>>(down_w, part + 20 * 256, LEN4);
    finalize_wscale<<<1, 32, 0, s2>>>(part, wsc, 4, 24);
    quantize_w<<<dim3(256, 8), 256, 0, s2>>>(gate_w, wq_gate, wsc, 4, LEN4);
    quantize_w<<<dim3(256, 8), 256, 0, s2>>>(up_w,   wq_up,   wsc, 12, LEN4);
    quantize_w<<<dim3(256, 8), 256, 0, s2>>>(down_w, wq_down, wsc, 20, LEN4);
    cudaEventRecord(evJoin, s2);

    // ---- main stream: attention weights + attention path ----
    zero_ints<<<1, 32>>>(cnt, cur);
    absmean4<<<dim3(256, 4), 256>>>(q_w, k_w, v_w, o_w, part, LEN4);
    quantizeF4<<<dim3(256, 4), 256>>>(q_w, k_w, v_w, o_w, wq_attn, part, wsc, LEN4);
    cudaStreamWaitEvent(0, evB, 0);   // xq1 ready
    gemm_mma<0><<<dim3(16, 32, 3), 256>>>(xq1, wq_attn, nullptr, qkvb, a1s, wsc, nullptr, nullptr, nullptr);

    attn_fa2<<<dim3(32, CB * CNH), 128>>>(
        qkvb, qkvb + (size_t)CT * CH, qkvb + 2 * (size_t)CT * CH, hb);

    // ---- o-proj + residual ----
    act_quant_rows<<<CT, 256>>>(hb, hqa, hsa);
    gemm_mma<1><<<dim3(16, 32, 1), 256>>>(hqa, wq_attn + 3 * (CH * CH), x2, nullptr, hsa, wsc + 3, x, nullptr, nullptr);

    // ---- MoE ----
    rmsnorm2_router<<<CT, 256>>>(x2, ln2_w, router_w, xq2, a2s, idx, cnt);
    build_offsets<<<1, 1>>>(cnt, seg);
    scatter_tokens<<<16, 256>>>(idx, seg, cur, perm);

    cudaStreamWaitEvent(0, evJoin, 0);   // MoE weights ready
    gemm_mma<2><<<dim3(16, 32, 16), 256>>>(xq2, wq_gate, gb, nullptr, a2s, wsc + 4, nullptr, perm, seg);
    hh_quant<<<CT, 256>>>(gb, ub, hqm, hsm);
    gemm_mma<3><<<dim3(16, 32, 8), 256>>>(hqm, wq_down, out, nullptr, hsm, wsc + 20, x2, perm, seg);
}

// round 12
// speedup vs baseline: 2.5317x; 1.0021x over previous
#include <cuda_runtime.h>
#include <cuda_bf16.h>
#include <math.h>
#include <stdint.h>

#define CB 2
#define CS 2048
#define CH 1024
#define CNH 16
#define CHD 64
#define CE 8
#define CD 1024
#define CT (CB*CS)

#define MB (1024ull*1024ull)

// ---------------- scratch layout ----------------
static constexpr size_t OFF_WQ_ATTN = 0;
static constexpr size_t OFF_WQ_GATE = 4*MB;
static constexpr size_t OFF_WQ_UP   = 12*MB;
static constexpr size_t OFF_WQ_DOWN = 20*MB;
static constexpr size_t OFF_WSCALE  = 28*MB;
static constexpr size_t OFF_PART    = 28*MB + 4096;
static constexpr size_t OFF_XQ1     = 29*MB;
static constexpr size_t OFF_A1S     = 33*MB;
static constexpr size_t OFF_QKV     = 34*MB;
static constexpr size_t OFF_HB      = 82*MB;
static constexpr size_t OFF_HQA     = 98*MB;
static constexpr size_t OFF_HSA     = 102*MB;
static constexpr size_t OFF_X2      = 103*MB;
static constexpr size_t OFF_XQ2     = 119*MB;
static constexpr size_t OFF_A2S     = 123*MB;
static constexpr size_t OFF_IDX     = 123*MB + 64*1024;
static constexpr size_t OFF_CNT     = 123*MB + 128*1024;
static constexpr size_t OFF_SEG     = 123*MB + 129*1024;
static constexpr size_t OFF_CUR     = 123*MB + 130*1024;
static constexpr size_t OFF_PERM    = 124*MB;
static constexpr size_t OFF_GB      = 125*MB;
static constexpr size_t OFF_UB      = 141*MB;
static constexpr size_t OFF_HQM     = 157*MB;
static constexpr size_t OFF_HSM     = 161*MB;
static constexpr size_t SCRATCH_BYTES = 162*MB;

__device__ __align__(256) unsigned char g_scratch[SCRATCH_BYTES];

// ---------------- reductions ----------------
__device__ __forceinline__ float blk_reduce_sum(float v, float* red) {
    int tid = threadIdx.x;
    red[tid] = v; __syncthreads();
    #pragma unroll
    for (int s = 128; s > 0; s >>= 1) {
        if (tid < s) red[tid] += red[tid + s];
        __syncthreads();
    }
    float r = red[0]; __syncthreads();
    return r;
}

__device__ __forceinline__ float blk_reduce_max(float v, float* red) {
    int tid = threadIdx.x;
    red[tid] = v; __syncthreads();
    #pragma unroll
    for (int s = 128; s > 0; s >>= 1) {
        if (tid < s) red[tid] = fmaxf(red[tid], red[tid + s]);
        __syncthreads();
    }
    float r = red[0]; __syncthreads();
    return r;
}

// ---------------- weight quantization (4x float4 ILP) ----------------
__device__ __forceinline__ float abs4(float4 v) {
    return fabsf(v.x) + fabsf(v.y) + fabsf(v.z) + fabsf(v.w);
}

__global__ void absmean_partial(const float* __restrict__ w, float* __restrict__ part, int len4) {
    __shared__ float red[256];
    const float4* p = (const float4*)w + (size_t)blockIdx.y * len4;
    int i = blockIdx.x * 1024 + threadIdx.x;
    float4 v0 = p[i], v1 = p[i + 256], v2 = p[i + 512], v3 = p[i + 768];
    float s = (abs4(v0) + abs4(v1)) + (abs4(v2) + abs4(v3));
    s = blk_reduce_sum(s, red);
    if (threadIdx.x == 0) part[(size_t)blockIdx.y * gridDim.x + blockIdx.x] = s;
}

__global__ void absmean4(const float* __restrict__ w0, const float* __restrict__ w1,
                         const float* __restrict__ w2, const float* __restrict__ w3,
                         float* __restrict__ part, int len4) {
    __shared__ float red[256];
    int sl = blockIdx.y;
    const float* p = sl == 0 ? w0 : sl == 1 ? w1 : sl == 2 ? w2 : w3;
    const float4* p4 = (const float4*)p;
    int i = blockIdx.x * 1024 + threadIdx.x;
    float4 v0 = p4[i], v1 = p4[i + 256], v2 = p4[i + 512], v3 = p4[i + 768];
    float s = (abs4(v0) + abs4(v1)) + (abs4(v2) + abs4(v3));
    s = blk_reduce_sum(s, red);
    if (threadIdx.x == 0) part[(size_t)sl * gridDim.x + blockIdx.x] = s;
}

__global__ void finalize_wscale(const float* __restrict__ part, float* __restrict__ wsc,
                                int i0, int n) {
    int i = i0 + threadIdx.x;
    if (threadIdx.x >= n) return;
    float s = 0.f;
    for (int j = 0; j < 256; j++) s += part[i * 256 + j];
    wsc[i] = fmaxf(s * (1.0f / (1024.f * 1024.f)), 1e-5f);
}

__device__ __forceinline__ char quant_tern(float v, float s) {
    float q = rintf(v * s);
    q = fminf(fmaxf(q, -1.f), 1.f);
    return (char)(int)q;
}

__device__ __forceinline__ char4 qt4(float4 v, float s) {
    char4 o;
    o.x = quant_tern(v.x, s); o.y = quant_tern(v.y, s);
    o.z = quant_tern(v.z, s); o.w = quant_tern(v.w, s);
    return o;
}

__global__ void quantize_w(const float* __restrict__ w, int8_t* __restrict__ wq,
                           const float* __restrict__ wsc, int widx0, int len4) {
    int slice = blockIdx.y;
    float s = 1.0f / wsc[widx0 + slice];
    const float4* p = (const float4*)w + (size_t)slice * len4;
    char4* q = (char4*)wq + (size_t)slice * len4;
    int i = blockIdx.x * 1024 + threadIdx.x;
    float4 v0 = p[i], v1 = p[i + 256], v2 = p[i + 512], v3 = p[i + 768];
    q[i] = qt4(v0, s); q[i + 256] = qt4(v1, s);
    q[i + 512] = qt4(v2, s); q[i + 768] = qt4(v3, s);
}

__global__ void quantizeF4(const float* __restrict__ w0, const float* __restrict__ w1,
                           const float* __restrict__ w2, const float* __restrict__ w3,
                           int8_t* __restrict__ wq, const float* __restrict__ part,
                           float* __restrict__ wsc, int len4) {
    __shared__ float red[256];
    int sl = blockIdx.y;
    int tid = threadIdx.x;
    float total = blk_reduce_sum(part[sl * 256 + tid], red);
    float mean = fmaxf(total * (1.0f / (1024.f * 1024.f)), 1e-5f);
    if (blockIdx.x == 0 && tid == 0) wsc[sl] = mean;
    float s = 1.0f / mean;
    const float* p = sl == 0 ? w0 : sl == 1 ? w1 : sl == 2 ? w2 : w3;
    const float4* p4 = (const float4*)p;
    char4* q = (char4*)wq + (size_t)sl * len4;
    int i = blockIdx.x * 1024 + tid;
    float4 v0 = p4[i], v1 = p4[i + 256], v2 = p4[i + 512], v3 = p4[i + 768];
    q[i] = qt4(v0, s); q[i + 256] = qt4(v1, s);
    q[i + 512] = qt4(v2, s); q[i + 768] = qt4(v3, s);
}

// ---------------- activation rmsnorm + quant ----------------
__global__ void rmsnorm_quant(const float* __restrict__ x, const float* __restrict__ lnw,
                              int8_t* __restrict__ xq, float* __restrict__ ainv) {
    __shared__ float red[256];
    __shared__ float xs[CH];
    int t = blockIdx.x, tid = threadIdx.x;
    const float* xr = x + (size_t)t * CH;
    float v[4]; float ss = 0.f;
    #pragma unroll
    for (int i = 0; i < 4; i++) { v[i] = xr[tid + i * 256]; ss += v[i] * v[i]; }
    ss = blk_reduce_sum(ss, red);
    float r = rsqrtf(ss * (1.0f / CH) + 1e-5f);
    float amax = 0.f;
    #pragma unroll
    for (int i = 0; i < 4; i++) {
        float xn = v[i] * r * lnw[tid + i * 256];
        xs[tid + i * 256] = xn;
        amax = fmaxf(amax, fabsf(xn));
    }
    amax = blk_reduce_max(amax, red);
    float m = fmaxf(amax, 1e-5f);
    float s = 127.f / m;
    #pragma unroll
    for (int i = 0; i < 4; i++) {
        float qv = fminf(fmaxf(rintf(xs[tid + i * 256] * s), -128.f), 127.f);
        xq[(size_t)t * CH + tid + i * 256] = (int8_t)(int)qv;
    }
    if (tid == 0) ainv[t] = m * (1.0f / 127.f);
}

__global__ void act_quant_rows(const float* __restrict__ x, int8_t* __restrict__ xq,
                               float* __restrict__ ainv) {
    __shared__ float red[256];
    int t = blockIdx.x, tid = threadIdx.x;
    const float* xr = x + (size_t)t * CH;
    float v[4]; float amax = 0.f;
    #pragma unroll
    for (int i = 0; i < 4; i++) { v[i] = xr[tid + i * 256]; amax = fmaxf(amax, fabsf(v[i])); }
    amax = blk_reduce_max(amax, red);
    float m = fmaxf(amax, 1e-5f);
    float s = 127.f / m;
    #pragma unroll
    for (int i = 0; i < 4; i++) {
        float qv = fminf(fmaxf(rintf(v[i] * s), -128.f), 127.f);
        xq[(size_t)t * CH + tid + i * 256] = (int8_t)(int)qv;
    }
    if (tid == 0) ainv[t] = m * (1.0f / 127.f);
}

__global__ void rmsnorm2_router(const float* __restrict__ x, const float* __restrict__ lnw,
                                const float* __restrict__ rw, int8_t* __restrict__ xq,
                                float* __restrict__ ainv, int* __restrict__ idx,
                                int* __restrict__ counts) {
    __shared__ float red[256];
    __shared__ float xs[CH];
    __shared__ float logits[CE];
    int t = blockIdx.x, tid = threadIdx.x;
    const float* xr = x + (size_t)t * CH;
    float v[4]; float ss = 0.f;
    #pragma unroll
    for (int i = 0; i < 4; i++) { v[i] = xr[tid + i * 256]; ss += v[i] * v[i]; }
    ss = blk_reduce_sum(ss, red);
    float r = rsqrtf(ss * (1.0f / CH) + 1e-5f);
    float amax = 0.f;
    #pragma unroll
    for (int i = 0; i < 4; i++) {
        float xn = v[i] * r * lnw[tid + i * 256];
        xs[tid + i * 256] = xn;
        amax = fmaxf(amax, fabsf(xn));
    }
    amax = blk_reduce_max(amax, red);
    float m = fmaxf(amax, 1e-5f);
    float s = 127.f / m;
    #pragma unroll
    for (int i = 0; i < 4; i++) {
        float qv = fminf(fmaxf(rintf(xs[tid + i * 256] * s), -128.f), 127.f);
        xq[(size_t)t * CH + tid + i * 256] = (int8_t)(int)qv;
    }
    if (tid == 0) ainv[t] = m * (1.0f / 127.f);
    __syncthreads();

    int w = tid >> 5, lane = tid & 31;
    float acc = 0.f;
    for (int h = lane; h < CH; h += 32) acc += xs[h] * rw[w * CH + h];
    #pragma unroll
    for (int o = 16; o > 0; o >>= 1) acc += __shfl_down_sync(0xffffffffu, acc, o);
    if (lane == 0) logits[w] = acc;
    __syncthreads();
    if (tid == 0) {
        float best = logits[0]; int bi = 0;
        #pragma unroll
        for (int e = 1; e < CE; e++) if (logits[e] > best) { best = logits[e]; bi = e; }
        idx[t] = bi;
        atomicAdd(&counts[bi], 1);
    }
}

__global__ void zero_ints(int* __restrict__ counts, int* __restrict__ cursor) {
    if (threadIdx.x < CE) { counts[threadIdx.x] = 0; cursor[threadIdx.x] = 0; }
}

__global__ void build_offsets(const int* __restrict__ counts, int* __restrict__ seg) {
    if (threadIdx.x == 0) {
        int a = 0;
        for (int e = 0; e < CE; e++) { seg[e] = a; a += counts[e]; }
        seg[CE] = a;
    }
}

__global__ void scatter_tokens(const int* __restrict__ idx, const int* __restrict__ seg,
                               int* __restrict__ cursor, int* __restrict__ perm) {
    int t = blockIdx.x * 256 + threadIdx.x;
    if (t >= CT) return;
    int e = idx[t];
    int p = atomicAdd(&cursor[e], 1);
    perm[seg[e] + p] = t;
}

// ---------------- int8 x ternary GEMM: mma.sync + ldmatrix + cp.async (3-stage) ----------------
__device__ __forceinline__ void mma_s8(int* c, const int* a, const int* b) {
    asm volatile(
        "mma.sync.aligned.m16n8k32.row.col.s32.s8.s8.s32 "
        "{%0,%1,%2,%3}, {%4,%5,%6,%7}, {%8,%9}, {%0,%1,%2,%3};"
        : "+r"(c[0]), "+r"(c[1]), "+r"(c[2]), "+r"(c[3])
        : "r"(a[0]), "r"(a[1]), "r"(a[2]), "r"(a[3]), "r"(b[0]), "r"(b[1]));
}

#define LDMX4(r, addr) \
    asm volatile("ldmatrix.sync.aligned.m8n8.x4.shared.b16 {%0,%1,%2,%3}, [%4];" \
        : "=r"((r)[0]), "=r"((r)[1]), "=r"((r)[2]), "=r"((r)[3]) : "r"(addr))

#define CPA16(dst, src) \
    asm volatile("cp.async.cg.shared.global [%0], [%1], 16;" :: "r"(dst), "l"(src))
#define CPCOMMIT() asm volatile("cp.async.commit_group;" ::: "memory")

static constexpr int A_STG = 128 * 80;   // bytes per A stage
static constexpr int B_STG = 64 * 80;

template<int MODE>
__global__ void __launch_bounds__(256) gemm_mma(
        const int8_t* __restrict__ A, const int8_t* __restrict__ Bw,
        float* __restrict__ Out, __nv_bfloat16* __restrict__ OutB,
        const float* __restrict__ ascale,
        const float* __restrict__ wscale,
        const float* __restrict__ resid,
        const int* __restrict__ perm,
        const int* __restrict__ seg) {
    int n0 = blockIdx.x * 64;
    int m0 = blockIdx.y * 128;
    int z = blockIdx.z;
    int e = (MODE == 2) ? (z & 7) : z;

    int off = 0, cnt = CT;
    if (MODE >= 2) {
        off = seg[e];
        cnt = seg[e + 1] - off;
        if (m0 >= cnt) return;
    }

    const int8_t* Bz = Bw;
    if (MODE == 0) Bz = Bw + (size_t)z * (CH * CH);
    if (MODE >= 2) Bz = Bw + (size_t)z * ((size_t)CD * CH);
    const int8_t* brow0 = Bz + (size_t)n0 * 1024;

    __shared__ __align__(16) int8_t As[3][128][80];
    __shared__ __align__(16) int8_t Bs[3][64][80];
    __shared__ const int8_t* aptr[128];
    __shared__ float rowsc[128];
    __shared__ int dstrow[128];

    int tid = threadIdx.x;
    if (tid < 128) {
        int r = m0 + tid;
        if (MODE <= 1) {
            aptr[tid] = A + (size_t)r * 1024;
            rowsc[tid] = ascale[r];
        } else if (MODE == 2) {
            int rr = r < cnt - 1 ? r : cnt - 1;
            int tok = perm[off + rr];
            aptr[tid] = A + (size_t)tok * 1024;
            rowsc[tid] = ascale[tok];
            dstrow[tid] = off + r;
        } else {
            int rr = r < cnt - 1 ? r : cnt - 1;
            aptr[tid] = A + (size_t)(off + rr) * 1024;
            rowsc[tid] = ascale[off + rr];
            dstrow[tid] = perm[off + rr];
        }
    }
    __syncthreads();

    // staging assignments: A 128 rows x 64B/stage, 2 thr/row (32B each); B 64 rows, 4 thr/row (16B each)
    int ar = tid >> 1, ao = (tid & 1) * 32;
    int brr = tid >> 2, bo = (tid & 3) * 16;
    const int8_t* pA = aptr[ar];
    const int8_t* pB = brow0 + (size_t)brr * 1024;

    uint32_t As_u = (uint32_t)__cvta_generic_to_shared(&As[0][0][0]);
    uint32_t Bs_u = (uint32_t)__cvta_generic_to_shared(&Bs[0][0][0]);
    uint32_t aSt = As_u + ar * 80 + ao;
    uint32_t bSt = Bs_u + brr * 80 + bo;

    int w = tid >> 5, lane = tid & 31;
    int warpM = w & 3, warpN = w >> 2;
    int gid = lane >> 2, tig = lane & 3;

    // ldmatrix fragment base addresses
    // A: lanes 0-7 rows +0..7 @kb, 8-15 rows +8..15 @kb, 16-23 rows +0..7 @kb+16, 24-31 rows +8..15 @kb+16
    int rowA_ld = warpM * 32 + (lane & 7) + ((lane >> 3) & 1) * 8;
    uint32_t aF = As_u + rowA_ld * 80 + (lane >> 4) * 16;
    // B: lanes 0-7 rows +0..7 @kb, 8-15 rows +0..7 @kb+16, 16-23 rows +8..15 @kb, 24-31 rows +8..15 @kb+16
    int rowB_ld = warpN * 32 + (lane & 7) + (lane >> 4) * 8;
    uint32_t bF = Bs_u + rowB_ld * 80 + ((lane >> 3) & 1) * 16;

    int c[2][4][4];
    #pragma unroll
    for (int i = 0; i < 2; i++)
        #pragma unroll
        for (int j = 0; j < 4; j++)
            #pragma unroll
            for (int k = 0; k < 4; k++) c[i][j][k] = 0;

    // prologue: stages 0 and 1
    #pragma unroll
    for (int s = 0; s < 2; s++) {
        uint32_t aD = aSt + s * A_STG;
        CPA16(aD, pA + s * 64 + ao);
        CPA16(aD + 16, pA + s * 64 + ao + 16);
        CPA16(bSt + s * B_STG, pB + s * 64 + bo);
        CPCOMMIT();
    }

    #pragma unroll 1
    for (int kt = 0; kt < 16; kt++) {
        if (kt < 15) {
            asm volatile("cp.async.wait_group 1;" ::: "memory");
        } else {
            asm volatile("cp.async.wait_group 0;" ::: "memory");
        }
        __syncthreads();
        // issue stage kt+2 (buffer (kt+2)%3 is free: computed at kt-1)
        if (kt < 14) {
            int s = kt + 2;
            int b = s - (s >= 3 ? 3 : 0); b = s % 3;
            uint32_t aD = aSt + b * A_STG;
            CPA16(aD, pA + s * 64 + ao);
            CPA16(aD + 16, pA + s * 64 + ao + 16);
            CPA16(bSt + b * B_STG, pB + s * 64 + bo);
            CPCOMMIT();
        }
        int stg = kt % 3;
        uint32_t aBase = aF + stg * A_STG;
        uint32_t bBase = bF + stg * B_STG;
        #pragma unroll
        for (int ks = 0; ks < 2; ks++) {
            int a0[4], a1[4], b01[4], b23[4];
            LDMX4(a0, aBase + ks * 32);
            LDMX4(a1, aBase + 16 * 80 + ks * 32);
            LDMX4(b01, bBase + ks * 32);
            LDMX4(b23, bBase + 16 * 80 + ks * 32);
            mma_s8(c[0][0], a0, b01 + 0);
            mma_s8(c[0][1], a0, b01 + 2);
            mma_s8(c[0][2], a0, b23 + 0);
            mma_s8(c[0][3], a0, b23 + 2);
            mma_s8(c[1][0], a1, b01 + 0);
            mma_s8(c[1][1], a1, b01 + 2);
            mma_s8(c[1][2], a1, b23 + 0);
            mma_s8(c[1][3], a1, b23 + 2);
        }
        __syncthreads();
    }

    float wS = wscale[(MODE == 0 || MODE >= 2) ? z : 0];

    #pragma unroll
    for (int wm = 0; wm < 2; wm++) {
        int r0 = warpM * 32 + wm * 16 + gid;
        int r1 = r0 + 8;
        float av0 = rowsc[r0] * wS;
        float av1 = rowsc[r1] * wS;
        #pragma unroll
        for (int nt = 0; nt < 4; nt++) {
            int colL = warpN * 32 + nt * 8 + tig * 2;
            int* cc = c[wm][nt];
            if (MODE == 0) {
                int nh = n0 >> 6;
                int gr0 = m0 + r0, gr1 = m0 + r1;
                int b0 = gr0 / CS, sr0 = gr0 % CS;
                int b1 = gr1 / CS, sr1 = gr1 % CS;
                __nv_bfloat16* base = OutB + (size_t)z * ((size_t)CT * CH);
                __nv_bfloat162 o0 = {__float2bfloat16(cc[0] * av0), __float2bfloat16(cc[1] * av0)};
                __nv_bfloat162 o1 = {__float2bfloat16(cc[2] * av1), __float2bfloat16(cc[3] * av1)};
                *(__nv_bfloat162*)(base + (((size_t)b0 * CNH + nh) * CS + sr0) * CHD + colL) = o0;
                *(__nv_bfloat162*)(base + (((size_t)b1 * CNH + nh) * CS + sr1) * CHD + colL) = o1;
            } else if (MODE == 1) {
                size_t rb0 = (size_t)(m0 + r0) * CH + n0 + colL;
                size_t rb1 = (size_t)(m0 + r1) * CH + n0 + colL;
                float2 rv0 = *(const float2*)(resid + rb0);
                float2 rv1 = *(const float2*)(resid + rb1);
                float2 o0 = {rv0.x + cc[0] * av0, rv0.y + cc[1] * av0};
                float2 o1 = {rv1.x + cc[2] * av1, rv1.y + cc[3] * av1};
                *(float2*)(Out + rb0) = o0;
                *(float2*)(Out + rb1) = o1;
            } else if (MODE == 2) {
                size_t half = (size_t)(z >> 3) * ((size_t)CT * CD);
                if (m0 + r0 < cnt) {
                    size_t rb = half + (size_t)dstrow[r0] * CD + n0 + colL;
                    float2 o = {cc[0] * av0, cc[1] * av0};
                    *(float2*)(Out + rb) = o;
                }
                if (m0 + r1 < cnt) {
                    size_t rb = half + (size_t)dstrow[r1] * CD + n0 + colL;
                    float2 o = {cc[2] * av1, cc[3] * av1};
                    *(float2*)(Out + rb) = o;
                }
            } else {
                if (m0 + r0 < cnt) {
                    size_t rb = (size_t)dstrow[r0] * CH + n0 + colL;
                    float2 rv = *(const float2*)(resid + rb);
                    float2 o = {rv.x + cc[0] * av0, rv.y + cc[1] * av0};
                    *(float2*)(Out + rb) = o;
                }
                if (m0 + r1 < cnt) {
                    size_t rb = (size_t)dstrow[r1] * CH + n0 + colL;
                    float2 rv = *(const float2*)(resid + rb);
                    float2 o = {rv.x + cc[2] * av1, rv.y + cc[3] * av1};
                    *(float2*)(Out + rb) = o;
                }
            }
        }
    }
}

// ---------------- attention: FA2-style, register-resident ----------------
__device__ __forceinline__ void mma_bf16(float* c, const uint32_t* a, uint32_t b0, uint32_t b1) {
    asm volatile(
        "mma.sync.aligned.m16n8k16.row.col.f32.bf16.bf16.f32 "
        "{%0,%1,%2,%3}, {%4,%5,%6,%7}, {%8,%9}, {%0,%1,%2,%3};"
        : "+f"(c[0]), "+f"(c[1]), "+f"(c[2]), "+f"(c[3])
        : "r"(a[0]), "r"(a[1]), "r"(a[2]), "r"(a[3]), "r"(b0), "r"(b1));
}

__device__ __forceinline__ void ldmx4t(uint32_t& r0, uint32_t& r1, uint32_t& r2, uint32_t& r3,
                                       uint32_t addr) {
    asm volatile("ldmatrix.sync.aligned.m8n8.x4.trans.shared.b16 {%0,%1,%2,%3}, [%4];"
        : "=r"(r0), "=r"(r1), "=r"(r2), "=r"(r3) : "r"(addr));
}

__device__ __forceinline__ uint32_t pack_bf2(float a, float b) {
    __nv_bfloat162 t = __floats2bfloat162_rn(a, b);
    return *(uint32_t*)&t;
}

static constexpr int KLD = 72;
// scores scaled by 0.125 * log2(e) so probabilities use exp2 directly
#define ASCL 0.18033688011112042f

__global__ void __launch_bounds__(128) attn_fa2(
        const __nv_bfloat16* __restrict__ Qg, const __nv_bfloat16* __restrict__ Kg,
        const __nv_bfloat16* __restrict__ Vg, float* __restrict__ Hout) {
    __shared__ __align__(16) __nv_bfloat16 Ks[64][KLD];
    __shared__ __align__(16) __nv_bfloat16 Vs[64][KLD];

    int bh = blockIdx.y;
    int q0 = blockIdx.x * 64;
    const __nv_bfloat16* Qb = Qg + (size_t)bh * CS * CHD;
    const __nv_bfloat16* Kb = Kg + (size_t)bh * CS * CHD;
    const __nv_bfloat16* Vb = Vg + (size_t)bh * CS * CHD;

    int tid = threadIdx.x;
    int w = tid >> 5, lane = tid & 31;
    int gid = lane >> 2, tig = lane & 3;

    int qr0 = q0 + w * 16 + gid;
    int qr1 = qr0 + 8;

    uint32_t qf[4][4];
    #pragma unroll
    for (int k = 0; k < 4; k++) {
        const __nv_bfloat16* p0 = Qb + (size_t)qr0 * CHD + k * 16 + 2 * tig;
        const __nv_bfloat16* p1 = Qb + (size_t)qr1 * CHD + k * 16 + 2 * tig;
        qf[k][0] = *(const uint32_t*)p0;
        qf[k][1] = *(const uint32_t*)p1;
        qf[k][2] = *(const uint32_t*)(p0 + 8);
        qf[k][3] = *(const uint32_t*)(p1 + 8);
    }

    float o[8][4];
    #pragma unroll
    for (int nt = 0; nt < 8; nt++)
        #pragma unroll
        for (int j = 0; j < 4; j++) o[nt][j] = 0.f;
    float m0 = -INFINITY, m1 = -INFINITY, l0 = 0.f, l1 = 0.f;

    int nkt = blockIdx.x + 1;
    for (int kt = 0; kt < nkt; kt++) {
        int k0 = kt * 64;
        __syncthreads();
        for (int i = tid; i < 512; i += 128) {
            int row = i >> 3, c8 = (i & 7) * 8;
            *(uint4*)&Ks[row][c8] = *(const uint4*)(Kb + (size_t)(k0 + row) * CHD + c8);
            *(uint4*)&Vs[row][c8] = *(const uint4*)(Vb + (size_t)(k0 + row) * CHD + c8);
        }
        __syncthreads();

        float s[8][4];
        #pragma unroll
        for (int nt = 0; nt < 8; nt++)
            #pragma unroll
            for (int j = 0; j < 4; j++) s[nt][j] = 0.f;
        #pragma unroll
        for (int k = 0; k < 4; k++) {
            #pragma unroll
            for (int nt = 0; nt < 8; nt++) {
                uint32_t b0 = *(const uint32_t*)&Ks[nt * 8 + gid][k * 16 + 2 * tig];
                uint32_t b1 = *(const uint32_t*)&Ks[nt * 8 + gid][k * 16 + 8 + 2 * tig];
                mma_bf16(s[nt], qf[k], b0, b1);
            }
        }

        bool diag = (kt == blockIdx.x);
        float rmax0 = -INFINITY, rmax1 = -INFINITY;
        #pragma unroll
        for (int nt = 0; nt < 8; nt++) {
            int cg = k0 + nt * 8 + 2 * tig;
            #pragma unroll
            for (int j = 0; j < 2; j++) {
                float v0 = s[nt][j] * ASCL;
                float v1 = s[nt][2 + j] * ASCL;
                if (diag && cg + j > qr0) v0 = -INFINITY;
                if (diag && cg + j > qr1) v1 = -INFINITY;
                s[nt][j] = v0; s[nt][2 + j] = v1;
                rmax0 = fmaxf(rmax0, v0); rmax1 = fmaxf(rmax1, v1);
            }
        }
        rmax0 = fmaxf(rmax0, __shfl_xor_sync(0xffffffffu, rmax0, 1));
        rmax0 = fmaxf(rmax0, __shfl_xor_sync(0xffffffffu, rmax0, 2));
        rmax1 = fmaxf(rmax1, __shfl_xor_sync(0xffffffffu, rmax1, 1));
        rmax1 = fmaxf(rmax1, __shfl_xor_sync(0xffffffffu, rmax1, 2));

        float mn0 = fmaxf(m0, rmax0), mn1 = fmaxf(m1, rmax1);
        float sum0 = 0.f, sum1 = 0.f;
        #pragma unroll
        for (int nt = 0; nt < 8; nt++) {
            s[nt][0] = exp2f(s[nt][0] - mn0);
            s[nt][1] = exp2f(s[nt][1] - mn0);
            s[nt][2] = exp2f(s[nt][2] - mn1);
            s[nt][3] = exp2f(s[nt][3] - mn1);
            sum0 += s[nt][0] + s[nt][1];
            sum1 += s[nt][2] + s[nt][3];
        }
        sum0 += __shfl_xor_sync(0xffffffffu, sum0, 1);
        sum0 += __shfl_xor_sync(0xffffffffu, sum0, 2);
        sum1 += __shfl_xor_sync(0xffffffffu, sum1, 1);
        sum1 += __shfl_xor_sync(0xffffffffu, sum1, 2);

        float rs0 = exp2f(m0 - mn0), rs1 = exp2f(m1 - mn1);
        m0 = mn0; m1 = mn1;
        l0 = l0 * rs0 + sum0;
        l1 = l1 * rs1 + sum1;
        #pragma unroll
        for (int nt = 0; nt < 8; nt++) {
            o[nt][0] *= rs0; o[nt][1] *= rs0;
            o[nt][2] *= rs1; o[nt][3] *= rs1;
        }

        #pragma unroll
        for (int kb = 0; kb < 4; kb++) {
            uint32_t pf[4];
            pf[0] = pack_bf2(s[2 * kb][0], s[2 * kb][1]);
            pf[1] = pack_bf2(s[2 * kb][2], s[2 * kb][3]);
            pf[2] = pack_bf2(s[2 * kb + 1][0], s[2 * kb + 1][1]);
            pf[3] = pack_bf2(s[2 * kb + 1][2], s[2 * kb + 1][3]);
            #pragma unroll
            for (int nb = 0; nb < 4; nb++) {
                uint32_t v0, v1, v2, v3;
                uint32_t addr = (uint32_t)__cvta_generic_to_shared(
                    &Vs[kb * 16 + (lane & 15)][nb * 16 + ((lane >> 4) << 3)]);
                ldmx4t(v0, v1, v2, v3, addr);
                mma_bf16(o[2 * nb], pf, v0, v1);
                mma_bf16(o[2 * nb + 1], pf, v2, v3);
            }
        }
    }

    float inv0 = 1.0f / l0, inv1 = 1.0f / l1;
    int b = bh / CNH, nh = bh % CNH;
    #pragma unroll
    for (int nt = 0; nt < 8; nt++) {
        int col = nt * 8 + 2 * tig;
        float2 w0v = {o[nt][0] * inv0, o[nt][1] * inv0};
        float2 w1v = {o[nt][2] * inv1, o[nt][3] * inv1};
        *(float2*)(Hout + (((size_t)b * CS + qr0) * CNH + nh) * CHD + col) = w0v;
        *(float2*)(Hout + (((size_t)b * CS + qr1) * CNH + nh) * CHD + col) = w1v;
    }
}

// ---------------- MoE elementwise: hh = relu(g)^2 * u, then act_quant ----------------
__global__ void hh_quant(const float* __restrict__ g, const float* __restrict__ u,
                         int8_t* __restrict__ hq, float* __restrict__ hs) {
    __shared__ float red[256];
    __shared__ float hb[CD];
    int slot = blockIdx.x, tid = threadIdx.x;
    float amax = 0.f;
    #pragma unroll
    for (int i = 0; i < 4; i++) {
        int k = tid + i * 256;
        float gv = g[(size_t)slot * CD + k];
        float uv = u[(size_t)slot * CD + k];
        float rl = fmaxf(gv, 0.f);
        float h = rl * rl * uv;
        hb[k] = h;
        amax = fmaxf(amax, fabsf(h));
    }
    amax = blk_reduce_max(amax, red);
    float m = fmaxf(amax, 1e-5f);
    float s = 127.f / m;
    #pragma unroll
    for (int i = 0; i < 4; i++) {
        int k = tid + i * 256;
        float qv = fminf(fmaxf(rintf(hb[k] * s), -128.f), 127.f);
        hq[(size_t)slot * CD + k] = (int8_t)(int)qv;
    }
    if (tid == 0) hs[slot] = m * (1.0f / 127.f);
}

// ---------------- launch (fork-join dual stream) ----------------
extern "C" void kernel_launch(void* const* d_in, const int* in_sizes, int n_in,
                              void* d_out, int out_size) {
    const float* x        = (const float*)d_in[0];
    const float* q_w      = (const float*)d_in[1];
    const float* k_w      = (const float*)d_in[2];
    const float* v_w      = (const float*)d_in[3];
    const float* o_w      = (const float*)d_in[4];
    const float* ln1_w    = (const float*)d_in[5];
    const float* ln2_w    = (const float*)d_in[6];
    const float* router_w = (const float*)d_in[7];
    const float* gate_w   = (const float*)d_in[8];
    const float* up_w     = (const float*)d_in[9];
    const float* down_w   = (const float*)d_in[10];

    unsigned char* base = nullptr;
    cudaGetSymbolAddress((void**)&base, g_scratch);

    int8_t* wq_attn = (int8_t*)(base + OFF_WQ_ATTN);
    int8_t* wq_gate = (int8_t*)(base + OFF_WQ_GATE);
    int8_t* wq_up   = (int8_t*)(base + OFF_WQ_UP);
    int8_t* wq_down = (int8_t*)(base + OFF_WQ_DOWN);
    float*  wsc     = (float*)(base + OFF_WSCALE);
    float*  part    = (float*)(base + OFF_PART);
    int8_t* xq1     = (int8_t*)(base + OFF_XQ1);
    float*  a1s     = (float*)(base + OFF_A1S);
    __nv_bfloat16* qkvb = (__nv_bfloat16*)(base + OFF_QKV);
    float*  hb      = (float*)(base + OFF_HB);
    int8_t* hqa     = (int8_t*)(base + OFF_HQA);
    float*  hsa     = (float*)(base + OFF_HSA);
    float*  x2      = (float*)(base + OFF_X2);
    int8_t* xq2     = (int8_t*)(base + OFF_XQ2);
    float*  a2s     = (float*)(base + OFF_A2S);
    int*    idx     = (int*)(base + OFF_IDX);
    int*    cnt     = (int*)(base + OFF_CNT);
    int*    seg     = (int*)(base + OFF_SEG);
    int*    cur     = (int*)(base + OFF_CUR);
    int*    perm    = (int*)(base + OFF_PERM);
    float*  gb      = (float*)(base + OFF_GB);
    float*  ub      = (float*)(base + OFF_UB);
    int8_t* hqm     = (int8_t*)(base + OFF_HQM);
    float*  hsm     = (float*)(base + OFF_HSM);
    float*  out     = (float*)d_out;

    const int LEN4 = (CH * CH) / 4;

    cudaStream_t s2;
    cudaStreamCreateWithFlags(&s2, cudaStreamNonBlocking);
    cudaEvent_t evFork, evB, evJoin;
    cudaEventCreateWithFlags(&evFork, cudaEventDisableTiming);
    cudaEventCreateWithFlags(&evB, cudaEventDisableTiming);
    cudaEventCreateWithFlags(&evJoin, cudaEventDisableTiming);

    cudaEventRecord(evFork, 0);
    cudaStreamWaitEvent(s2, evFork, 0);

    // ---- side stream: activation quant, then MoE weight quant ----
    rmsnorm_quant<<<CT, 256, 0, s2>>>(x, ln1_w, xq1, a1s);
    cudaEventRecord(evB, s2);
    absmean_partial<<<dim3(256, 8), 256, 0, s2>>>(gate_w, part + 4 * 256, LEN4);
    absmean_partial<<<dim3(256, 8), 256, 0, s2>>>(up_w,   part + 12 * 256, LEN4);
    absmean_partial<<<dim3(256, 8), 256, 0, s2>>>(down_w, part + 20 * 256, LEN4);
    finalize_wscale<<<1, 32, 0, s2>>>(part, wsc, 4, 24);
    quantize_w<<<dim3(256, 8), 256, 0, s2>>>(gate_w, wq_gate, wsc, 4, LEN4);
    quantize_w<<<dim3(256, 8), 256, 0, s2>>>(up_w,   wq_up,   wsc, 12, LEN4);
    quantize_w<<<dim3(256, 8), 256, 0, s2>>>(down_w, wq_down, wsc, 20, LEN4);
    cudaEventRecord(evJoin, s2);

    // ---- main stream: attention weights + attention path ----
    zero_ints<<<1, 32>>>(cnt, cur);
    absmean4<<<dim3(256, 4), 256>>>(q_w, k_w, v_w, o_w, part, LEN4);
    quantizeF4<<<dim3(256, 4), 256>>>(q_w, k_w, v_w, o_w, wq_attn, part, wsc, LEN4);
    cudaStreamWaitEvent(0, evB, 0);
    gemm_mma<0><<<dim3(16, 32, 3), 256>>>(xq1, wq_attn, nullptr, qkvb, a1s, wsc, nullptr, nullptr, nullptr);

    attn_fa2<<<dim3(32, CB * CNH), 128>>>(
        qkvb, qkvb + (size_t)CT * CH, qkvb + 2 * (size_t)CT * CH, hb);

    // ---- o-proj + residual ----
    act_quant_rows<<<CT, 256>>>(hb, hqa, hsa);
    gemm_mma<1><<<dim3(16, 32, 1), 256>>>(hqa, wq_attn + 3 * (CH * CH), x2, nullptr, hsa, wsc + 3, x, nullptr, nullptr);

    // ---- MoE ----
    rmsnorm2_router<<<CT, 256>>>(x2, ln2_w, router_w, xq2, a2s, idx, cnt);
    build_offsets<<<1, 1>>>(cnt, seg);
    scatter_tokens<<<16, 256>>>(idx, seg, cur, perm);

    cudaStreamWaitEvent(0, evJoin, 0);
    gemm_mma<2><<<dim3(16, 32, 16), 256>>>(xq2, wq_gate, gb, nullptr, a2s, wsc + 4, nullptr, perm, seg);
    hh_quant<<<CT, 256>>>(gb, ub, hqm, hsm);
    gemm_mma<3><<<dim3(16, 32, 8), 256>>>(hqm, wq_down, out, nullptr, hsm, wsc + 20, x2, perm, seg);
}

// round 13
// speedup vs baseline: 2.6384x; 1.0422x over previous
#include <cuda_runtime.h>
#include <cuda_bf16.h>
#include <math.h>
#include <stdint.h>

#define CB 2
#define CS 2048
#define CH 1024
#define CNH 16
#define CHD 64
#define CE 8
#define CD 1024
#define CT (CB*CS)

#define MB (1024ull*1024ull)

// ---------------- scratch layout ----------------
static constexpr size_t OFF_WQ_ATTN = 0;
static constexpr size_t OFF_WQ_GATE = 4*MB;
static constexpr size_t OFF_WQ_UP   = 12*MB;
static constexpr size_t OFF_WQ_DOWN = 20*MB;
static constexpr size_t OFF_WSCALE  = 28*MB;
static constexpr size_t OFF_PART    = 28*MB + 4096;
static constexpr size_t OFF_XQ1     = 29*MB;
static constexpr size_t OFF_A1S     = 33*MB;
static constexpr size_t OFF_QKV     = 34*MB;
static constexpr size_t OFF_HB      = 82*MB;
static constexpr size_t OFF_HQA     = 98*MB;
static constexpr size_t OFF_HSA     = 102*MB;
static constexpr size_t OFF_X2      = 103*MB;
static constexpr size_t OFF_XQ2     = 119*MB;
static constexpr size_t OFF_A2S     = 123*MB;
static constexpr size_t OFF_IDX     = 123*MB + 64*1024;
static constexpr size_t OFF_CNT     = 123*MB + 128*1024;
static constexpr size_t OFF_SEG     = 123*MB + 129*1024;
static constexpr size_t OFF_CUR     = 123*MB + 130*1024;
static constexpr size_t OFF_PERM    = 124*MB;
static constexpr size_t OFF_GB      = 125*MB;
static constexpr size_t OFF_UB      = 141*MB;
static constexpr size_t OFF_HQM     = 157*MB;
static constexpr size_t OFF_HSM     = 161*MB;
static constexpr size_t SCRATCH_BYTES = 162*MB;

__device__ __align__(256) unsigned char g_scratch[SCRATCH_BYTES];

// ---------------- reductions ----------------
__device__ __forceinline__ float blk_reduce_sum(float v, float* red) {
    int tid = threadIdx.x;
    red[tid] = v; __syncthreads();
    #pragma unroll
    for (int s = 128; s > 0; s >>= 1) {
        if (tid < s) red[tid] += red[tid + s];
        __syncthreads();
    }
    float r = red[0]; __syncthreads();
    return r;
}

__device__ __forceinline__ float blk_reduce_max(float v, float* red) {
    int tid = threadIdx.x;
    red[tid] = v; __syncthreads();
    #pragma unroll
    for (int s = 128; s > 0; s >>= 1) {
        if (tid < s) red[tid] = fmaxf(red[tid], red[tid + s]);
        __syncthreads();
    }
    float r = red[0]; __syncthreads();
    return r;
}

// ---------------- weight quantization (4x float4 ILP) ----------------
__device__ __forceinline__ float abs4(float4 v) {
    return fabsf(v.x) + fabsf(v.y) + fabsf(v.z) + fabsf(v.w);
}

__global__ void absmean_partial(const float* __restrict__ w, float* __restrict__ part, int len4) {
    __shared__ float red[256];
    const float4* p = (const float4*)w + (size_t)blockIdx.y * len4;
    int i = blockIdx.x * 1024 + threadIdx.x;
    float4 v0 = p[i], v1 = p[i + 256], v2 = p[i + 512], v3 = p[i + 768];
    float s = (abs4(v0) + abs4(v1)) + (abs4(v2) + abs4(v3));
    s = blk_reduce_sum(s, red);
    if (threadIdx.x == 0) part[(size_t)blockIdx.y * gridDim.x + blockIdx.x] = s;
}

__global__ void absmean4(const float* __restrict__ w0, const float* __restrict__ w1,
                         const float* __restrict__ w2, const float* __restrict__ w3,
                         float* __restrict__ part, int len4) {
    __shared__ float red[256];
    int sl = blockIdx.y;
    const float* p = sl == 0 ? w0 : sl == 1 ? w1 : sl == 2 ? w2 : w3;
    const float4* p4 = (const float4*)p;
    int i = blockIdx.x * 1024 + threadIdx.x;
    float4 v0 = p4[i], v1 = p4[i + 256], v2 = p4[i + 512], v3 = p4[i + 768];
    float s = (abs4(v0) + abs4(v1)) + (abs4(v2) + abs4(v3));
    s = blk_reduce_sum(s, red);
    if (threadIdx.x == 0) part[(size_t)sl * gridDim.x + blockIdx.x] = s;
}

__global__ void finalize_wscale(const float* __restrict__ part, float* __restrict__ wsc,
                                int i0, int n) {
    int i = i0 + threadIdx.x;
    if (threadIdx.x >= n) return;
    float s = 0.f;
    for (int j = 0; j < 256; j++) s += part[i * 256 + j];
    wsc[i] = fmaxf(s * (1.0f / (1024.f * 1024.f)), 1e-5f);
}

__device__ __forceinline__ char quant_tern(float v, float s) {
    float q = rintf(v * s);
    q = fminf(fmaxf(q, -1.f), 1.f);
    return (char)(int)q;
}

__device__ __forceinline__ char4 qt4(float4 v, float s) {
    char4 o;
    o.x = quant_tern(v.x, s); o.y = quant_tern(v.y, s);
    o.z = quant_tern(v.z, s); o.w = quant_tern(v.w, s);
    return o;
}

__global__ void quantize_w(const float* __restrict__ w, int8_t* __restrict__ wq,
                           const float* __restrict__ wsc, int widx0, int len4) {
    int slice = blockIdx.y;
    float s = 1.0f / wsc[widx0 + slice];
    const float4* p = (const float4*)w + (size_t)slice * len4;
    char4* q = (char4*)wq + (size_t)slice * len4;
    int i = blockIdx.x * 1024 + threadIdx.x;
    float4 v0 = p[i], v1 = p[i + 256], v2 = p[i + 512], v3 = p[i + 768];
    q[i] = qt4(v0, s); q[i + 256] = qt4(v1, s);
    q[i + 512] = qt4(v2, s); q[i + 768] = qt4(v3, s);
}

__global__ void quantizeF4(const float* __restrict__ w0, const float* __restrict__ w1,
                           const float* __restrict__ w2, const float* __restrict__ w3,
                           int8_t* __restrict__ wq, const float* __restrict__ part,
                           float* __restrict__ wsc, int len4) {
    __shared__ float red[256];
    int sl = blockIdx.y;
    int tid = threadIdx.x;
    float total = blk_reduce_sum(part[sl * 256 + tid], red);
    float mean = fmaxf(total * (1.0f / (1024.f * 1024.f)), 1e-5f);
    if (blockIdx.x == 0 && tid == 0) wsc[sl] = mean;
    float s = 1.0f / mean;
    const float* p = sl == 0 ? w0 : sl == 1 ? w1 : sl == 2 ? w2 : w3;
    const float4* p4 = (const float4*)p;
    char4* q = (char4*)wq + (size_t)sl * len4;
    int i = blockIdx.x * 1024 + tid;
    float4 v0 = p4[i], v1 = p4[i + 256], v2 = p4[i + 512], v3 = p4[i + 768];
    q[i] = qt4(v0, s); q[i + 256] = qt4(v1, s);
    q[i + 512] = qt4(v2, s); q[i + 768] = qt4(v3, s);
}

// ---------------- activation rmsnorm + quant ----------------
__global__ void rmsnorm_quant(const float* __restrict__ x, const float* __restrict__ lnw,
                              int8_t* __restrict__ xq, float* __restrict__ ainv) {
    __shared__ float red[256];
    __shared__ float xs[CH];
    int t = blockIdx.x, tid = threadIdx.x;
    const float* xr = x + (size_t)t * CH;
    float v[4]; float ss = 0.f;
    #pragma unroll
    for (int i = 0; i < 4; i++) { v[i] = xr[tid + i * 256]; ss += v[i] * v[i]; }
    ss = blk_reduce_sum(ss, red);
    float r = rsqrtf(ss * (1.0f / CH) + 1e-5f);
    float amax = 0.f;
    #pragma unroll
    for (int i = 0; i < 4; i++) {
        float xn = v[i] * r * lnw[tid + i * 256];
        xs[tid + i * 256] = xn;
        amax = fmaxf(amax, fabsf(xn));
    }
    amax = blk_reduce_max(amax, red);
    float m = fmaxf(amax, 1e-5f);
    float s = 127.f / m;
    #pragma unroll
    for (int i = 0; i < 4; i++) {
        float qv = fminf(fmaxf(rintf(xs[tid + i * 256] * s), -128.f), 127.f);
        xq[(size_t)t * CH + tid + i * 256] = (int8_t)(int)qv;
    }
    if (tid == 0) ainv[t] = m * (1.0f / 127.f);
}

__global__ void act_quant_rows(const float* __restrict__ x, int8_t* __restrict__ xq,
                               float* __restrict__ ainv) {
    __shared__ float red[256];
    int t = blockIdx.x, tid = threadIdx.x;
    const float* xr = x + (size_t)t * CH;
    float v[4]; float amax = 0.f;
    #pragma unroll
    for (int i = 0; i < 4; i++) { v[i] = xr[tid + i * 256]; amax = fmaxf(amax, fabsf(v[i])); }
    amax = blk_reduce_max(amax, red);
    float m = fmaxf(amax, 1e-5f);
    float s = 127.f / m;
    #pragma unroll
    for (int i = 0; i < 4; i++) {
        float qv = fminf(fmaxf(rintf(v[i] * s), -128.f), 127.f);
        xq[(size_t)t * CH + tid + i * 256] = (int8_t)(int)qv;
    }
    if (tid == 0) ainv[t] = m * (1.0f / 127.f);
}

__global__ void rmsnorm2_router(const float* __restrict__ x, const float* __restrict__ lnw,
                                const float* __restrict__ rw, int8_t* __restrict__ xq,
                                float* __restrict__ ainv, int* __restrict__ idx,
                                int* __restrict__ counts) {
    __shared__ float red[256];
    __shared__ float xs[CH];
    __shared__ float logits[CE];
    int t = blockIdx.x, tid = threadIdx.x;
    const float* xr = x + (size_t)t * CH;
    float v[4]; float ss = 0.f;
    #pragma unroll
    for (int i = 0; i < 4; i++) { v[i] = xr[tid + i * 256]; ss += v[i] * v[i]; }
    ss = blk_reduce_sum(ss, red);
    float r = rsqrtf(ss * (1.0f / CH) + 1e-5f);
    float amax = 0.f;
    #pragma unroll
    for (int i = 0; i < 4; i++) {
        float xn = v[i] * r * lnw[tid + i * 256];
        xs[tid + i * 256] = xn;
        amax = fmaxf(amax, fabsf(xn));
    }
    amax = blk_reduce_max(amax, red);
    float m = fmaxf(amax, 1e-5f);
    float s = 127.f / m;
    #pragma unroll
    for (int i = 0; i < 4; i++) {
        float qv = fminf(fmaxf(rintf(xs[tid + i * 256] * s), -128.f), 127.f);
        xq[(size_t)t * CH + tid + i * 256] = (int8_t)(int)qv;
    }
    if (tid == 0) ainv[t] = m * (1.0f / 127.f);
    __syncthreads();

    int w = tid >> 5, lane = tid & 31;
    float acc = 0.f;
    for (int h = lane; h < CH; h += 32) acc += xs[h] * rw[w * CH + h];
    #pragma unroll
    for (int o = 16; o > 0; o >>= 1) acc += __shfl_down_sync(0xffffffffu, acc, o);
    if (lane == 0) logits[w] = acc;
    __syncthreads();
    if (tid == 0) {
        float best = logits[0]; int bi = 0;
        #pragma unroll
        for (int e = 1; e < CE; e++) if (logits[e] > best) { best = logits[e]; bi = e; }
        idx[t] = bi;
        atomicAdd(&counts[bi], 1);
    }
}

__global__ void zero_ints(int* __restrict__ counts, int* __restrict__ cursor) {
    if (threadIdx.x < CE) { counts[threadIdx.x] = 0; cursor[threadIdx.x] = 0; }
}

__global__ void build_offsets(const int* __restrict__ counts, int* __restrict__ seg) {
    if (threadIdx.x == 0) {
        int a = 0;
        for (int e = 0; e < CE; e++) { seg[e] = a; a += counts[e]; }
        seg[CE] = a;
    }
}

__global__ void scatter_tokens(const int* __restrict__ idx, const int* __restrict__ seg,
                               int* __restrict__ cursor, int* __restrict__ perm) {
    int t = blockIdx.x * 256 + threadIdx.x;
    if (t >= CT) return;
    int e = idx[t];
    int p = atomicAdd(&cursor[e], 1);
    perm[seg[e] + p] = t;
}

// ---------------- int8 x ternary GEMM: mma.sync + ldmatrix + cp.async (3-stage) ----------------
__device__ __forceinline__ void mma_s8(int* c, const int* a, const int* b) {
    asm volatile(
        "mma.sync.aligned.m16n8k32.row.col.s32.s8.s8.s32 "
        "{%0,%1,%2,%3}, {%4,%5,%6,%7}, {%8,%9}, {%0,%1,%2,%3};"
        : "+r"(c[0]), "+r"(c[1]), "+r"(c[2]), "+r"(c[3])
        : "r"(a[0]), "r"(a[1]), "r"(a[2]), "r"(a[3]), "r"(b[0]), "r"(b[1]));
}

#define LDMX4(r, addr) \
    asm volatile("ldmatrix.sync.aligned.m8n8.x4.shared.b16 {%0,%1,%2,%3}, [%4];" \
        : "=r"((r)[0]), "=r"((r)[1]), "=r"((r)[2]), "=r"((r)[3]) : "r"(addr))

#define CPA16(dst, src) \
    asm volatile("cp.async.cg.shared.global [%0], [%1], 16;" :: "r"(dst), "l"(src))
#define CPCOMMIT() asm volatile("cp.async.commit_group;" ::: "memory")

static constexpr int A_STG = 128 * 80;
static constexpr int B_STG = 64 * 80;

template<int MODE>
__global__ void __launch_bounds__(256) gemm_mma(
        const int8_t* __restrict__ A, const int8_t* __restrict__ Bw,
        float* __restrict__ Out, __nv_bfloat16* __restrict__ OutB,
        const float* __restrict__ ascale,
        const float* __restrict__ wscale,
        const float* __restrict__ resid,
        const int* __restrict__ perm,
        const int* __restrict__ seg) {
    int n0 = blockIdx.x * 64;
    int m0 = blockIdx.y * 128;
    int z = blockIdx.z;
    int e = (MODE == 2) ? (z & 7) : z;

    int off = 0, cnt = CT;
    if (MODE >= 2) {
        off = seg[e];
        cnt = seg[e + 1] - off;
        if (m0 >= cnt) return;
    }

    const int8_t* Bz = Bw;
    if (MODE == 0) Bz = Bw + (size_t)z * (CH * CH);
    if (MODE >= 2) Bz = Bw + (size_t)z * ((size_t)CD * CH);
    const int8_t* brow0 = Bz + (size_t)n0 * 1024;

    __shared__ __align__(16) int8_t As[3][128][80];
    __shared__ __align__(16) int8_t Bs[3][64][80];
    __shared__ const int8_t* aptr[128];
    __shared__ float rowsc[128];
    __shared__ int dstrow[128];

    int tid = threadIdx.x;
    if (tid < 128) {
        int r = m0 + tid;
        if (MODE <= 1) {
            aptr[tid] = A + (size_t)r * 1024;
            rowsc[tid] = ascale[r];
        } else if (MODE == 2) {
            int rr = r < cnt - 1 ? r : cnt - 1;
            int tok = perm[off + rr];
            aptr[tid] = A + (size_t)tok * 1024;
            rowsc[tid] = ascale[tok];
            dstrow[tid] = off + r;
        } else {
            int rr = r < cnt - 1 ? r : cnt - 1;
            aptr[tid] = A + (size_t)(off + rr) * 1024;
            rowsc[tid] = ascale[off + rr];
            dstrow[tid] = perm[off + rr];
        }
    }
    __syncthreads();

    int ar = tid >> 1, ao = (tid & 1) * 32;
    int brr = tid >> 2, bo = (tid & 3) * 16;
    const int8_t* pA = aptr[ar];
    const int8_t* pB = brow0 + (size_t)brr * 1024;

    uint32_t As_u = (uint32_t)__cvta_generic_to_shared(&As[0][0][0]);
    uint32_t Bs_u = (uint32_t)__cvta_generic_to_shared(&Bs[0][0][0]);
    uint32_t aSt = As_u + ar * 80 + ao;
    uint32_t bSt = Bs_u + brr * 80 + bo;

    int w = tid >> 5, lane = tid & 31;
    int warpM = w & 3, warpN = w >> 2;
    int gid = lane >> 2, tig = lane & 3;

    int rowA_ld = warpM * 32 + (lane & 7) + ((lane >> 3) & 1) * 8;
    uint32_t aF = As_u + rowA_ld * 80 + (lane >> 4) * 16;
    int rowB_ld = warpN * 32 + (lane & 7) + (lane >> 4) * 8;
    uint32_t bF = Bs_u + rowB_ld * 80 + ((lane >> 3) & 1) * 16;

    int c[2][4][4];
    #pragma unroll
    for (int i = 0; i < 2; i++)
        #pragma unroll
        for (int j = 0; j < 4; j++)
            #pragma unroll
            for (int k = 0; k < 4; k++) c[i][j][k] = 0;

    #pragma unroll
    for (int s = 0; s < 2; s++) {
        uint32_t aD = aSt + s * A_STG;
        CPA16(aD, pA + s * 64 + ao);
        CPA16(aD + 16, pA + s * 64 + ao + 16);
        CPA16(bSt + s * B_STG, pB + s * 64 + bo);
        CPCOMMIT();
    }

    #pragma unroll 1
    for (int kt = 0; kt < 16; kt++) {
        if (kt < 15) {
            asm volatile("cp.async.wait_group 1;" ::: "memory");
        } else {
            asm volatile("cp.async.wait_group 0;" ::: "memory");
        }
        __syncthreads();
        if (kt < 14) {
            int s = kt + 2;
            int b = s % 3;
            uint32_t aD = aSt + b * A_STG;
            CPA16(aD, pA + s * 64 + ao);
            CPA16(aD + 16, pA + s * 64 + ao + 16);
            CPA16(bSt + b * B_STG, pB + s * 64 + bo);
            CPCOMMIT();
        }
        int stg = kt % 3;
        uint32_t aBase = aF + stg * A_STG;
        uint32_t bBase = bF + stg * B_STG;
        #pragma unroll
        for (int ks = 0; ks < 2; ks++) {
            int a0[4], a1[4], b01[4], b23[4];
            LDMX4(a0, aBase + ks * 32);
            LDMX4(a1, aBase + 16 * 80 + ks * 32);
            LDMX4(b01, bBase + ks * 32);
            LDMX4(b23, bBase + 16 * 80 + ks * 32);
            mma_s8(c[0][0], a0, b01 + 0);
            mma_s8(c[0][1], a0, b01 + 2);
            mma_s8(c[0][2], a0, b23 + 0);
            mma_s8(c[0][3], a0, b23 + 2);
            mma_s8(c[1][0], a1, b01 + 0);
            mma_s8(c[1][1], a1, b01 + 2);
            mma_s8(c[1][2], a1, b23 + 0);
            mma_s8(c[1][3], a1, b23 + 2);
        }
        __syncthreads();
    }

    float wS = wscale[(MODE == 0 || MODE >= 2) ? z : 0];

    #pragma unroll
    for (int wm = 0; wm < 2; wm++) {
        int r0 = warpM * 32 + wm * 16 + gid;
        int r1 = r0 + 8;
        float av0 = rowsc[r0] * wS;
        float av1 = rowsc[r1] * wS;
        #pragma unroll
        for (int nt = 0; nt < 4; nt++) {
            int colL = warpN * 32 + nt * 8 + tig * 2;
            int* cc = c[wm][nt];
            if (MODE == 0) {
                int nh = n0 >> 6;
                int gr0 = m0 + r0, gr1 = m0 + r1;
                int b0 = gr0 / CS, sr0 = gr0 % CS;
                int b1 = gr1 / CS, sr1 = gr1 % CS;
                __nv_bfloat16* base = OutB + (size_t)z * ((size_t)CT * CH);
                __nv_bfloat162 o0 = {__float2bfloat16(cc[0] * av0), __float2bfloat16(cc[1] * av0)};
                __nv_bfloat162 o1 = {__float2bfloat16(cc[2] * av1), __float2bfloat16(cc[3] * av1)};
                *(__nv_bfloat162*)(base + (((size_t)b0 * CNH + nh) * CS + sr0) * CHD + colL) = o0;
                *(__nv_bfloat162*)(base + (((size_t)b1 * CNH + nh) * CS + sr1) * CHD + colL) = o1;
            } else if (MODE == 1) {
                size_t rb0 = (size_t)(m0 + r0) * CH + n0 + colL;
                size_t rb1 = (size_t)(m0 + r1) * CH + n0 + colL;
                float2 rv0 = *(const float2*)(resid + rb0);
                float2 rv1 = *(const float2*)(resid + rb1);
                float2 o0 = {rv0.x + cc[0] * av0, rv0.y + cc[1] * av0};
                float2 o1 = {rv1.x + cc[2] * av1, rv1.y + cc[3] * av1};
                *(float2*)(Out + rb0) = o0;
                *(float2*)(Out + rb1) = o1;
            } else if (MODE == 2) {
                size_t half = (size_t)(z >> 3) * ((size_t)CT * CD);
                if (m0 + r0 < cnt) {
                    size_t rb = half + (size_t)dstrow[r0] * CD + n0 + colL;
                    float2 o = {cc[0] * av0, cc[1] * av0};
                    *(float2*)(Out + rb) = o;
                }
                if (m0 + r1 < cnt) {
                    size_t rb = half + (size_t)dstrow[r1] * CD + n0 + colL;
                    float2 o = {cc[2] * av1, cc[3] * av1};
                    *(float2*)(Out + rb) = o;
                }
            } else {
                if (m0 + r0 < cnt) {
                    size_t rb = (size_t)dstrow[r0] * CH + n0 + colL;
                    float2 rv = *(const float2*)(resid + rb);
                    float2 o = {rv.x + cc[0] * av0, rv.y + cc[1] * av0};
                    *(float2*)(Out + rb) = o;
                }
                if (m0 + r1 < cnt) {
                    size_t rb = (size_t)dstrow[r1] * CH + n0 + colL;
                    float2 rv = *(const float2*)(resid + rb);
                    float2 o = {rv.x + cc[2] * av1, rv.y + cc[3] * av1};
                    *(float2*)(Out + rb) = o;
                }
            }
        }
    }
}

// ---------------- attention: FA2-style, causal-balanced (2 q-tiles per CTA) ----------------
__device__ __forceinline__ void mma_bf16(float* c, const uint32_t* a, uint32_t b0, uint32_t b1) {
    asm volatile(
        "mma.sync.aligned.m16n8k16.row.col.f32.bf16.bf16.f32 "
        "{%0,%1,%2,%3}, {%4,%5,%6,%7}, {%8,%9}, {%0,%1,%2,%3};"
        : "+f"(c[0]), "+f"(c[1]), "+f"(c[2]), "+f"(c[3])
        : "r"(a[0]), "r"(a[1]), "r"(a[2]), "r"(a[3]), "r"(b0), "r"(b1));
}

__device__ __forceinline__ void ldmx4t(uint32_t& r0, uint32_t& r1, uint32_t& r2, uint32_t& r3,
                                       uint32_t addr) {
    asm volatile("ldmatrix.sync.aligned.m8n8.x4.trans.shared.b16 {%0,%1,%2,%3}, [%4];"
        : "=r"(r0), "=r"(r1), "=r"(r2), "=r"(r3) : "r"(addr));
}

__device__ __forceinline__ uint32_t pack_bf2(float a, float b) {
    __nv_bfloat162 t = __floats2bfloat162_rn(a, b);
    return *(uint32_t*)&t;
}

static constexpr int KLD = 72;
#define ASCL 0.18033688011112042f   // 0.125 * log2(e)

__global__ void __launch_bounds__(128) attn_fa2(
        const __nv_bfloat16* __restrict__ Qg, const __nv_bfloat16* __restrict__ Kg,
        const __nv_bfloat16* __restrict__ Vg, float* __restrict__ Hout) {
    __shared__ __align__(16) __nv_bfloat16 Ks[64][KLD];
    __shared__ __align__(16) __nv_bfloat16 Vs[64][KLD];

    int bh = blockIdx.y;
    const __nv_bfloat16* Qb = Qg + (size_t)bh * CS * CHD;
    const __nv_bfloat16* Kb = Kg + (size_t)bh * CS * CHD;
    const __nv_bfloat16* Vb = Vg + (size_t)bh * CS * CHD;

    int tid = threadIdx.x;
    int w = tid >> 5, lane = tid & 31;
    int gid = lane >> 2, tig = lane & 3;

    int b = bh / CNH, nh = bh % CNH;

    // causal balancing: this CTA handles q-tiles (31 - blockIdx.x) and blockIdx.x
    // total k-tile iterations = (32 - blockIdx.x) + (blockIdx.x + 1) = 33 for every CTA
    #pragma unroll 1
    for (int rep = 0; rep < 2; rep++) {
        int qb = rep == 0 ? (31 - (int)blockIdx.x) : (int)blockIdx.x;
        int q0 = qb * 64;
        int qr0 = q0 + w * 16 + gid;
        int qr1 = qr0 + 8;

        uint32_t qf[4][4];
        #pragma unroll
        for (int k = 0; k < 4; k++) {
            const __nv_bfloat16* p0 = Qb + (size_t)qr0 * CHD + k * 16 + 2 * tig;
            const __nv_bfloat16* p1 = Qb + (size_t)qr1 * CHD + k * 16 + 2 * tig;
            qf[k][0] = *(const uint32_t*)p0;
            qf[k][1] = *(const uint32_t*)p1;
            qf[k][2] = *(const uint32_t*)(p0 + 8);
            qf[k][3] = *(const uint32_t*)(p1 + 8);
        }

        float o[8][4];
        #pragma unroll
        for (int nt = 0; nt < 8; nt++)
            #pragma unroll
            for (int j = 0; j < 4; j++) o[nt][j] = 0.f;
        float m0 = -INFINITY, m1 = -INFINITY, l0 = 0.f, l1 = 0.f;

        int nkt = qb + 1;
        #pragma unroll 1
        for (int kt = 0; kt < nkt; kt++) {
            int k0 = kt * 64;
            __syncthreads();
            for (int i = tid; i < 512; i += 128) {
                int row = i >> 3, c8 = (i & 7) * 8;
                *(uint4*)&Ks[row][c8] = *(const uint4*)(Kb + (size_t)(k0 + row) * CHD + c8);
                *(uint4*)&Vs[row][c8] = *(const uint4*)(Vb + (size_t)(k0 + row) * CHD + c8);
            }
            __syncthreads();

            float s[8][4];
            #pragma unroll
            for (int nt = 0; nt < 8; nt++)
                #pragma unroll
                for (int j = 0; j < 4; j++) s[nt][j] = 0.f;
            #pragma unroll
            for (int k = 0; k < 4; k++) {
                #pragma unroll
                for (int nt = 0; nt < 8; nt++) {
                    uint32_t b0 = *(const uint32_t*)&Ks[nt * 8 + gid][k * 16 + 2 * tig];
                    uint32_t b1 = *(const uint32_t*)&Ks[nt * 8 + gid][k * 16 + 8 + 2 * tig];
                    mma_bf16(s[nt], qf[k], b0, b1);
                }
            }

            bool diag = (kt == qb);
            float rmax0 = -INFINITY, rmax1 = -INFINITY;
            #pragma unroll
            for (int nt = 0; nt < 8; nt++) {
                int cg = k0 + nt * 8 + 2 * tig;
                #pragma unroll
                for (int j = 0; j < 2; j++) {
                    float v0 = s[nt][j] * ASCL;
                    float v1 = s[nt][2 + j] * ASCL;
                    if (diag && cg + j > qr0) v0 = -INFINITY;
                    if (diag && cg + j > qr1) v1 = -INFINITY;
                    s[nt][j] = v0; s[nt][2 + j] = v1;
                    rmax0 = fmaxf(rmax0, v0); rmax1 = fmaxf(rmax1, v1);
                }
            }
            rmax0 = fmaxf(rmax0, __shfl_xor_sync(0xffffffffu, rmax0, 1));
            rmax0 = fmaxf(rmax0, __shfl_xor_sync(0xffffffffu, rmax0, 2));
            rmax1 = fmaxf(rmax1, __shfl_xor_sync(0xffffffffu, rmax1, 1));
            rmax1 = fmaxf(rmax1, __shfl_xor_sync(0xffffffffu, rmax1, 2));

            float mn0 = fmaxf(m0, rmax0), mn1 = fmaxf(m1, rmax1);
            float sum0 = 0.f, sum1 = 0.f;
            #pragma unroll
            for (int nt = 0; nt < 8; nt++) {
                s[nt][0] = exp2f(s[nt][0] - mn0);
                s[nt][1] = exp2f(s[nt][1] - mn0);
                s[nt][2] = exp2f(s[nt][2] - mn1);
                s[nt][3] = exp2f(s[nt][3] - mn1);
                sum0 += s[nt][0] + s[nt][1];
                sum1 += s[nt][2] + s[nt][3];
            }
            sum0 += __shfl_xor_sync(0xffffffffu, sum0, 1);
            sum0 += __shfl_xor_sync(0xffffffffu, sum0, 2);
            sum1 += __shfl_xor_sync(0xffffffffu, sum1, 1);
            sum1 += __shfl_xor_sync(0xffffffffu, sum1, 2);

            float rs0 = exp2f(m0 - mn0), rs1 = exp2f(m1 - mn1);
            m0 = mn0; m1 = mn1;
            l0 = l0 * rs0 + sum0;
            l1 = l1 * rs1 + sum1;
            #pragma unroll
            for (int nt = 0; nt < 8; nt++) {
                o[nt][0] *= rs0; o[nt][1] *= rs0;
                o[nt][2] *= rs1; o[nt][3] *= rs1;
            }

            #pragma unroll
            for (int kb = 0; kb < 4; kb++) {
                uint32_t pf[4];
                pf[0] = pack_bf2(s[2 * kb][0], s[2 * kb][1]);
                pf[1] = pack_bf2(s[2 * kb][2], s[2 * kb][3]);
                pf[2] = pack_bf2(s[2 * kb + 1][0], s[2 * kb + 1][1]);
                pf[3] = pack_bf2(s[2 * kb + 1][2], s[2 * kb + 1][3]);
                #pragma unroll
                for (int nb = 0; nb < 4; nb++) {
                    uint32_t v0, v1, v2, v3;
                    uint32_t addr = (uint32_t)__cvta_generic_to_shared(
                        &Vs[kb * 16 + (lane & 15)][nb * 16 + ((lane >> 4) << 3)]);
                    ldmx4t(v0, v1, v2, v3, addr);
                    mma_bf16(o[2 * nb], pf, v0, v1);
                    mma_bf16(o[2 * nb + 1], pf, v2, v3);
                }
            }
        }

        float inv0 = 1.0f / l0, inv1 = 1.0f / l1;
        #pragma unroll
        for (int nt = 0; nt < 8; nt++) {
            int col = nt * 8 + 2 * tig;
            float2 w0v = {o[nt][0] * inv0, o[nt][1] * inv0};
            float2 w1v = {o[nt][2] * inv1, o[nt][3] * inv1};
            *(float2*)(Hout + (((size_t)b * CS + qr0) * CNH + nh) * CHD + col) = w0v;
            *(float2*)(Hout + (((size_t)b * CS + qr1) * CNH + nh) * CHD + col) = w1v;
        }
    }
}

// ---------------- MoE elementwise: hh = relu(g)^2 * u, then act_quant ----------------
__global__ void hh_quant(const float* __restrict__ g, const float* __restrict__ u,
                         int8_t* __restrict__ hq, float* __restrict__ hs) {
    __shared__ float red[256];
    __shared__ float hb[CD];
    int slot = blockIdx.x, tid = threadIdx.x;
    float amax = 0.f;
    #pragma unroll
    for (int i = 0; i < 4; i++) {
        int k = tid + i * 256;
        float gv = g[(size_t)slot * CD + k];
        float uv = u[(size_t)slot * CD + k];
        float rl = fmaxf(gv, 0.f);
        float h = rl * rl * uv;
        hb[k] = h;
        amax = fmaxf(amax, fabsf(h));
    }
    amax = blk_reduce_max(amax, red);
    float m = fmaxf(amax, 1e-5f);
    float s = 127.f / m;
    #pragma unroll
    for (int i = 0; i < 4; i++) {
        int k = tid + i * 256;
        float qv = fminf(fmaxf(rintf(hb[k] * s), -128.f), 127.f);
        hq[(size_t)slot * CD + k] = (int8_t)(int)qv;
    }
    if (tid == 0) hs[slot] = m * (1.0f / 127.f);
}

// ---------------- launch (fork-join dual stream) ----------------
extern "C" void kernel_launch(void* const* d_in, const int* in_sizes, int n_in,
                              void* d_out, int out_size) {
    const float* x        = (const float*)d_in[0];
    const float* q_w      = (const float*)d_in[1];
    const float* k_w      = (const float*)d_in[2];
    const float* v_w      = (const float*)d_in[3];
    const float* o_w      = (const float*)d_in[4];
    const float* ln1_w    = (const float*)d_in[5];
    const float* ln2_w    = (const float*)d_in[6];
    const float* router_w = (const float*)d_in[7];
    const float* gate_w   = (const float*)d_in[8];
    const float* up_w     = (const float*)d_in[9];
    const float* down_w   = (const float*)d_in[10];

    unsigned char* base = nullptr;
    cudaGetSymbolAddress((void**)&base, g_scratch);

    int8_t* wq_attn = (int8_t*)(base + OFF_WQ_ATTN);
    int8_t* wq_gate = (int8_t*)(base + OFF_WQ_GATE);
    int8_t* wq_up   = (int8_t*)(base + OFF_WQ_UP);
    int8_t* wq_down = (int8_t*)(base + OFF_WQ_DOWN);
    float*  wsc     = (float*)(base + OFF_WSCALE);
    float*  part    = (float*)(base + OFF_PART);
    int8_t* xq1     = (int8_t*)(base + OFF_XQ1);
    float*  a1s     = (float*)(base + OFF_A1S);
    __nv_bfloat16* qkvb = (__nv_bfloat16*)(base + OFF_QKV);
    float*  hb      = (float*)(base + OFF_HB);
    int8_t* hqa     = (int8_t*)(base + OFF_HQA);
    float*  hsa     = (float*)(base + OFF_HSA);
    float*  x2      = (float*)(base + OFF_X2);
    int8_t* xq2     = (int8_t*)(base + OFF_XQ2);
    float*  a2s     = (float*)(base + OFF_A2S);
    int*    idx     = (int*)(base + OFF_IDX);
    int*    cnt     = (int*)(base + OFF_CNT);
    int*    seg     = (int*)(base + OFF_SEG);
    int*    cur     = (int*)(base + OFF_CUR);
    int*    perm    = (int*)(base + OFF_PERM);
    float*  gb      = (float*)(base + OFF_GB);
    float*  ub      = (float*)(base + OFF_UB);
    int8_t* hqm     = (int8_t*)(base + OFF_HQM);
    float*  hsm     = (float*)(base + OFF_HSM);
    float*  out     = (float*)d_out;

    const int LEN4 = (CH * CH) / 4;

    cudaStream_t s2;
    cudaStreamCreateWithFlags(&s2, cudaStreamNonBlocking);
    cudaEvent_t evFork, evB, evJoin;
    cudaEventCreateWithFlags(&evFork, cudaEventDisableTiming);
    cudaEventCreateWithFlags(&evB, cudaEventDisableTiming);
    cudaEventCreateWithFlags(&evJoin, cudaEventDisableTiming);

    cudaEventRecord(evFork, 0);
    cudaStreamWaitEvent(s2, evFork, 0);

    // ---- side stream: activation quant, then MoE weight quant ----
    rmsnorm_quant<<<CT, 256, 0, s2>>>(x, ln1_w, xq1, a1s);
    cudaEventRecord(evB, s2);
    absmean_partial<<<dim3(256, 8), 256, 0, s2>>>(gate_w, part + 4 * 256, LEN4);
    absmean_partial<<<dim3(256, 8), 256, 0, s2>>>(up_w,   part + 12 * 256, LEN4);
    absmean_partial<<<dim3(256, 8), 256, 0, s2>>>(down_w, part + 20 * 256, LEN4);
    finalize_wscale<<<1, 32, 0, s2>>>(part, wsc, 4, 24);
    quantize_w<<<dim3(256, 8), 256, 0, s2>>>(gate_w, wq_gate, wsc, 4, LEN4);
    quantize_w<<<dim3(256, 8), 256, 0, s2>>>(up_w,   wq_up,   wsc, 12, LEN4);
    quantize_w<<<dim3(256, 8), 256, 0, s2>>>(down_w, wq_down, wsc, 20, LEN4);
    cudaEventRecord(evJoin, s2);

    // ---- main stream: attention weights + attention path ----
    zero_ints<<<1, 32>>>(cnt, cur);
    absmean4<<<dim3(256, 4), 256>>>(q_w, k_w, v_w, o_w, part, LEN4);
    quantizeF4<<<dim3(256, 4), 256>>>(q_w, k_w, v_w, o_w, wq_attn, part, wsc, LEN4);
    cudaStreamWaitEvent(0, evB, 0);
    gemm_mma<0><<<dim3(16, 32, 3), 256>>>(xq1, wq_attn, nullptr, qkvb, a1s, wsc, nullptr, nullptr, nullptr);

    attn_fa2<<<dim3(16, CB * CNH), 128>>>(
        qkvb, qkvb + (size_t)CT * CH, qkvb + 2 * (size_t)CT * CH, hb);

    // ---- o-proj + residual ----
    act_quant_rows<<<CT, 256>>>(hb, hqa, hsa);
    gemm_mma<1><<<dim3(16, 32, 1), 256>>>(hqa, wq_attn + 3 * (CH * CH), x2, nullptr, hsa, wsc + 3, x, nullptr, nullptr);

    // ---- MoE ----
    rmsnorm2_router<<<CT, 256>>>(x2, ln2_w, router_w, xq2, a2s, idx, cnt);
    build_offsets<<<1, 1>>>(cnt, seg);
    scatter_tokens<<<16, 256>>>(idx, seg, cur, perm);

    cudaStreamWaitEvent(0, evJoin, 0);
    gemm_mma<2><<<dim3(16, 32, 16), 256>>>(xq2, wq_gate, gb, nullptr, a2s, wsc + 4, nullptr, perm, seg);
    hh_quant<<<CT, 256>>>(gb, ub, hqm, hsm);
    gemm_mma<3><<<dim3(16, 32, 8), 256>>>(hqm, wq_down, out, nullptr, hsm, wsc + 20, x2, perm, seg);
}

// round 14
// speedup vs baseline: 2.7007x; 1.0236x over previous
#include <cuda_runtime.h>
#include <cuda_bf16.h>
#include <math.h>
#include <stdint.h>

#define CB 2
#define CS 2048
#define CH 1024
#define CNH 16
#define CHD 64
#define CE 8
#define CD 1024
#define CT (CB*CS)

#define MB (1024ull*1024ull)

// ---------------- scratch layout ----------------
static constexpr size_t OFF_WQ_ATTN = 0;
static constexpr size_t OFF_WQ_GATE = 4*MB;
static constexpr size_t OFF_WQ_UP   = 12*MB;
static constexpr size_t OFF_WQ_DOWN = 20*MB;
static constexpr size_t OFF_WSCALE  = 28*MB;
static constexpr size_t OFF_PART    = 28*MB + 4096;
static constexpr size_t OFF_XQ1     = 29*MB;
static constexpr size_t OFF_A1S     = 33*MB;
static constexpr size_t OFF_QKV     = 34*MB;
static constexpr size_t OFF_HB      = 82*MB;
static constexpr size_t OFF_HQA     = 98*MB;
static constexpr size_t OFF_HSA     = 102*MB;
static constexpr size_t OFF_X2      = 103*MB;
static constexpr size_t OFF_XQ2     = 119*MB;
static constexpr size_t OFF_A2S     = 123*MB;
static constexpr size_t OFF_IDX     = 123*MB + 64*1024;
static constexpr size_t OFF_CNT     = 123*MB + 128*1024;
static constexpr size_t OFF_SEG     = 123*MB + 129*1024;
static constexpr size_t OFF_CUR     = 123*MB + 130*1024;
static constexpr size_t OFF_PERM    = 124*MB;
static constexpr size_t OFF_GB      = 125*MB;
static constexpr size_t OFF_UB      = 141*MB;
static constexpr size_t OFF_HQM     = 157*MB;
static constexpr size_t OFF_HSM     = 161*MB;
static constexpr size_t SCRATCH_BYTES = 162*MB;

__device__ __align__(256) unsigned char g_scratch[SCRATCH_BYTES];

// ---------------- reductions ----------------
__device__ __forceinline__ float blk_reduce_sum(float v, float* red) {
    int tid = threadIdx.x;
    red[tid] = v; __syncthreads();
    #pragma unroll
    for (int s = 128; s > 0; s >>= 1) {
        if (tid < s) red[tid] += red[tid + s];
        __syncthreads();
    }
    float r = red[0]; __syncthreads();
    return r;
}

__device__ __forceinline__ float blk_reduce_max(float v, float* red) {
    int tid = threadIdx.x;
    red[tid] = v; __syncthreads();
    #pragma unroll
    for (int s = 128; s > 0; s >>= 1) {
        if (tid < s) red[tid] = fmaxf(red[tid], red[tid + s]);
        __syncthreads();
    }
    float r = red[0]; __syncthreads();
    return r;
}

// ---------------- weight quantization (4x float4 ILP) ----------------
__device__ __forceinline__ float abs4(float4 v) {
    return fabsf(v.x) + fabsf(v.y) + fabsf(v.z) + fabsf(v.w);
}

__global__ void absmean_partial(const float* __restrict__ w, float* __restrict__ part, int len4) {
    __shared__ float red[256];
    const float4* p = (const float4*)w + (size_t)blockIdx.y * len4;
    int i = blockIdx.x * 1024 + threadIdx.x;
    float4 v0 = p[i], v1 = p[i + 256], v2 = p[i + 512], v3 = p[i + 768];
    float s = (abs4(v0) + abs4(v1)) + (abs4(v2) + abs4(v3));
    s = blk_reduce_sum(s, red);
    if (threadIdx.x == 0) part[(size_t)blockIdx.y * gridDim.x + blockIdx.x] = s;
}

__global__ void absmean4(const float* __restrict__ w0, const float* __restrict__ w1,
                         const float* __restrict__ w2, const float* __restrict__ w3,
                         float* __restrict__ part, int len4) {
    __shared__ float red[256];
    int sl = blockIdx.y;
    const float* p = sl == 0 ? w0 : sl == 1 ? w1 : sl == 2 ? w2 : w3;
    const float4* p4 = (const float4*)p;
    int i = blockIdx.x * 1024 + threadIdx.x;
    float4 v0 = p4[i], v1 = p4[i + 256], v2 = p4[i + 512], v3 = p4[i + 768];
    float s = (abs4(v0) + abs4(v1)) + (abs4(v2) + abs4(v3));
    s = blk_reduce_sum(s, red);
    if (threadIdx.x == 0) part[(size_t)sl * gridDim.x + blockIdx.x] = s;
}

__global__ void finalize_wscale(const float* __restrict__ part, float* __restrict__ wsc,
                                int i0, int n) {
    int i = i0 + threadIdx.x;
    if (threadIdx.x >= n) return;
    float s = 0.f;
    for (int j = 0; j < 256; j++) s += part[i * 256 + j];
    wsc[i] = fmaxf(s * (1.0f / (1024.f * 1024.f)), 1e-5f);
}

__device__ __forceinline__ char quant_tern(float v, float s) {
    float q = rintf(v * s);
    q = fminf(fmaxf(q, -1.f), 1.f);
    return (char)(int)q;
}

__device__ __forceinline__ char4 qt4(float4 v, float s) {
    char4 o;
    o.x = quant_tern(v.x, s); o.y = quant_tern(v.y, s);
    o.z = quant_tern(v.z, s); o.w = quant_tern(v.w, s);
    return o;
}

__global__ void quantize_w(const float* __restrict__ w, int8_t* __restrict__ wq,
                           const float* __restrict__ wsc, int widx0, int len4) {
    int slice = blockIdx.y;
    float s = 1.0f / wsc[widx0 + slice];
    const float4* p = (const float4*)w + (size_t)slice * len4;
    char4* q = (char4*)wq + (size_t)slice * len4;
    int i = blockIdx.x * 1024 + threadIdx.x;
    float4 v0 = p[i], v1 = p[i + 256], v2 = p[i + 512], v3 = p[i + 768];
    q[i] = qt4(v0, s); q[i + 256] = qt4(v1, s);
    q[i + 512] = qt4(v2, s); q[i + 768] = qt4(v3, s);
}

__global__ void quantizeF4(const float* __restrict__ w0, const float* __restrict__ w1,
                           const float* __restrict__ w2, const float* __restrict__ w3,
                           int8_t* __restrict__ wq, const float* __restrict__ part,
                           float* __restrict__ wsc, int len4) {
    __shared__ float red[256];
    int sl = blockIdx.y;
    int tid = threadIdx.x;
    float total = blk_reduce_sum(part[sl * 256 + tid], red);
    float mean = fmaxf(total * (1.0f / (1024.f * 1024.f)), 1e-5f);
    if (blockIdx.x == 0 && tid == 0) wsc[sl] = mean;
    float s = 1.0f / mean;
    const float* p = sl == 0 ? w0 : sl == 1 ? w1 : sl == 2 ? w2 : w3;
    const float4* p4 = (const float4*)p;
    char4* q = (char4*)wq + (size_t)sl * len4;
    int i = blockIdx.x * 1024 + tid;
    float4 v0 = p4[i], v1 = p4[i + 256], v2 = p4[i + 512], v3 = p4[i + 768];
    q[i] = qt4(v0, s); q[i + 256] = qt4(v1, s);
    q[i + 512] = qt4(v2, s); q[i + 768] = qt4(v3, s);
}

// ---------------- activation rmsnorm + quant ----------------
__global__ void rmsnorm_quant(const float* __restrict__ x, const float* __restrict__ lnw,
                              int8_t* __restrict__ xq, float* __restrict__ ainv) {
    __shared__ float red[256];
    __shared__ float xs[CH];
    int t = blockIdx.x, tid = threadIdx.x;
    const float* xr = x + (size_t)t * CH;
    float v[4]; float ss = 0.f;
    #pragma unroll
    for (int i = 0; i < 4; i++) { v[i] = xr[tid + i * 256]; ss += v[i] * v[i]; }
    ss = blk_reduce_sum(ss, red);
    float r = rsqrtf(ss * (1.0f / CH) + 1e-5f);
    float amax = 0.f;
    #pragma unroll
    for (int i = 0; i < 4; i++) {
        float xn = v[i] * r * lnw[tid + i * 256];
        xs[tid + i * 256] = xn;
        amax = fmaxf(amax, fabsf(xn));
    }
    amax = blk_reduce_max(amax, red);
    float m = fmaxf(amax, 1e-5f);
    float s = 127.f / m;
    #pragma unroll
    for (int i = 0; i < 4; i++) {
        float qv = fminf(fmaxf(rintf(xs[tid + i * 256] * s), -128.f), 127.f);
        xq[(size_t)t * CH + tid + i * 256] = (int8_t)(int)qv;
    }
    if (tid == 0) ainv[t] = m * (1.0f / 127.f);
}

__global__ void act_quant_rows(const float* __restrict__ x, int8_t* __restrict__ xq,
                               float* __restrict__ ainv) {
    __shared__ float red[256];
    int t = blockIdx.x, tid = threadIdx.x;
    const float* xr = x + (size_t)t * CH;
    float v[4]; float amax = 0.f;
    #pragma unroll
    for (int i = 0; i < 4; i++) { v[i] = xr[tid + i * 256]; amax = fmaxf(amax, fabsf(v[i])); }
    amax = blk_reduce_max(amax, red);
    float m = fmaxf(amax, 1e-5f);
    float s = 127.f / m;
    #pragma unroll
    for (int i = 0; i < 4; i++) {
        float qv = fminf(fmaxf(rintf(v[i] * s), -128.f), 127.f);
        xq[(size_t)t * CH + tid + i * 256] = (int8_t)(int)qv;
    }
    if (tid == 0) ainv[t] = m * (1.0f / 127.f);
}

__global__ void rmsnorm2_router(const float* __restrict__ x, const float* __restrict__ lnw,
                                const float* __restrict__ rw, int8_t* __restrict__ xq,
                                float* __restrict__ ainv, int* __restrict__ idx,
                                int* __restrict__ counts) {
    __shared__ float red[256];
    __shared__ float xs[CH];
    __shared__ float logits[CE];
    int t = blockIdx.x, tid = threadIdx.x;
    const float* xr = x + (size_t)t * CH;
    float v[4]; float ss = 0.f;
    #pragma unroll
    for (int i = 0; i < 4; i++) { v[i] = xr[tid + i * 256]; ss += v[i] * v[i]; }
    ss = blk_reduce_sum(ss, red);
    float r = rsqrtf(ss * (1.0f / CH) + 1e-5f);
    float amax = 0.f;
    #pragma unroll
    for (int i = 0; i < 4; i++) {
        float xn = v[i] * r * lnw[tid + i * 256];
        xs[tid + i * 256] = xn;
        amax = fmaxf(amax, fabsf(xn));
    }
    amax = blk_reduce_max(amax, red);
    float m = fmaxf(amax, 1e-5f);
    float s = 127.f / m;
    #pragma unroll
    for (int i = 0; i < 4; i++) {
        float qv = fminf(fmaxf(rintf(xs[tid + i * 256] * s), -128.f), 127.f);
        xq[(size_t)t * CH + tid + i * 256] = (int8_t)(int)qv;
    }
    if (tid == 0) ainv[t] = m * (1.0f / 127.f);
    __syncthreads();

    int w = tid >> 5, lane = tid & 31;
    float acc = 0.f;
    for (int h = lane; h < CH; h += 32) acc += xs[h] * rw[w * CH + h];
    #pragma unroll
    for (int o = 16; o > 0; o >>= 1) acc += __shfl_down_sync(0xffffffffu, acc, o);
    if (lane == 0) logits[w] = acc;
    __syncthreads();
    if (tid == 0) {
        float best = logits[0]; int bi = 0;
        #pragma unroll
        for (int e = 1; e < CE; e++) if (logits[e] > best) { best = logits[e]; bi = e; }
        idx[t] = bi;
        atomicAdd(&counts[bi], 1);
    }
}

__global__ void zero_ints(int* __restrict__ counts, int* __restrict__ cursor) {
    if (threadIdx.x < CE) { counts[threadIdx.x] = 0; cursor[threadIdx.x] = 0; }
}

__global__ void build_offsets(const int* __restrict__ counts, int* __restrict__ seg) {
    if (threadIdx.x == 0) {
        int a = 0;
        for (int e = 0; e < CE; e++) { seg[e] = a; a += counts[e]; }
        seg[CE] = a;
    }
}

__global__ void scatter_tokens(const int* __restrict__ idx, const int* __restrict__ seg,
                               int* __restrict__ cursor, int* __restrict__ perm) {
    int t = blockIdx.x * 256 + threadIdx.x;
    if (t >= CT) return;
    int e = idx[t];
    int p = atomicAdd(&cursor[e], 1);
    perm[seg[e] + p] = t;
}

// ---------------- int8 x ternary GEMM: mma.sync + ldmatrix + cp.async (3-stage) ----------------
__device__ __forceinline__ void mma_s8(int* c, const int* a, const int* b) {
    asm volatile(
        "mma.sync.aligned.m16n8k32.row.col.s32.s8.s8.s32 "
        "{%0,%1,%2,%3}, {%4,%5,%6,%7}, {%8,%9}, {%0,%1,%2,%3};"
        : "+r"(c[0]), "+r"(c[1]), "+r"(c[2]), "+r"(c[3])
        : "r"(a[0]), "r"(a[1]), "r"(a[2]), "r"(a[3]), "r"(b[0]), "r"(b[1]));
}

#define LDMX4(r, addr) \
    asm volatile("ldmatrix.sync.aligned.m8n8.x4.shared.b16 {%0,%1,%2,%3}, [%4];" \
        : "=r"((r)[0]), "=r"((r)[1]), "=r"((r)[2]), "=r"((r)[3]) : "r"(addr))

#define CPA16(dst, src) \
    asm volatile("cp.async.cg.shared.global [%0], [%1], 16;" :: "r"(dst), "l"(src))
#define CPCOMMIT() asm volatile("cp.async.commit_group;" ::: "memory")

static constexpr int A_STG = 128 * 80;
static constexpr int B_STG = 64 * 80;

template<int MODE>
__global__ void __launch_bounds__(256) gemm_mma(
        const int8_t* __restrict__ A, const int8_t* __restrict__ Bw,
        float* __restrict__ Out, __nv_bfloat16* __restrict__ OutB,
        const float* __restrict__ ascale,
        const float* __restrict__ wscale,
        const float* __restrict__ resid,
        const int* __restrict__ perm,
        const int* __restrict__ seg) {
    int n0 = blockIdx.x * 64;
    int m0 = blockIdx.y * 128;
    int z = blockIdx.z;
    int e = (MODE == 2) ? (z & 7) : z;

    int off = 0, cnt = CT;
    if (MODE >= 2) {
        off = seg[e];
        cnt = seg[e + 1] - off;
        if (m0 >= cnt) return;
    }

    const int8_t* Bz = Bw;
    if (MODE == 0) Bz = Bw + (size_t)z * (CH * CH);
    if (MODE >= 2) Bz = Bw + (size_t)z * ((size_t)CD * CH);
    const int8_t* brow0 = Bz + (size_t)n0 * 1024;

    __shared__ __align__(16) int8_t As[3][128][80];
    __shared__ __align__(16) int8_t Bs[3][64][80];
    __shared__ const int8_t* aptr[128];
    __shared__ float rowsc[128];
    __shared__ int dstrow[128];

    int tid = threadIdx.x;
    if (tid < 128) {
        int r = m0 + tid;
        if (MODE <= 1) {
            aptr[tid] = A + (size_t)r * 1024;
            rowsc[tid] = ascale[r];
        } else if (MODE == 2) {
            int rr = r < cnt - 1 ? r : cnt - 1;
            int tok = perm[off + rr];
            aptr[tid] = A + (size_t)tok * 1024;
            rowsc[tid] = ascale[tok];
            dstrow[tid] = off + r;
        } else {
            int rr = r < cnt - 1 ? r : cnt - 1;
            aptr[tid] = A + (size_t)(off + rr) * 1024;
            rowsc[tid] = ascale[off + rr];
            dstrow[tid] = perm[off + rr];
        }
    }
    __syncthreads();

    int ar = tid >> 1, ao = (tid & 1) * 32;
    int brr = tid >> 2, bo = (tid & 3) * 16;
    const int8_t* pA = aptr[ar];
    const int8_t* pB = brow0 + (size_t)brr * 1024;

    uint32_t As_u = (uint32_t)__cvta_generic_to_shared(&As[0][0][0]);
    uint32_t Bs_u = (uint32_t)__cvta_generic_to_shared(&Bs[0][0][0]);
    uint32_t aSt = As_u + ar * 80 + ao;
    uint32_t bSt = Bs_u + brr * 80 + bo;

    int w = tid >> 5, lane = tid & 31;
    int warpM = w & 3, warpN = w >> 2;
    int gid = lane >> 2, tig = lane & 3;

    int rowA_ld = warpM * 32 + (lane & 7) + ((lane >> 3) & 1) * 8;
    uint32_t aF = As_u + rowA_ld * 80 + (lane >> 4) * 16;
    int rowB_ld = warpN * 32 + (lane & 7) + (lane >> 4) * 8;
    uint32_t bF = Bs_u + rowB_ld * 80 + ((lane >> 3) & 1) * 16;

    int c[2][4][4];
    #pragma unroll
    for (int i = 0; i < 2; i++)
        #pragma unroll
        for (int j = 0; j < 4; j++)
            #pragma unroll
            for (int k = 0; k < 4; k++) c[i][j][k] = 0;

    #pragma unroll
    for (int s = 0; s < 2; s++) {
        uint32_t aD = aSt + s * A_STG;
        CPA16(aD, pA + s * 64 + ao);
        CPA16(aD + 16, pA + s * 64 + ao + 16);
        CPA16(bSt + s * B_STG, pB + s * 64 + bo);
        CPCOMMIT();
    }

    #pragma unroll 1
    for (int kt = 0; kt < 16; kt++) {
        if (kt < 15) {
            asm volatile("cp.async.wait_group 1;" ::: "memory");
        } else {
            asm volatile("cp.async.wait_group 0;" ::: "memory");
        }
        __syncthreads();
        if (kt < 14) {
            int s = kt + 2;
            int b = s % 3;
            uint32_t aD = aSt + b * A_STG;
            CPA16(aD, pA + s * 64 + ao);
            CPA16(aD + 16, pA + s * 64 + ao + 16);
            CPA16(bSt + b * B_STG, pB + s * 64 + bo);
            CPCOMMIT();
        }
        int stg = kt % 3;
        uint32_t aBase = aF + stg * A_STG;
        uint32_t bBase = bF + stg * B_STG;
        #pragma unroll
        for (int ks = 0; ks < 2; ks++) {
            int a0[4], a1[4], b01[4], b23[4];
            LDMX4(a0, aBase + ks * 32);
            LDMX4(a1, aBase + 16 * 80 + ks * 32);
            LDMX4(b01, bBase + ks * 32);
            LDMX4(b23, bBase + 16 * 80 + ks * 32);
            mma_s8(c[0][0], a0, b01 + 0);
            mma_s8(c[0][1], a0, b01 + 2);
            mma_s8(c[0][2], a0, b23 + 0);
            mma_s8(c[0][3], a0, b23 + 2);
            mma_s8(c[1][0], a1, b01 + 0);
            mma_s8(c[1][1], a1, b01 + 2);
            mma_s8(c[1][2], a1, b23 + 0);
            mma_s8(c[1][3], a1, b23 + 2);
        }
        __syncthreads();
    }

    float wS = wscale[(MODE == 0 || MODE >= 2) ? z : 0];

    #pragma unroll
    for (int wm = 0; wm < 2; wm++) {
        int r0 = warpM * 32 + wm * 16 + gid;
        int r1 = r0 + 8;
        float av0 = rowsc[r0] * wS;
        float av1 = rowsc[r1] * wS;
        #pragma unroll
        for (int nt = 0; nt < 4; nt++) {
            int colL = warpN * 32 + nt * 8 + tig * 2;
            int* cc = c[wm][nt];
            if (MODE == 0) {
                int nh = n0 >> 6;
                int gr0 = m0 + r0, gr1 = m0 + r1;
                int b0 = gr0 / CS, sr0 = gr0 % CS;
                int b1 = gr1 / CS, sr1 = gr1 % CS;
                __nv_bfloat16* base = OutB + (size_t)z * ((size_t)CT * CH);
                __nv_bfloat162 o0 = {__float2bfloat16(cc[0] * av0), __float2bfloat16(cc[1] * av0)};
                __nv_bfloat162 o1 = {__float2bfloat16(cc[2] * av1), __float2bfloat16(cc[3] * av1)};
                *(__nv_bfloat162*)(base + (((size_t)b0 * CNH + nh) * CS + sr0) * CHD + colL) = o0;
                *(__nv_bfloat162*)(base + (((size_t)b1 * CNH + nh) * CS + sr1) * CHD + colL) = o1;
            } else if (MODE == 1) {
                size_t rb0 = (size_t)(m0 + r0) * CH + n0 + colL;
                size_t rb1 = (size_t)(m0 + r1) * CH + n0 + colL;
                float2 rv0 = *(const float2*)(resid + rb0);
                float2 rv1 = *(const float2*)(resid + rb1);
                float2 o0 = {rv0.x + cc[0] * av0, rv0.y + cc[1] * av0};
                float2 o1 = {rv1.x + cc[2] * av1, rv1.y + cc[3] * av1};
                *(float2*)(Out + rb0) = o0;
                *(float2*)(Out + rb1) = o1;
            } else if (MODE == 2) {
                size_t half = (size_t)(z >> 3) * ((size_t)CT * CD);
                if (m0 + r0 < cnt) {
                    size_t rb = half + (size_t)dstrow[r0] * CD + n0 + colL;
                    float2 o = {cc[0] * av0, cc[1] * av0};
                    *(float2*)(Out + rb) = o;
                }
                if (m0 + r1 < cnt) {
                    size_t rb = half + (size_t)dstrow[r1] * CD + n0 + colL;
                    float2 o = {cc[2] * av1, cc[3] * av1};
                    *(float2*)(Out + rb) = o;
                }
            } else {
                if (m0 + r0 < cnt) {
                    size_t rb = (size_t)dstrow[r0] * CH + n0 + colL;
                    float2 rv = *(const float2*)(resid + rb);
                    float2 o = {rv.x + cc[0] * av0, rv.y + cc[1] * av0};
                    *(float2*)(Out + rb) = o;
                }
                if (m0 + r1 < cnt) {
                    size_t rb = (size_t)dstrow[r1] * CH + n0 + colL;
                    float2 rv = *(const float2*)(resid + rb);
                    float2 o = {rv.x + cc[2] * av1, rv.y + cc[3] * av1};
                    *(float2*)(Out + rb) = o;
                }
            }
        }
    }
}

// ---------------- attention: FA2-style, causal-balanced, cp.async double-buffered K/V ----------------
__device__ __forceinline__ void mma_bf16(float* c, const uint32_t* a, uint32_t b0, uint32_t b1) {
    asm volatile(
        "mma.sync.aligned.m16n8k16.row.col.f32.bf16.bf16.f32 "
        "{%0,%1,%2,%3}, {%4,%5,%6,%7}, {%8,%9}, {%0,%1,%2,%3};"
        : "+f"(c[0]), "+f"(c[1]), "+f"(c[2]), "+f"(c[3])
        : "r"(a[0]), "r"(a[1]), "r"(a[2]), "r"(a[3]), "r"(b0), "r"(b1));
}

__device__ __forceinline__ void ldmx4t(uint32_t& r0, uint32_t& r1, uint32_t& r2, uint32_t& r3,
                                       uint32_t addr) {
    asm volatile("ldmatrix.sync.aligned.m8n8.x4.trans.shared.b16 {%0,%1,%2,%3}, [%4];"
        : "=r"(r0), "=r"(r1), "=r"(r2), "=r"(r3) : "r"(addr));
}

__device__ __forceinline__ uint32_t pack_bf2(float a, float b) {
    __nv_bfloat162 t = __floats2bfloat162_rn(a, b);
    return *(uint32_t*)&t;
}

static constexpr int KLD = 72;
#define ASCL 0.18033688011112042f   // 0.125 * log2(e)

__global__ void __launch_bounds__(128) attn_fa2(
        const __nv_bfloat16* __restrict__ Qg, const __nv_bfloat16* __restrict__ Kg,
        const __nv_bfloat16* __restrict__ Vg, float* __restrict__ Hout) {
    __shared__ __align__(16) __nv_bfloat16 Ks[2][64][KLD];
    __shared__ __align__(16) __nv_bfloat16 Vs[2][64][KLD];

    int bh = blockIdx.y;
    const __nv_bfloat16* Qb = Qg + (size_t)bh * CS * CHD;
    const __nv_bfloat16* Kb = Kg + (size_t)bh * CS * CHD;
    const __nv_bfloat16* Vb = Vg + (size_t)bh * CS * CHD;

    int tid = threadIdx.x;
    int w = tid >> 5, lane = tid & 31;
    int gid = lane >> 2, tig = lane & 3;

    int b = bh / CNH, nh = bh % CNH;

    // per-thread fixed load slots: 4 chunks of 16B for K and V each
    int lrow[4], lcol[4];
    #pragma unroll
    for (int u = 0; u < 4; u++) {
        int i = tid + u * 128;
        lrow[u] = i >> 3;
        lcol[u] = (i & 7) * 8;
    }

    // causal balancing: q-tiles (31 - blockIdx.x) then blockIdx.x; 33 k-iters total per CTA
    #pragma unroll 1
    for (int rep = 0; rep < 2; rep++) {
        int qb = rep == 0 ? (31 - (int)blockIdx.x) : (int)blockIdx.x;
        int q0 = qb * 64;
        int qr0 = q0 + w * 16 + gid;
        int qr1 = qr0 + 8;

        uint32_t qf[4][4];
        #pragma unroll
        for (int k = 0; k < 4; k++) {
            const __nv_bfloat16* p0 = Qb + (size_t)qr0 * CHD + k * 16 + 2 * tig;
            const __nv_bfloat16* p1 = Qb + (size_t)qr1 * CHD + k * 16 + 2 * tig;
            qf[k][0] = *(const uint32_t*)p0;
            qf[k][1] = *(const uint32_t*)p1;
            qf[k][2] = *(const uint32_t*)(p0 + 8);
            qf[k][3] = *(const uint32_t*)(p1 + 8);
        }

        float o[8][4];
        #pragma unroll
        for (int nt = 0; nt < 8; nt++)
            #pragma unroll
            for (int j = 0; j < 4; j++) o[nt][j] = 0.f;
        float m0 = -INFINITY, m1 = -INFINITY, l0 = 0.f, l1 = 0.f;

        int nkt = qb + 1;

        // prologue: all warps done with previous rep's buffers before refilling
        __syncthreads();
        #pragma unroll
        for (int u = 0; u < 4; u++) {
            CPA16((uint32_t)__cvta_generic_to_shared(&Ks[0][lrow[u]][lcol[u]]),
                  Kb + (size_t)lrow[u] * CHD + lcol[u]);
            CPA16((uint32_t)__cvta_generic_to_shared(&Vs[0][lrow[u]][lcol[u]]),
                  Vb + (size_t)lrow[u] * CHD + lcol[u]);
        }
        CPCOMMIT();

        #pragma unroll 1
        for (int kt = 0; kt < nkt; kt++) {
            int buf = kt & 1;
            asm volatile("cp.async.wait_group 0;" ::: "memory");
            __syncthreads();
            if (kt + 1 < nkt) {
                int k0n = (kt + 1) * 64;
                int nb = buf ^ 1;
                #pragma unroll
                for (int u = 0; u < 4; u++) {
                    CPA16((uint32_t)__cvta_generic_to_shared(&Ks[nb][lrow[u]][lcol[u]]),
                          Kb + (size_t)(k0n + lrow[u]) * CHD + lcol[u]);
                    CPA16((uint32_t)__cvta_generic_to_shared(&Vs[nb][lrow[u]][lcol[u]]),
                          Vb + (size_t)(k0n + lrow[u]) * CHD + lcol[u]);
                }
                CPCOMMIT();
            }
            int k0 = kt * 64;

            float s[8][4];
            #pragma unroll
            for (int nt = 0; nt < 8; nt++)
                #pragma unroll
                for (int j = 0; j < 4; j++) s[nt][j] = 0.f;
            #pragma unroll
            for (int k = 0; k < 4; k++) {
                #pragma unroll
                for (int nt = 0; nt < 8; nt++) {
                    uint32_t b0 = *(const uint32_t*)&Ks[buf][nt * 8 + gid][k * 16 + 2 * tig];
                    uint32_t b1 = *(const uint32_t*)&Ks[buf][nt * 8 + gid][k * 16 + 8 + 2 * tig];
                    mma_bf16(s[nt], qf[k], b0, b1);
                }
            }

            bool diag = (kt == qb);
            float rmax0 = -INFINITY, rmax1 = -INFINITY;
            #pragma unroll
            for (int nt = 0; nt < 8; nt++) {
                int cg = k0 + nt * 8 + 2 * tig;
                #pragma unroll
                for (int j = 0; j < 2; j++) {
                    float v0 = s[nt][j] * ASCL;
                    float v1 = s[nt][2 + j] * ASCL;
                    if (diag && cg + j > qr0) v0 = -INFINITY;
                    if (diag && cg + j > qr1) v1 = -INFINITY;
                    s[nt][j] = v0; s[nt][2 + j] = v1;
                    rmax0 = fmaxf(rmax0, v0); rmax1 = fmaxf(rmax1, v1);
                }
            }
            rmax0 = fmaxf(rmax0, __shfl_xor_sync(0xffffffffu, rmax0, 1));
            rmax0 = fmaxf(rmax0, __shfl_xor_sync(0xffffffffu, rmax0, 2));
            rmax1 = fmaxf(rmax1, __shfl_xor_sync(0xffffffffu, rmax1, 1));
            rmax1 = fmaxf(rmax1, __shfl_xor_sync(0xffffffffu, rmax1, 2));

            float mn0 = fmaxf(m0, rmax0), mn1 = fmaxf(m1, rmax1);
            float sum0 = 0.f, sum1 = 0.f;
            #pragma unroll
            for (int nt = 0; nt < 8; nt++) {
                s[nt][0] = exp2f(s[nt][0] - mn0);
                s[nt][1] = exp2f(s[nt][1] - mn0);
                s[nt][2] = exp2f(s[nt][2] - mn1);
                s[nt][3] = exp2f(s[nt][3] - mn1);
                sum0 += s[nt][0] + s[nt][1];
                sum1 += s[nt][2] + s[nt][3];
            }
            sum0 += __shfl_xor_sync(0xffffffffu, sum0, 1);
            sum0 += __shfl_xor_sync(0xffffffffu, sum0, 2);
            sum1 += __shfl_xor_sync(0xffffffffu, sum1, 1);
            sum1 += __shfl_xor_sync(0xffffffffu, sum1, 2);

            float rs0 = exp2f(m0 - mn0), rs1 = exp2f(m1 - mn1);
            m0 = mn0; m1 = mn1;
            l0 = l0 * rs0 + sum0;
            l1 = l1 * rs1 + sum1;
            #pragma unroll
            for (int nt = 0; nt < 8; nt++) {
                o[nt][0] *= rs0; o[nt][1] *= rs0;
                o[nt][2] *= rs1; o[nt][3] *= rs1;
            }

            #pragma unroll
            for (int kb = 0; kb < 4; kb++) {
                uint32_t pf[4];
                pf[0] = pack_bf2(s[2 * kb][0], s[2 * kb][1]);
                pf[1] = pack_bf2(s[2 * kb][2], s[2 * kb][3]);
                pf[2] = pack_bf2(s[2 * kb + 1][0], s[2 * kb + 1][1]);
                pf[3] = pack_bf2(s[2 * kb + 1][2], s[2 * kb + 1][3]);
                #pragma unroll
                for (int nb = 0; nb < 4; nb++) {
                    uint32_t v0, v1, v2, v3;
                    uint32_t addr = (uint32_t)__cvta_generic_to_shared(
                        &Vs[buf][kb * 16 + (lane & 15)][nb * 16 + ((lane >> 4) << 3)]);
                    ldmx4t(v0, v1, v2, v3, addr);
                    mma_bf16(o[2 * nb], pf, v0, v1);
                    mma_bf16(o[2 * nb + 1], pf, v2, v3);
                }
            }
        }

        float inv0 = 1.0f / l0, inv1 = 1.0f / l1;
        #pragma unroll
        for (int nt = 0; nt < 8; nt++) {
            int col = nt * 8 + 2 * tig;
            float2 w0v = {o[nt][0] * inv0, o[nt][1] * inv0};
            float2 w1v = {o[nt][2] * inv1, o[nt][3] * inv1};
            *(float2*)(Hout + (((size_t)b * CS + qr0) * CNH + nh) * CHD + col) = w0v;
            *(float2*)(Hout + (((size_t)b * CS + qr1) * CNH + nh) * CHD + col) = w1v;
        }
    }
}

// ---------------- MoE elementwise: hh = relu(g)^2 * u, then act_quant ----------------
__global__ void hh_quant(const float* __restrict__ g, const float* __restrict__ u,
                         int8_t* __restrict__ hq, float* __restrict__ hs) {
    __shared__ float red[256];
    __shared__ float hb[CD];
    int slot = blockIdx.x, tid = threadIdx.x;
    float amax = 0.f;
    #pragma unroll
    for (int i = 0; i < 4; i++) {
        int k = tid + i * 256;
        float gv = g[(size_t)slot * CD + k];
        float uv = u[(size_t)slot * CD + k];
        float rl = fmaxf(gv, 0.f);
        float h = rl * rl * uv;
        hb[k] = h;
        amax = fmaxf(amax, fabsf(h));
    }
    amax = blk_reduce_max(amax, red);
    float m = fmaxf(amax, 1e-5f);
    float s = 127.f / m;
    #pragma unroll
    for (int i = 0; i < 4; i++) {
        int k = tid + i * 256;
        float qv = fminf(fmaxf(rintf(hb[k] * s), -128.f), 127.f);
        hq[(size_t)slot * CD + k] = (int8_t)(int)qv;
    }
    if (tid == 0) hs[slot] = m * (1.0f / 127.f);
}

// ---------------- launch (fork-join dual stream) ----------------
extern "C" void kernel_launch(void* const* d_in, const int* in_sizes, int n_in,
                              void* d_out, int out_size) {
    const float* x        = (const float*)d_in[0];
    const float* q_w      = (const float*)d_in[1];
    const float* k_w      = (const float*)d_in[2];
    const float* v_w      = (const float*)d_in[3];
    const float* o_w      = (const float*)d_in[4];
    const float* ln1_w    = (const float*)d_in[5];
    const float* ln2_w    = (const float*)d_in[6];
    const float* router_w = (const float*)d_in[7];
    const float* gate_w   = (const float*)d_in[8];
    const float* up_w     = (const float*)d_in[9];
    const float* down_w   = (const float*)d_in[10];

    unsigned char* base = nullptr;
    cudaGetSymbolAddress((void**)&base, g_scratch);

    int8_t* wq_attn = (int8_t*)(base + OFF_WQ_ATTN);
    int8_t* wq_gate = (int8_t*)(base + OFF_WQ_GATE);
    int8_t* wq_up   = (int8_t*)(base + OFF_WQ_UP);
    int8_t* wq_down = (int8_t*)(base + OFF_WQ_DOWN);
    float*  wsc     = (float*)(base + OFF_WSCALE);
    float*  part    = (float*)(base + OFF_PART);
    int8_t* xq1     = (int8_t*)(base + OFF_XQ1);
    float*  a1s     = (float*)(base + OFF_A1S);
    __nv_bfloat16* qkvb = (__nv_bfloat16*)(base + OFF_QKV);
    float*  hb      = (float*)(base + OFF_HB);
    int8_t* hqa     = (int8_t*)(base + OFF_HQA);
    float*  hsa     = (float*)(base + OFF_HSA);
    float*  x2      = (float*)(base + OFF_X2);
    int8_t* xq2     = (int8_t*)(base + OFF_XQ2);
    float*  a2s     = (float*)(base + OFF_A2S);
    int*    idx     = (int*)(base + OFF_IDX);
    int*    cnt     = (int*)(base + OFF_CNT);
    int*    seg     = (int*)(base + OFF_SEG);
    int*    cur     = (int*)(base + OFF_CUR);
    int*    perm    = (int*)(base + OFF_PERM);
    float*  gb      = (float*)(base + OFF_GB);
    float*  ub      = (float*)(base + OFF_UB);
    int8_t* hqm     = (int8_t*)(base + OFF_HQM);
    float*  hsm     = (float*)(base + OFF_HSM);
    float*  out     = (float*)d_out;

    const int LEN4 = (CH * CH) / 4;

    cudaStream_t s2;
    cudaStreamCreateWithFlags(&s2, cudaStreamNonBlocking);
    cudaEvent_t evFork, evB, evJoin;
    cudaEventCreateWithFlags(&evFork, cudaEventDisableTiming);
    cudaEventCreateWithFlags(&evB, cudaEventDisableTiming);
    cudaEventCreateWithFlags(&evJoin, cudaEventDisableTiming);

    cudaEventRecord(evFork, 0);
    cudaStreamWaitEvent(s2, evFork, 0);

    // ---- side stream: activation quant, then MoE weight quant ----
    rmsnorm_quant<<<CT, 256, 0, s2>>>(x, ln1_w, xq1, a1s);
    cudaEventRecord(evB, s2);
    absmean_partial<<<dim3(256, 8), 256, 0, s2>>>(gate_w, part + 4 * 256, LEN4);
    absmean_partial<<<dim3(256, 8), 256, 0, s2>>>(up_w,   part + 12 * 256, LEN4);
    absmean_partial<<<dim3(256, 8), 256, 0, s2>>>(down_w, part + 20 * 256, LEN4);
    finalize_wscale<<<1, 32, 0, s2>>>(part, wsc, 4, 24);
    quantize_w<<<dim3(256, 8), 256, 0, s2>>>(gate_w, wq_gate, wsc, 4, LEN4);
    quantize_w<<<dim3(256, 8), 256, 0, s2>>>(up_w,   wq_up,   wsc, 12, LEN4);
    quantize_w<<<dim3(256, 8), 256, 0, s2>>>(down_w, wq_down, wsc, 20, LEN4);
    cudaEventRecord(evJoin, s2);

    // ---- main stream: attention weights + attention path ----
    zero_ints<<<1, 32>>>(cnt, cur);
    absmean4<<<dim3(256, 4), 256>>>(q_w, k_w, v_w, o_w, part, LEN4);
    quantizeF4<<<dim3(256, 4), 256>>>(q_w, k_w, v_w, o_w, wq_attn, part, wsc, LEN4);
    cudaStreamWaitEvent(0, evB, 0);
    gemm_mma<0><<<dim3(16, 32, 3), 256>>>(xq1, wq_attn, nullptr, qkvb, a1s, wsc, nullptr, nullptr, nullptr);

    attn_fa2<<<dim3(16, CB * CNH), 128>>>(
        qkvb, qkvb + (size_t)CT * CH, qkvb + 2 * (size_t)CT * CH, hb);

    // ---- o-proj + residual ----
    act_quant_rows<<<CT, 256>>>(hb, hqa, hsa);
    gemm_mma<1><<<dim3(16, 32, 1), 256>>>(hqa, wq_attn + 3 * (CH * CH), x2, nullptr, hsa, wsc + 3, x, nullptr, nullptr);

    // ---- MoE ----
    rmsnorm2_router<<<CT, 256>>>(x2, ln2_w, router_w, xq2, a2s, idx, cnt);
    build_offsets<<<1, 1>>>(cnt, seg);
    scatter_tokens<<<16, 256>>>(idx, seg, cur, perm);

    cudaStreamWaitEvent(0, evJoin, 0);
    gemm_mma<2><<<dim3(16, 32, 16), 256>>>(xq2, wq_gate, gb, nullptr, a2s, wsc + 4, nullptr, perm, seg);
    hh_quant<<<CT, 256>>>(gb, ub, hqm, hsm);
    gemm_mma<3><<<dim3(16, 32, 8), 256>>>(hqm, wq_down, out, nullptr, hsm, wsc + 20, x2, perm, seg);
}

// round 15
// speedup vs baseline: 2.7153x; 1.0054x over previous
#include <cuda_runtime.h>
#include <cuda_bf16.h>
#include <math.h>
#include <stdint.h>

#define CB 2
#define CS 2048
#define CH 1024
#define CNH 16
#define CHD 64
#define CE 8
#define CD 1024
#define CT (CB*CS)

#define MB (1024ull*1024ull)

// ---------------- scratch layout ----------------
static constexpr size_t OFF_WQ_ATTN = 0;
static constexpr size_t OFF_WQ_GATE = 4*MB;
static constexpr size_t OFF_WQ_UP   = 12*MB;
static constexpr size_t OFF_WQ_DOWN = 20*MB;
static constexpr size_t OFF_WSCALE  = 28*MB;
static constexpr size_t OFF_PART    = 28*MB + 4096;
static constexpr size_t OFF_XQ1     = 29*MB;
static constexpr size_t OFF_A1S     = 33*MB;
static constexpr size_t OFF_QKV     = 34*MB;
static constexpr size_t OFF_HB      = 82*MB;
static constexpr size_t OFF_HQA     = 98*MB;
static constexpr size_t OFF_HSA     = 102*MB;
static constexpr size_t OFF_X2      = 103*MB;
static constexpr size_t OFF_XQ2     = 119*MB;
static constexpr size_t OFF_A2S     = 123*MB;
static constexpr size_t OFF_IDX     = 123*MB + 64*1024;
static constexpr size_t OFF_CNT     = 123*MB + 128*1024;
static constexpr size_t OFF_SEG     = 123*MB + 129*1024;
static constexpr size_t OFF_CUR     = 123*MB + 130*1024;
static constexpr size_t OFF_PERM    = 124*MB;
static constexpr size_t OFF_GB      = 125*MB;
static constexpr size_t OFF_UB      = 141*MB;
static constexpr size_t OFF_HQM     = 157*MB;
static constexpr size_t OFF_HSM     = 161*MB;
static constexpr size_t SCRATCH_BYTES = 162*MB;

__device__ __align__(256) unsigned char g_scratch[SCRATCH_BYTES];

// ---------------- reductions ----------------
__device__ __forceinline__ float blk_reduce_sum(float v, float* red) {
    int tid = threadIdx.x;
    red[tid] = v; __syncthreads();
    #pragma unroll
    for (int s = 128; s > 0; s >>= 1) {
        if (tid < s) red[tid] += red[tid + s];
        __syncthreads();
    }
    float r = red[0]; __syncthreads();
    return r;
}

__device__ __forceinline__ float blk_reduce_max(float v, float* red) {
    int tid = threadIdx.x;
    red[tid] = v; __syncthreads();
    #pragma unroll
    for (int s = 128; s > 0; s >>= 1) {
        if (tid < s) red[tid] = fmaxf(red[tid], red[tid + s]);
        __syncthreads();
    }
    float r = red[0]; __syncthreads();
    return r;
}

// ---------------- weight quantization (4x float4 ILP) ----------------
__device__ __forceinline__ float abs4(float4 v) {
    return fabsf(v.x) + fabsf(v.y) + fabsf(v.z) + fabsf(v.w);
}

__global__ void absmean_partial(const float* __restrict__ w, float* __restrict__ part, int len4) {
    __shared__ float red[256];
    const float4* p = (const float4*)w + (size_t)blockIdx.y * len4;
    int i = blockIdx.x * 1024 + threadIdx.x;
    float4 v0 = p[i], v1 = p[i + 256], v2 = p[i + 512], v3 = p[i + 768];
    float s = (abs4(v0) + abs4(v1)) + (abs4(v2) + abs4(v3));
    s = blk_reduce_sum(s, red);
    if (threadIdx.x == 0) part[(size_t)blockIdx.y * gridDim.x + blockIdx.x] = s;
}

__global__ void absmean4(const float* __restrict__ w0, const float* __restrict__ w1,
                         const float* __restrict__ w2, const float* __restrict__ w3,
                         float* __restrict__ part, int len4) {
    __shared__ float red[256];
    int sl = blockIdx.y;
    const float* p = sl == 0 ? w0 : sl == 1 ? w1 : sl == 2 ? w2 : w3;
    const float4* p4 = (const float4*)p;
    int i = blockIdx.x * 1024 + threadIdx.x;
    float4 v0 = p4[i], v1 = p4[i + 256], v2 = p4[i + 512], v3 = p4[i + 768];
    float s = (abs4(v0) + abs4(v1)) + (abs4(v2) + abs4(v3));
    s = blk_reduce_sum(s, red);
    if (threadIdx.x == 0) part[(size_t)sl * gridDim.x + blockIdx.x] = s;
}

__global__ void finalize_wscale(const float* __restrict__ part, float* __restrict__ wsc,
                                int i0, int n) {
    int i = i0 + threadIdx.x;
    if (threadIdx.x >= n) return;
    float s = 0.f;
    for (int j = 0; j < 256; j++) s += part[i * 256 + j];
    wsc[i] = fmaxf(s * (1.0f / (1024.f * 1024.f)), 1e-5f);
}

__device__ __forceinline__ char quant_tern(float v, float s) {
    float q = rintf(v * s);
    q = fminf(fmaxf(q, -1.f), 1.f);
    return (char)(int)q;
}

__device__ __forceinline__ char4 qt4(float4 v, float s) {
    char4 o;
    o.x = quant_tern(v.x, s); o.y = quant_tern(v.y, s);
    o.z = quant_tern(v.z, s); o.w = quant_tern(v.w, s);
    return o;
}

__global__ void quantize_w(const float* __restrict__ w, int8_t* __restrict__ wq,
                           const float* __restrict__ wsc, int widx0, int len4) {
    int slice = blockIdx.y;
    float s = 1.0f / wsc[widx0 + slice];
    const float4* p = (const float4*)w + (size_t)slice * len4;
    char4* q = (char4*)wq + (size_t)slice * len4;
    int i = blockIdx.x * 1024 + threadIdx.x;
    float4 v0 = p[i], v1 = p[i + 256], v2 = p[i + 512], v3 = p[i + 768];
    q[i] = qt4(v0, s); q[i + 256] = qt4(v1, s);
    q[i + 512] = qt4(v2, s); q[i + 768] = qt4(v3, s);
}

__global__ void quantizeF4(const float* __restrict__ w0, const float* __restrict__ w1,
                           const float* __restrict__ w2, const float* __restrict__ w3,
                           int8_t* __restrict__ wq, const float* __restrict__ part,
                           float* __restrict__ wsc, int len4) {
    __shared__ float red[256];
    int sl = blockIdx.y;
    int tid = threadIdx.x;
    float total = blk_reduce_sum(part[sl * 256 + tid], red);
    float mean = fmaxf(total * (1.0f / (1024.f * 1024.f)), 1e-5f);
    if (blockIdx.x == 0 && tid == 0) wsc[sl] = mean;
    float s = 1.0f / mean;
    const float* p = sl == 0 ? w0 : sl == 1 ? w1 : sl == 2 ? w2 : w3;
    const float4* p4 = (const float4*)p;
    char4* q = (char4*)wq + (size_t)sl * len4;
    int i = blockIdx.x * 1024 + tid;
    float4 v0 = p4[i], v1 = p4[i + 256], v2 = p4[i + 512], v3 = p4[i + 768];
    q[i] = qt4(v0, s); q[i + 256] = qt4(v1, s);
    q[i + 512] = qt4(v2, s); q[i + 768] = qt4(v3, s);
}

// ---------------- activation rmsnorm + quant ----------------
__global__ void rmsnorm_quant(const float* __restrict__ x, const float* __restrict__ lnw,
                              int8_t* __restrict__ xq, float* __restrict__ ainv) {
    __shared__ float red[256];
    __shared__ float xs[CH];
    int t = blockIdx.x, tid = threadIdx.x;
    const float* xr = x + (size_t)t * CH;
    float v[4]; float ss = 0.f;
    #pragma unroll
    for (int i = 0; i < 4; i++) { v[i] = xr[tid + i * 256]; ss += v[i] * v[i]; }
    ss = blk_reduce_sum(ss, red);
    float r = rsqrtf(ss * (1.0f / CH) + 1e-5f);
    float amax = 0.f;
    #pragma unroll
    for (int i = 0; i < 4; i++) {
        float xn = v[i] * r * lnw[tid + i * 256];
        xs[tid + i * 256] = xn;
        amax = fmaxf(amax, fabsf(xn));
    }
    amax = blk_reduce_max(amax, red);
    float m = fmaxf(amax, 1e-5f);
    float s = 127.f / m;
    #pragma unroll
    for (int i = 0; i < 4; i++) {
        float qv = fminf(fmaxf(rintf(xs[tid + i * 256] * s), -128.f), 127.f);
        xq[(size_t)t * CH + tid + i * 256] = (int8_t)(int)qv;
    }
    if (tid == 0) ainv[t] = m * (1.0f / 127.f);
}

__global__ void act_quant_rows(const float* __restrict__ x, int8_t* __restrict__ xq,
                               float* __restrict__ ainv) {
    __shared__ float red[256];
    int t = blockIdx.x, tid = threadIdx.x;
    const float* xr = x + (size_t)t * CH;
    float v[4]; float amax = 0.f;
    #pragma unroll
    for (int i = 0; i < 4; i++) { v[i] = xr[tid + i * 256]; amax = fmaxf(amax, fabsf(v[i])); }
    amax = blk_reduce_max(amax, red);
    float m = fmaxf(amax, 1e-5f);
    float s = 127.f / m;
    #pragma unroll
    for (int i = 0; i < 4; i++) {
        float qv = fminf(fmaxf(rintf(v[i] * s), -128.f), 127.f);
        xq[(size_t)t * CH + tid + i * 256] = (int8_t)(int)qv;
    }
    if (tid == 0) ainv[t] = m * (1.0f / 127.f);
}

__global__ void rmsnorm2_router(const float* __restrict__ x, const float* __restrict__ lnw,
                                const float* __restrict__ rw, int8_t* __restrict__ xq,
                                float* __restrict__ ainv, int* __restrict__ idx,
                                int* __restrict__ counts) {
    __shared__ float red[256];
    __shared__ float xs[CH];
    __shared__ float logits[CE];
    int t = blockIdx.x, tid = threadIdx.x;
    const float* xr = x + (size_t)t * CH;
    float v[4]; float ss = 0.f;
    #pragma unroll
    for (int i = 0; i < 4; i++) { v[i] = xr[tid + i * 256]; ss += v[i] * v[i]; }
    ss = blk_reduce_sum(ss, red);
    float r = rsqrtf(ss * (1.0f / CH) + 1e-5f);
    float amax = 0.f;
    #pragma unroll
    for (int i = 0; i < 4; i++) {
        float xn = v[i] * r * lnw[tid + i * 256];
        xs[tid + i * 256] = xn;
        amax = fmaxf(amax, fabsf(xn));
    }
    amax = blk_reduce_max(amax, red);
    float m = fmaxf(amax, 1e-5f);
    float s = 127.f / m;
    #pragma unroll
    for (int i = 0; i < 4; i++) {
        float qv = fminf(fmaxf(rintf(xs[tid + i * 256] * s), -128.f), 127.f);
        xq[(size_t)t * CH + tid + i * 256] = (int8_t)(int)qv;
    }
    if (tid == 0) ainv[t] = m * (1.0f / 127.f);
    __syncthreads();

    int w = tid >> 5, lane = tid & 31;
    float acc = 0.f;
    for (int h = lane; h < CH; h += 32) acc += xs[h] * rw[w * CH + h];
    #pragma unroll
    for (int o = 16; o > 0; o >>= 1) acc += __shfl_down_sync(0xffffffffu, acc, o);
    if (lane == 0) logits[w] = acc;
    __syncthreads();
    if (tid == 0) {
        float best = logits[0]; int bi = 0;
        #pragma unroll
        for (int e = 1; e < CE; e++) if (logits[e] > best) { best = logits[e]; bi = e; }
        idx[t] = bi;
        atomicAdd(&counts[bi], 1);
    }
}

__global__ void zero_ints(int* __restrict__ counts, int* __restrict__ cursor) {
    if (threadIdx.x < CE) { counts[threadIdx.x] = 0; cursor[threadIdx.x] = 0; }
}

__global__ void build_offsets(const int* __restrict__ counts, int* __restrict__ seg) {
    if (threadIdx.x == 0) {
        int a = 0;
        for (int e = 0; e < CE; e++) { seg[e] = a; a += counts[e]; }
        seg[CE] = a;
    }
}

__global__ void scatter_tokens(const int* __restrict__ idx, const int* __restrict__ seg,
                               int* __restrict__ cursor, int* __restrict__ perm) {
    int t = blockIdx.x * 256 + threadIdx.x;
    if (t >= CT) return;
    int e = idx[t];
    int p = atomicAdd(&cursor[e], 1);
    perm[seg[e] + p] = t;
}

// ---------------- int8 x ternary GEMM: mma.sync + ldmatrix + cp.async (3-stage) ----------------
__device__ __forceinline__ void mma_s8(int* c, const int* a, const int* b) {
    asm volatile(
        "mma.sync.aligned.m16n8k32.row.col.s32.s8.s8.s32 "
        "{%0,%1,%2,%3}, {%4,%5,%6,%7}, {%8,%9}, {%0,%1,%2,%3};"
        : "+r"(c[0]), "+r"(c[1]), "+r"(c[2]), "+r"(c[3])
        : "r"(a[0]), "r"(a[1]), "r"(a[2]), "r"(a[3]), "r"(b[0]), "r"(b[1]));
}

#define LDMX4(r, addr) \
    asm volatile("ldmatrix.sync.aligned.m8n8.x4.shared.b16 {%0,%1,%2,%3}, [%4];" \
        : "=r"((r)[0]), "=r"((r)[1]), "=r"((r)[2]), "=r"((r)[3]) : "r"(addr))

#define CPA16(dst, src) \
    asm volatile("cp.async.cg.shared.global [%0], [%1], 16;" :: "r"(dst), "l"(src))
#define CPCOMMIT() asm volatile("cp.async.commit_group;" ::: "memory")

static constexpr int A_STG = 128 * 80;
static constexpr int B_STG = 64 * 80;

template<int MODE>
__global__ void __launch_bounds__(256) gemm_mma(
        const int8_t* __restrict__ A, const int8_t* __restrict__ Bw,
        float* __restrict__ Out, __nv_bfloat16* __restrict__ OutB,
        const float* __restrict__ ascale,
        const float* __restrict__ wscale,
        const float* __restrict__ resid,
        const int* __restrict__ perm,
        const int* __restrict__ seg) {
    int n0 = blockIdx.x * 64;
    int m0 = blockIdx.y * 128;
    int z = blockIdx.z;
    int e = (MODE == 2) ? (z & 7) : z;

    int off = 0, cnt = CT;
    if (MODE >= 2) {
        off = seg[e];
        cnt = seg[e + 1] - off;
        if (m0 >= cnt) return;
    }

    const int8_t* Bz = Bw;
    if (MODE == 0) Bz = Bw + (size_t)z * (CH * CH);
    if (MODE >= 2) Bz = Bw + (size_t)z * ((size_t)CD * CH);
    const int8_t* brow0 = Bz + (size_t)n0 * 1024;

    __shared__ __align__(16) int8_t As[3][128][80];
    __shared__ __align__(16) int8_t Bs[3][64][80];
    __shared__ const int8_t* aptr[128];
    __shared__ float rowsc[128];
    __shared__ int dstrow[128];

    int tid = threadIdx.x;
    if (tid < 128) {
        int r = m0 + tid;
        if (MODE <= 1) {
            aptr[tid] = A + (size_t)r * 1024;
            rowsc[tid] = ascale[r];
        } else if (MODE == 2) {
            int rr = r < cnt - 1 ? r : cnt - 1;
            int tok = perm[off + rr];
            aptr[tid] = A + (size_t)tok * 1024;
            rowsc[tid] = ascale[tok];
            dstrow[tid] = off + r;
        } else {
            int rr = r < cnt - 1 ? r : cnt - 1;
            aptr[tid] = A + (size_t)(off + rr) * 1024;
            rowsc[tid] = ascale[off + rr];
            dstrow[tid] = perm[off + rr];
        }
    }
    __syncthreads();

    int ar = tid >> 1, ao = (tid & 1) * 32;
    int brr = tid >> 2, bo = (tid & 3) * 16;
    const int8_t* pA = aptr[ar];
    const int8_t* pB = brow0 + (size_t)brr * 1024;

    uint32_t As_u = (uint32_t)__cvta_generic_to_shared(&As[0][0][0]);
    uint32_t Bs_u = (uint32_t)__cvta_generic_to_shared(&Bs[0][0][0]);
    uint32_t aSt = As_u + ar * 80 + ao;
    uint32_t bSt = Bs_u + brr * 80 + bo;

    int w = tid >> 5, lane = tid & 31;
    int warpM = w & 3, warpN = w >> 2;
    int gid = lane >> 2, tig = lane & 3;

    int rowA_ld = warpM * 32 + (lane & 7) + ((lane >> 3) & 1) * 8;
    uint32_t aF = As_u + rowA_ld * 80 + (lane >> 4) * 16;
    int rowB_ld = warpN * 32 + (lane & 7) + (lane >> 4) * 8;
    uint32_t bF = Bs_u + rowB_ld * 80 + ((lane >> 3) & 1) * 16;

    int c[2][4][4];
    #pragma unroll
    for (int i = 0; i < 2; i++)
        #pragma unroll
        for (int j = 0; j < 4; j++)
            #pragma unroll
            for (int k = 0; k < 4; k++) c[i][j][k] = 0;

    #pragma unroll
    for (int s = 0; s < 2; s++) {
        uint32_t aD = aSt + s * A_STG;
        CPA16(aD, pA + s * 64 + ao);
        CPA16(aD + 16, pA + s * 64 + ao + 16);
        CPA16(bSt + s * B_STG, pB + s * 64 + bo);
        CPCOMMIT();
    }

    #pragma unroll 1
    for (int kt = 0; kt < 16; kt++) {
        if (kt < 15) {
            asm volatile("cp.async.wait_group 1;" ::: "memory");
        } else {
            asm volatile("cp.async.wait_group 0;" ::: "memory");
        }
        // head barrier: (a) makes all threads' cp.async for the current stage
        // visible, (b) proves everyone finished computing on the buffer the
        // next prefetch below will overwrite — tail barrier is redundant.
        __syncthreads();
        if (kt < 14) {
            int s = kt + 2;
            int b = s % 3;
            uint32_t aD = aSt + b * A_STG;
            CPA16(aD, pA + s * 64 + ao);
            CPA16(aD + 16, pA + s * 64 + ao + 16);
            CPA16(bSt + b * B_STG, pB + s * 64 + bo);
            CPCOMMIT();
        }
        int stg = kt % 3;
        uint32_t aBase = aF + stg * A_STG;
        uint32_t bBase = bF + stg * B_STG;
        #pragma unroll
        for (int ks = 0; ks < 2; ks++) {
            int a0[4], a1[4], b01[4], b23[4];
            LDMX4(a0, aBase + ks * 32);
            LDMX4(a1, aBase + 16 * 80 + ks * 32);
            LDMX4(b01, bBase + ks * 32);
            LDMX4(b23, bBase + 16 * 80 + ks * 32);
            mma_s8(c[0][0], a0, b01 + 0);
            mma_s8(c[0][1], a0, b01 + 2);
            mma_s8(c[0][2], a0, b23 + 0);
            mma_s8(c[0][3], a0, b23 + 2);
            mma_s8(c[1][0], a1, b01 + 0);
            mma_s8(c[1][1], a1, b01 + 2);
            mma_s8(c[1][2], a1, b23 + 0);
            mma_s8(c[1][3], a1, b23 + 2);
        }
    }

    float wS = wscale[(MODE == 0 || MODE >= 2) ? z : 0];

    #pragma unroll
    for (int wm = 0; wm < 2; wm++) {
        int r0 = warpM * 32 + wm * 16 + gid;
        int r1 = r0 + 8;
        float av0 = rowsc[r0] * wS;
        float av1 = rowsc[r1] * wS;
        #pragma unroll
        for (int nt = 0; nt < 4; nt++) {
            int colL = warpN * 32 + nt * 8 + tig * 2;
            int* cc = c[wm][nt];
            if (MODE == 0) {
                int nh = n0 >> 6;
                int gr0 = m0 + r0, gr1 = m0 + r1;
                int b0 = gr0 / CS, sr0 = gr0 % CS;
                int b1 = gr1 / CS, sr1 = gr1 % CS;
                __nv_bfloat16* base = OutB + (size_t)z * ((size_t)CT * CH);
                __nv_bfloat162 o0 = {__float2bfloat16(cc[0] * av0), __float2bfloat16(cc[1] * av0)};
                __nv_bfloat162 o1 = {__float2bfloat16(cc[2] * av1), __float2bfloat16(cc[3] * av1)};
                *(__nv_bfloat162*)(base + (((size_t)b0 * CNH + nh) * CS + sr0) * CHD + colL) = o0;
                *(__nv_bfloat162*)(base + (((size_t)b1 * CNH + nh) * CS + sr1) * CHD + colL) = o1;
            } else if (MODE == 1) {
                size_t rb0 = (size_t)(m0 + r0) * CH + n0 + colL;
                size_t rb1 = (size_t)(m0 + r1) * CH + n0 + colL;
                float2 rv0 = *(const float2*)(resid + rb0);
                float2 rv1 = *(const float2*)(resid + rb1);
                float2 o0 = {rv0.x + cc[0] * av0, rv0.y + cc[1] * av0};
                float2 o1 = {rv1.x + cc[2] * av1, rv1.y + cc[3] * av1};
                *(float2*)(Out + rb0) = o0;
                *(float2*)(Out + rb1) = o1;
            } else if (MODE == 2) {
                size_t half = (size_t)(z >> 3) * ((size_t)CT * CD);
                if (m0 + r0 < cnt) {
                    size_t rb = half + (size_t)dstrow[r0] * CD + n0 + colL;
                    float2 o = {cc[0] * av0, cc[1] * av0};
                    *(float2*)(Out + rb) = o;
                }
                if (m0 + r1 < cnt) {
                    size_t rb = half + (size_t)dstrow[r1] * CD + n0 + colL;
                    float2 o = {cc[2] * av1, cc[3] * av1};
                    *(float2*)(Out + rb) = o;
                }
            } else {
                if (m0 + r0 < cnt) {
                    size_t rb = (size_t)dstrow[r0] * CH + n0 + colL;
                    float2 rv = *(const float2*)(resid + rb);
                    float2 o = {rv.x + cc[0] * av0, rv.y + cc[1] * av0};
                    *(float2*)(Out + rb) = o;
                }
                if (m0 + r1 < cnt) {
                    size_t rb = (size_t)dstrow[r1] * CH + n0 + colL;
                    float2 rv = *(const float2*)(resid + rb);
                    float2 o = {rv.x + cc[2] * av1, rv.y + cc[3] * av1};
                    *(float2*)(Out + rb) = o;
                }
            }
        }
    }
}

// ---------------- attention: FA2-style, causal-balanced, cp.async double-buffered K/V ----------------
__device__ __forceinline__ void mma_bf16(float* c, const uint32_t* a, uint32_t b0, uint32_t b1) {
    asm volatile(
        "mma.sync.aligned.m16n8k16.row.col.f32.bf16.bf16.f32 "
        "{%0,%1,%2,%3}, {%4,%5,%6,%7}, {%8,%9}, {%0,%1,%2,%3};"
        : "+f"(c[0]), "+f"(c[1]), "+f"(c[2]), "+f"(c[3])
        : "r"(a[0]), "r"(a[1]), "r"(a[2]), "r"(a[3]), "r"(b0), "r"(b1));
}

__device__ __forceinline__ void ldmx4t(uint32_t& r0, uint32_t& r1, uint32_t& r2, uint32_t& r3,
                                       uint32_t addr) {
    asm volatile("ldmatrix.sync.aligned.m8n8.x4.trans.shared.b16 {%0,%1,%2,%3}, [%4];"
        : "=r"(r0), "=r"(r1), "=r"(r2), "=r"(r3) : "r"(addr));
}

__device__ __forceinline__ uint32_t pack_bf2(float a, float b) {
    __nv_bfloat162 t = __floats2bfloat162_rn(a, b);
    return *(uint32_t*)&t;
}

static constexpr int KLD = 72;
#define ASCL 0.18033688011112042f   // 0.125 * log2(e)

__global__ void __launch_bounds__(128) attn_fa2(
        const __nv_bfloat16* __restrict__ Qg, const __nv_bfloat16* __restrict__ Kg,
        const __nv_bfloat16* __restrict__ Vg, float* __restrict__ Hout) {
    __shared__ __align__(16) __nv_bfloat16 Ks[2][64][KLD];
    __shared__ __align__(16) __nv_bfloat16 Vs[2][64][KLD];

    int bh = blockIdx.y;
    const __nv_bfloat16* Qb = Qg + (size_t)bh * CS * CHD;
    const __nv_bfloat16* Kb = Kg + (size_t)bh * CS * CHD;
    const __nv_bfloat16* Vb = Vg + (size_t)bh * CS * CHD;

    int tid = threadIdx.x;
    int w = tid >> 5, lane = tid & 31;
    int gid = lane >> 2, tig = lane & 3;

    int b = bh / CNH, nh = bh % CNH;

    int lrow[4], lcol[4];
    #pragma unroll
    for (int u = 0; u < 4; u++) {
        int i = tid + u * 128;
        lrow[u] = i >> 3;
        lcol[u] = (i & 7) * 8;
    }

    #pragma unroll 1
    for (int rep = 0; rep < 2; rep++) {
        int qb = rep == 0 ? (31 - (int)blockIdx.x) : (int)blockIdx.x;
        int q0 = qb * 64;
        int qr0 = q0 + w * 16 + gid;
        int qr1 = qr0 + 8;

        uint32_t qf[4][4];
        #pragma unroll
        for (int k = 0; k < 4; k++) {
            const __nv_bfloat16* p0 = Qb + (size_t)qr0 * CHD + k * 16 + 2 * tig;
            const __nv_bfloat16* p1 = Qb + (size_t)qr1 * CHD + k * 16 + 2 * tig;
            qf[k][0] = *(const uint32_t*)p0;
            qf[k][1] = *(const uint32_t*)p1;
            qf[k][2] = *(const uint32_t*)(p0 + 8);
            qf[k][3] = *(const uint32_t*)(p1 + 8);
        }

        float o[8][4];
        #pragma unroll
        for (int nt = 0; nt < 8; nt++)
            #pragma unroll
            for (int j = 0; j < 4; j++) o[nt][j] = 0.f;
        float m0 = -INFINITY, m1 = -INFINITY, l0 = 0.f, l1 = 0.f;

        int nkt = qb + 1;

        __syncthreads();
        #pragma unroll
        for (int u = 0; u < 4; u++) {
            CPA16((uint32_t)__cvta_generic_to_shared(&Ks[0][lrow[u]][lcol[u]]),
                  Kb + (size_t)lrow[u] * CHD + lcol[u]);
            CPA16((uint32_t)__cvta_generic_to_shared(&Vs[0][lrow[u]][lcol[u]]),
                  Vb + (size_t)lrow[u] * CHD + lcol[u]);
        }
        CPCOMMIT();

        #pragma unroll 1
        for (int kt = 0; kt < nkt; kt++) {
            int buf = kt & 1;
            asm volatile("cp.async.wait_group 0;" ::: "memory");
            __syncthreads();
            if (kt + 1 < nkt) {
                int k0n = (kt + 1) * 64;
                int nb = buf ^ 1;
                #pragma unroll
                for (int u = 0; u < 4; u++) {
                    CPA16((uint32_t)__cvta_generic_to_shared(&Ks[nb][lrow[u]][lcol[u]]),
                          Kb + (size_t)(k0n + lrow[u]) * CHD + lcol[u]);
                    CPA16((uint32_t)__cvta_generic_to_shared(&Vs[nb][lrow[u]][lcol[u]]),
                          Vb + (size_t)(k0n + lrow[u]) * CHD + lcol[u]);
                }
                CPCOMMIT();
            }
            int k0 = kt * 64;

            float s[8][4];
            #pragma unroll
            for (int nt = 0; nt < 8; nt++)
                #pragma unroll
                for (int j = 0; j < 4; j++) s[nt][j] = 0.f;
            #pragma unroll
            for (int k = 0; k < 4; k++) {
                #pragma unroll
                for (int nt = 0; nt < 8; nt++) {
                    uint32_t b0 = *(const uint32_t*)&Ks[buf][nt * 8 + gid][k * 16 + 2 * tig];
                    uint32_t b1 = *(const uint32_t*)&Ks[buf][nt * 8 + gid][k * 16 + 8 + 2 * tig];
                    mma_bf16(s[nt], qf[k], b0, b1);
                }
            }

            bool diag = (kt == qb);
            float rmax0 = -INFINITY, rmax1 = -INFINITY;
            #pragma unroll
            for (int nt = 0; nt < 8; nt++) {
                int cg = k0 + nt * 8 + 2 * tig;
                #pragma unroll
                for (int j = 0; j < 2; j++) {
                    float v0 = s[nt][j] * ASCL;
                    float v1 = s[nt][2 + j] * ASCL;
                    if (diag && cg + j > qr0) v0 = -INFINITY;
                    if (diag && cg + j > qr1) v1 = -INFINITY;
                    s[nt][j] = v0; s[nt][2 + j] = v1;
                    rmax0 = fmaxf(rmax0, v0); rmax1 = fmaxf(rmax1, v1);
                }
            }
            rmax0 = fmaxf(rmax0, __shfl_xor_sync(0xffffffffu, rmax0, 1));
            rmax0 = fmaxf(rmax0, __shfl_xor_sync(0xffffffffu, rmax0, 2));
            rmax1 = fmaxf(rmax1, __shfl_xor_sync(0xffffffffu, rmax1, 1));
            rmax1 = fmaxf(rmax1, __shfl_xor_sync(0xffffffffu, rmax1, 2));

            float mn0 = fmaxf(m0, rmax0), mn1 = fmaxf(m1, rmax1);
            float sum0 = 0.f, sum1 = 0.f;
            #pragma unroll
            for (int nt = 0; nt < 8; nt++) {
                s[nt][0] = exp2f(s[nt][0] - mn0);
                s[nt][1] = exp2f(s[nt][1] - mn0);
                s[nt][2] = exp2f(s[nt][2] - mn1);
                s[nt][3] = exp2f(s[nt][3] - mn1);
                sum0 += s[nt][0] + s[nt][1];
                sum1 += s[nt][2] + s[nt][3];
            }
            sum0 += __shfl_xor_sync(0xffffffffu, sum0, 1);
            sum0 += __shfl_xor_sync(0xffffffffu, sum0, 2);
            sum1 += __shfl_xor_sync(0xffffffffu, sum1, 1);
            sum1 += __shfl_xor_sync(0xffffffffu, sum1, 2);

            float rs0 = exp2f(m0 - mn0), rs1 = exp2f(m1 - mn1);
            m0 = mn0; m1 = mn1;
            l0 = l0 * rs0 + sum0;
            l1 = l1 * rs1 + sum1;
            #pragma unroll
            for (int nt = 0; nt < 8; nt++) {
                o[nt][0] *= rs0; o[nt][1] *= rs0;
                o[nt][2] *= rs1; o[nt][3] *= rs1;
            }

            #pragma unroll
            for (int kb = 0; kb < 4; kb++) {
                uint32_t pf[4];
                pf[0] = pack_bf2(s[2 * kb][0], s[2 * kb][1]);
                pf[1] = pack_bf2(s[2 * kb][2], s[2 * kb][3]);
                pf[2] = pack_bf2(s[2 * kb + 1][0], s[2 * kb + 1][1]);
                pf[3] = pack_bf2(s[2 * kb + 1][2], s[2 * kb + 1][3]);
                #pragma unroll
                for (int nb = 0; nb < 4; nb++) {
                    uint32_t v0, v1, v2, v3;
                    uint32_t addr = (uint32_t)__cvta_generic_to_shared(
                        &Vs[buf][kb * 16 + (lane & 15)][nb * 16 + ((lane >> 4) << 3)]);
                    ldmx4t(v0, v1, v2, v3, addr);
                    mma_bf16(o[2 * nb], pf, v0, v1);
                    mma_bf16(o[2 * nb + 1], pf, v2, v3);
                }
            }
        }

        float inv0 = 1.0f / l0, inv1 = 1.0f / l1;
        #pragma unroll
        for (int nt = 0; nt < 8; nt++) {
            int col = nt * 8 + 2 * tig;
            float2 w0v = {o[nt][0] * inv0, o[nt][1] * inv0};
            float2 w1v = {o[nt][2] * inv1, o[nt][3] * inv1};
            *(float2*)(Hout + (((size_t)b * CS + qr0) * CNH + nh) * CHD + col) = w0v;
            *(float2*)(Hout + (((size_t)b * CS + qr1) * CNH + nh) * CHD + col) = w1v;
        }
    }
}

// ---------------- MoE elementwise: hh = relu(g)^2 * u, then act_quant ----------------
__global__ void hh_quant(const float* __restrict__ g, const float* __restrict__ u,
                         int8_t* __restrict__ hq, float* __restrict__ hs) {
    __shared__ float red[256];
    __shared__ float hb[CD];
    int slot = blockIdx.x, tid = threadIdx.x;
    float amax = 0.f;
    #pragma unroll
    for (int i = 0; i < 4; i++) {
        int k = tid + i * 256;
        float gv = g[(size_t)slot * CD + k];
        float uv = u[(size_t)slot * CD + k];
        float rl = fmaxf(gv, 0.f);
        float h = rl * rl * uv;
        hb[k] = h;
        amax = fmaxf(amax, fabsf(h));
    }
    amax = blk_reduce_max(amax, red);
    float m = fmaxf(amax, 1e-5f);
    float s = 127.f / m;
    #pragma unroll
    for (int i = 0; i < 4; i++) {
        int k = tid + i * 256;
        float qv = fminf(fmaxf(rintf(hb[k] * s), -128.f), 127.f);
        hq[(size_t)slot * CD + k] = (int8_t)(int)qv;
    }
    if (tid == 0) hs[slot] = m * (1.0f / 127.f);
}

// ---------------- launch (fork-join dual stream) ----------------
extern "C" void kernel_launch(void* const* d_in, const int* in_sizes, int n_in,
                              void* d_out, int out_size) {
    const float* x        = (const float*)d_in[0];
    const float* q_w      = (const float*)d_in[1];
    const float* k_w      = (const float*)d_in[2];
    const float* v_w      = (const float*)d_in[3];
    const float* o_w      = (const float*)d_in[4];
    const float* ln1_w    = (const float*)d_in[5];
    const float* ln2_w    = (const float*)d_in[6];
    const float* router_w = (const float*)d_in[7];
    const float* gate_w   = (const float*)d_in[8];
    const float* up_w     = (const float*)d_in[9];
    const float* down_w   = (const float*)d_in[10];

    unsigned char* base = nullptr;
    cudaGetSymbolAddress((void**)&base, g_scratch);

    int8_t* wq_attn = (int8_t*)(base + OFF_WQ_ATTN);
    int8_t* wq_gate = (int8_t*)(base + OFF_WQ_GATE);
    int8_t* wq_up   = (int8_t*)(base + OFF_WQ_UP);
    int8_t* wq_down = (int8_t*)(base + OFF_WQ_DOWN);
    float*  wsc     = (float*)(base + OFF_WSCALE);
    float*  part    = (float*)(base + OFF_PART);
    int8_t* xq1     = (int8_t*)(base + OFF_XQ1);
    float*  a1s     = (float*)(base + OFF_A1S);
    __nv_bfloat16* qkvb = (__nv_bfloat16*)(base + OFF_QKV);
    float*  hb      = (float*)(base + OFF_HB);
    int8_t* hqa     = (int8_t*)(base + OFF_HQA);
    float*  hsa     = (float*)(base + OFF_HSA);
    float*  x2      = (float*)(base + OFF_X2);
    int8_t* xq2     = (int8_t*)(base + OFF_XQ2);
    float*  a2s     = (float*)(base + OFF_A2S);
    int*    idx     = (int*)(base + OFF_IDX);
    int*    cnt     = (int*)(base + OFF_CNT);
    int*    seg     = (int*)(base + OFF_SEG);
    int*    cur     = (int*)(base + OFF_CUR);
    int*    perm    = (int*)(base + OFF_PERM);
    float*  gb      = (float*)(base + OFF_GB);
    float*  ub      = (float*)(base + OFF_UB);
    int8_t* hqm     = (int8_t*)(base + OFF_HQM);
    float*  hsm     = (float*)(base + OFF_HSM);
    float*  out     = (float*)d_out;

    const int LEN4 = (CH * CH) / 4;

    cudaStream_t s2;
    cudaStreamCreateWithFlags(&s2, cudaStreamNonBlocking);
    cudaEvent_t evFork, evB, evJoin;
    cudaEventCreateWithFlags(&evFork, cudaEventDisableTiming);
    cudaEventCreateWithFlags(&evB, cudaEventDisableTiming);
    cudaEventCreateWithFlags(&evJoin, cudaEventDisableTiming);

    cudaEventRecord(evFork, 0);
    cudaStreamWaitEvent(s2, evFork, 0);

    // ---- side stream: counter zeroing + activation quant + MoE weight quant ----
    // zero_ints ordering to rmsnorm2_router is transitive: zero -> rmsnorm_quant
    // -> evB -> (main waits) gemm<0> -> ... -> router.
    zero_ints<<<1, 32, 0, s2>>>(cnt, cur);
    rmsnorm_quant<<<CT, 256, 0, s2>>>(x, ln1_w, xq1, a1s);
    cudaEventRecord(evB, s2);
    absmean_partial<<<dim3(256, 8), 256, 0, s2>>>(gate_w, part + 4 * 256, LEN4);
    absmean_partial<<<dim3(256, 8), 256, 0, s2>>>(up_w,   part + 12 * 256, LEN4);
    absmean_partial<<<dim3(256, 8), 256, 0, s2>>>(down_w, part + 20 * 256, LEN4);
    finalize_wscale<<<1, 32, 0, s2>>>(part, wsc, 4, 24);
    quantize_w<<<dim3(256, 8), 256, 0, s2>>>(gate_w, wq_gate, wsc, 4, LEN4);
    quantize_w<<<dim3(256, 8), 256, 0, s2>>>(up_w,   wq_up,   wsc, 12, LEN4);
    quantize_w<<<dim3(256, 8), 256, 0, s2>>>(down_w, wq_down, wsc, 20, LEN4);
    cudaEventRecord(evJoin, s2);

    // ---- main stream: attention weights + attention path ----
    absmean4<<<dim3(256, 4), 256>>>(q_w, k_w, v_w, o_w, part, LEN4);
    quantizeF4<<<dim3(256, 4), 256>>>(q_w, k_w, v_w, o_w, wq_attn, part, wsc, LEN4);
    cudaStreamWaitEvent(0, evB, 0);
    gemm_mma<0><<<dim3(16, 32, 3), 256>>>(xq1, wq_attn, nullptr, qkvb, a1s, wsc, nullptr, nullptr, nullptr);

    attn_fa2<<<dim3(16, CB * CNH), 128>>>(
        qkvb, qkvb + (size_t)CT * CH, qkvb + 2 * (size_t)CT * CH, hb);

    // ---- o-proj + residual ----
    act_quant_rows<<<CT, 256>>>(hb, hqa, hsa);
    gemm_mma<1><<<dim3(16, 32, 1), 256>>>(hqa, wq_attn + 3 * (CH * CH), x2, nullptr, hsa, wsc + 3, x, nullptr, nullptr);

    // ---- MoE ----
    rmsnorm2_router<<<CT, 256>>>(x2, ln2_w, router_w, xq2, a2s, idx, cnt);
    build_offsets<<<1, 1>>>(cnt, seg);
    scatter_tokens<<<16, 256>>>(idx, seg, cur, perm);

    cudaStreamWaitEvent(0, evJoin, 0);
    gemm_mma<2><<<dim3(16, 32, 16), 256>>>(xq2, wq_gate, gb, nullptr, a2s, wsc + 4, nullptr, perm, seg);
    hh_quant<<<CT, 256>>>(gb, ub, hqm, hsm);
    gemm_mma<3><<<dim3(16, 32, 8), 256>>>(hqm, wq_down, out, nullptr, hsm, wsc + 20, x2, perm, seg);
}